// round 8
// baseline (speedup 1.0000x reference)
#include <cuda_runtime.h>
#include <cuda_bf16.h>

// ---------------------------------------------------------------------------
// OACNNs block, round 8.
//  - conv: 3-buffer depth-2 cp.async pipeline, smem-cached nbr indices,
//    one __syncthreads per tap (was depth-1, 2 syncs).
//  - rest identical to round 7.
// ---------------------------------------------------------------------------

#define NPTS_MAX 500000
#define SEGTOT   167936     // 4096 + 32768 + 131072
#define TM   128
#define NTHR 256
#define AS   36             // uints per row (144B stride, LDSM conflict-free)
#define OFF_AL 4608        // TM*AS   (A lo plane)
#define OFF_B  9216        // 2*TM*AS (B region within a tile buffer)
#define BUFU   13824       // uints per conv tile buffer (A hi/lo + B hi/lo)
#define ROWSZ  ((size_t)NPTS_MAX * 64)

// scratch (device globals: allocation-free rule)
__device__ float          g_bufs[7 * ROWSZ];     // P0,P1,P2,Q0,Q1,Q2,Q3
__device__ float          g_bufF[ROWSZ];
__device__ __nv_bfloat162 g_pH[NPTS_MAX * 32];
__device__ __nv_bfloat162 g_pL[NPTS_MAX * 32];
__device__ float          g_segMean[SEGTOT * 64];
__device__ float          g_segDen [SEGTOT * 64];
__device__ float          g_segS   [SEGTOT * 64];
__device__ float          g_cnt    [SEGTOT];
__device__ float          g_adpv[NPTS_MAX * 3];
__device__ float          g_statsA[10 * 128];    // 0-6 gemm7, 7 fuse, 8 c1, 9 c2
__device__ unsigned       g_wpack[66 * 4608];

__device__ __constant__ int c_soff[3] = {0, 4096, 36864};

// ---------------- helpers ----------------
__device__ __forceinline__ void red_add_v4(float* addr, float4 v) {
    asm volatile("red.global.add.v4.f32 [%0], {%1,%2,%3,%4};"
                 :: "l"(addr), "f"(v.x), "f"(v.y), "f"(v.z), "f"(v.w)
                 : "memory");
}
__device__ __forceinline__ void red_add_v2(float* addr, float x, float y) {
    asm volatile("red.global.add.v2.f32 [%0], {%1,%2};"
                 :: "l"(addr), "f"(x), "f"(y) : "memory");
}
__device__ __forceinline__ void cp16(unsigned* dst, const void* src, bool v) {
    unsigned d = (unsigned)__cvta_generic_to_shared(dst);
    int sz = v ? 16 : 0;
    asm volatile("cp.async.cg.shared.global [%0], [%1], 16, %2;"
                 :: "r"(d), "l"(src), "r"(sz) : "memory");
}
__device__ __forceinline__ void cp_commit() {
    asm volatile("cp.async.commit_group;" ::: "memory");
}
template <int N> __device__ __forceinline__ void cp_wait() {
    asm volatile("cp.async.wait_group %0;" :: "n"(N) : "memory");
}

__device__ __forceinline__ void split2(float x, float y, unsigned& h, unsigned& l) {
    __nv_bfloat16 hx = __float2bfloat16(x), hy = __float2bfloat16(y);
    float lx = x - __bfloat162float(hx);
    float ly = y - __bfloat162float(hy);
    __nv_bfloat162 hp; hp.x = hx; hp.y = hy;
    __nv_bfloat162 lp; lp.x = __float2bfloat16(lx); lp.y = __float2bfloat16(ly);
    h = *reinterpret_cast<unsigned*>(&hp);
    l = *reinterpret_cast<unsigned*>(&lp);
}

__device__ __forceinline__ void mma16816(float* d, unsigned a0, unsigned a1,
                                         unsigned a2, unsigned a3,
                                         unsigned b0, unsigned b1) {
    asm volatile(
        "mma.sync.aligned.m16n8k16.row.col.f32.bf16.bf16.f32 "
        "{%0,%1,%2,%3}, {%4,%5,%6,%7}, {%8,%9}, {%0,%1,%2,%3};"
        : "+f"(d[0]), "+f"(d[1]), "+f"(d[2]), "+f"(d[3])
        : "r"(a0), "r"(a1), "r"(a2), "r"(a3), "r"(b0), "r"(b1));
}
__device__ __forceinline__ void ldsm4(unsigned& r0, unsigned& r1, unsigned& r2,
                                      unsigned& r3, const unsigned* p) {
    unsigned a = (unsigned)__cvta_generic_to_shared(p);
    asm volatile("ldmatrix.sync.aligned.m8n8.x4.shared.b16 {%0,%1,%2,%3}, [%4];"
                 : "=r"(r0), "=r"(r1), "=r"(r2), "=r"(r3) : "r"(a));
}

__device__ __forceinline__ void a_store(unsigned* buf, int r, int c4, float4 v) {
    unsigned h0, l0, h1, l1;
    split2(v.x, v.y, h0, l0);
    split2(v.z, v.w, h1, l1);
    int w = r * AS + c4 * 2;
    *reinterpret_cast<uint2*>(buf + w)          = make_uint2(h0, h1);
    *reinterpret_cast<uint2*>(buf + OFF_AL + w) = make_uint2(l0, l1);
}

__device__ __forceinline__ void stage_B(unsigned* Bdst, const unsigned* tile, int tid) {
    const uint4* s = reinterpret_cast<const uint4*>(tile);
    for (int i = tid; i < 1152; i += NTHR) cp16(Bdst + i * 4, s + i, true);
}

// 128x64x64 (x3 split) mma sweep via ldmatrix
__device__ __forceinline__ void mma_compute(const unsigned* Areg, const unsigned* Breg,
                                            float acc[8][4], int wid, int lane) {
    const unsigned* Ah = Areg;
    const unsigned* Al = Areg + OFF_AL;
    const unsigned* Bh = Breg;
    const unsigned* Bl = Breg + 2304;
    int alr = lane & 15;
    int acol = (lane >> 4) * 4;
    const unsigned* aph = Ah + (wid * 16 + alr) * AS + acol;
    const unsigned* apl = Al + (wid * 16 + alr) * AS + acol;
    int brow = lane & 7;
    const unsigned* bp = ((lane & 16) ? Bl : Bh) + brow * AS + ((lane & 8) ? 4 : 0);
#pragma unroll
    for (int kk = 0; kk < 4; ++kk) {
        int ko = kk * 8;
        unsigned a0h, a1h, a2h, a3h, a0l, a1l, a2l, a3l;
        ldsm4(a0h, a1h, a2h, a3h, aph + ko);
        ldsm4(a0l, a1l, a2l, a3l, apl + ko);
#pragma unroll
        for (int nt = 0; nt < 8; ++nt) {
            unsigned b0h, b1h, b0l, b1l;
            ldsm4(b0h, b1h, b0l, b1l, bp + nt * 8 * AS + ko);
            mma16816(acc[nt], a0h, a1h, a2h, a3h, b0h, b1h);
            mma16816(acc[nt], a0l, a1l, a2l, a3l, b0h, b1h);
            mma16816(acc[nt], a0h, a1h, a2h, a3h, b0l, b1l);
        }
    }
}

__device__ __forceinline__ void epilogue_stats(float acc[8][4], float* __restrict__ Co,
                                               float* __restrict__ statsg,
                                               float* csum, float* csq,
                                               int row0, int n, int wid, int lane, int tid) {
    int g = lane >> 2, c = lane & 3;
    int r0 = row0 + wid * 16 + g, r1 = r0 + 8;
#pragma unroll
    for (int nt = 0; nt < 8; ++nt) {
        int ch = nt * 8 + 2 * c;
        if (r0 < n) *(float2*)(Co + (size_t)r0 * 64 + ch) = make_float2(acc[nt][0], acc[nt][1]);
        if (r1 < n) *(float2*)(Co + (size_t)r1 * 64 + ch) = make_float2(acc[nt][2], acc[nt][3]);
        float s0 = acc[nt][0] + acc[nt][2];
        float s1 = acc[nt][1] + acc[nt][3];
        float q0 = acc[nt][0] * acc[nt][0] + acc[nt][2] * acc[nt][2];
        float q1 = acc[nt][1] * acc[nt][1] + acc[nt][3] * acc[nt][3];
#pragma unroll
        for (int d = 4; d < 32; d <<= 1) {
            s0 += __shfl_xor_sync(0xffffffffu, s0, d);
            s1 += __shfl_xor_sync(0xffffffffu, s1, d);
            q0 += __shfl_xor_sync(0xffffffffu, q0, d);
            q1 += __shfl_xor_sync(0xffffffffu, q1, d);
        }
        if (lane < 4) {
            atomicAdd(&csum[ch], s0);
            atomicAdd(&csum[ch + 1], s1);
            atomicAdd(&csq[ch], q0);
            atomicAdd(&csq[ch + 1], q1);
        }
    }
    __syncthreads();
    if (tid < 64)       atomicAdd(&statsg[tid], csum[tid]);
    else if (tid < 128) atomicAdd(&statsg[tid], csq[tid - 64]);
}

__device__ __forceinline__ void load_coef(float* sc, const float* __restrict__ stats,
                                          const float* __restrict__ g,
                                          const float* __restrict__ b, int n, int tid) {
    if (tid < 64) {
        float inv_n = 1.f / (float)n;
        float mean = stats[tid] * inv_n;
        float var = stats[64 + tid] * inv_n - mean * mean;
        float a = g[tid] * rsqrtf(var + 1e-3f);
        sc[tid] = a;
        sc[64 + tid] = b[tid] - mean * a;
    }
}

// ---------------- prepack ----------------
__global__ void k_prepack(const float* __restrict__ Wlw, const float* __restrict__ Ww,
                          const float* __restrict__ Wproj, const float* __restrict__ Wfuse,
                          const float* __restrict__ Wc1, const float* __restrict__ Wc2,
                          unsigned* __restrict__ pack) {
    int t = blockIdx.x;
    const float* src;
    if (t < 3)       src = Wlw  + t * 4096;
    else if (t < 6)  src = Ww   + (t - 3) * 4096;
    else if (t < 10) src = Wproj+ (t - 6) * 4096;
    else if (t < 12) src = Wfuse+ (t - 10) * 4096;
    else if (t < 39) src = Wc1  + (t - 12) * 4096;
    else             src = Wc2  + (t - 39) * 4096;
    unsigned* ph = pack + (size_t)t * 4608;
    unsigned* pl = ph + 2304;
    for (int idx = threadIdx.x; idx < 2048; idx += 256) {
        int cout = idx & 63, p = idx >> 6;
        unsigned h, l;
        split2(src[2 * p * 64 + cout], src[(2 * p + 1) * 64 + cout], h, l);
        ph[cout * AS + p] = h;
        pl[cout * AS + p] = l;
    }
}

// F = relu(bn(rawF)) + feat; emit bf16 planes of F
__global__ void k_bnrelu_add_split(float* __restrict__ F, const float* __restrict__ stats,
                                   const float* __restrict__ g, const float* __restrict__ b,
                                   const float* __restrict__ feat,
                                   __nv_bfloat162* __restrict__ H,
                                   __nv_bfloat162* __restrict__ L, int n, int total4) {
    __shared__ float sc[128];
    load_coef(sc, stats, g, b, n, threadIdx.x);
    __syncthreads();
    int i = blockIdx.x * 256 + threadIdx.x;
    if (i >= total4) return;
    int ch = (i & 15) * 4;
    float4 x = ((const float4*)F)[i];
    float4 r = ((const float4*)feat)[i];
    x.x = fmaxf(x.x * sc[ch + 0] + sc[64 + ch + 0], 0.f) + r.x;
    x.y = fmaxf(x.y * sc[ch + 1] + sc[64 + ch + 1], 0.f) + r.y;
    x.z = fmaxf(x.z * sc[ch + 2] + sc[64 + ch + 2], 0.f) + r.z;
    x.w = fmaxf(x.w * sc[ch + 3] + sc[64 + ch + 3], 0.f) + r.w;
    ((float4*)F)[i] = x;
    unsigned h0, l0, h1, l1;
    split2(x.x, x.y, h0, l0);
    split2(x.z, x.w, h1, l1);
    ((uint2*)H)[i] = make_uint2(h0, h1);
    ((uint2*)L)[i] = make_uint2(l0, l1);
}

__global__ void k_bnrelu_split(const float* __restrict__ P, const float* __restrict__ stats,
                               const float* __restrict__ g, const float* __restrict__ b,
                               __nv_bfloat162* __restrict__ H,
                               __nv_bfloat162* __restrict__ L, int n, int total4) {
    __shared__ float sc[128];
    load_coef(sc, stats, g, b, n, threadIdx.x);
    __syncthreads();
    int i = blockIdx.x * 256 + threadIdx.x;
    if (i >= total4) return;
    int ch = (i & 15) * 4;
    float4 x = ((const float4*)P)[i];
    x.x = fmaxf(x.x * sc[ch + 0] + sc[64 + ch + 0], 0.f);
    x.y = fmaxf(x.y * sc[ch + 1] + sc[64 + ch + 1], 0.f);
    x.z = fmaxf(x.z * sc[ch + 2] + sc[64 + ch + 2], 0.f);
    x.w = fmaxf(x.w * sc[ch + 3] + sc[64 + ch + 3], 0.f);
    unsigned h0, l0, h1, l1;
    split2(x.x, x.y, h0, l0);
    split2(x.z, x.w, h1, l1);
    ((uint2*)H)[i] = make_uint2(h0, h1);
    ((uint2*)L)[i] = make_uint2(l0, l1);
}

// ---------------- tensor-core kernels ----------------
// 7 GEMMs sharing A=feat (converted in staging): outputs P0..P2,Q0..Q3 + stats
__global__ __launch_bounds__(NTHR)
void k_mma_gemm7(const float* __restrict__ feat, const unsigned* __restrict__ pack,
                 float* __restrict__ bufs, float* __restrict__ statsg, int n) {
    extern __shared__ unsigned sm[];     // A:[0,9216) B0:[9216,13824) B1:[13824,18432)
    __shared__ float csum[64], csq[64];
    const int tidx[7] = {0, 1, 2, 6, 7, 8, 9};
    int tid = threadIdx.x, wid = tid >> 5, lane = tid & 31;
    int row0 = blockIdx.x * TM;
    stage_B(sm + OFF_B, pack + (size_t)tidx[0] * 4608, tid);
    cp_commit();
#pragma unroll
    for (int i = 0; i < 8; ++i) {   // convert feat -> hi/lo planes
        int idx = tid + i * NTHR;
        int r = idx >> 4, c4 = idx & 15;
        int grow = row0 + r;
        float4 v = make_float4(0.f, 0.f, 0.f, 0.f);
        if (grow < n) v = *(const float4*)(feat + (size_t)grow * 64 + c4 * 4);
        a_store(sm, r, c4, v);
    }
    for (int t = 0; t < 7; ++t) {
        unsigned* bcur = sm + OFF_B + (t & 1) * 4608;
        if (t + 1 < 7) {
            stage_B(sm + OFF_B + ((t + 1) & 1) * 4608, pack + (size_t)tidx[t + 1] * 4608, tid);
            cp_commit();
            cp_wait<1>();
        } else {
            cp_wait<0>();
        }
        if (tid < 64) { csum[tid] = 0.f; csq[tid] = 0.f; }
        __syncthreads();
        float acc[8][4] = {};
        mma_compute(sm, bcur, acc, wid, lane);
        epilogue_stats(acc, bufs + (size_t)t * ROWSZ, statsg + t * 128,
                       csum, csq, row0, n, wid, lane, tid);
        __syncthreads();
    }
}

// gather conv: 3-buffer depth-2 cp.async pipeline over 27 taps; + stats
__global__ __launch_bounds__(NTHR)
void k_mma_conv(const uint4* __restrict__ AH, const uint4* __restrict__ AL,
                const int* __restrict__ nbr, const unsigned* __restrict__ pack,
                float* __restrict__ Co, float* __restrict__ statsg, int n) {
    extern __shared__ unsigned sm[];          // 3 tile buffers + idx cache
    int* idxs = (int*)(sm + 3 * BUFU);        // [TM*27]
    __shared__ float csum[64], csq[64];
    int tid = threadIdx.x, wid = tid >> 5, lane = tid & 31;
    int row0 = blockIdx.x * TM;
    if (tid < 64) { csum[tid] = 0.f; csq[tid] = 0.f; }
    {   // coalesced preload of all neighbor indices for this tile
        size_t base = (size_t)row0 * 27;
        size_t lim = (size_t)n * 27;
        for (int i = tid; i < TM * 27; i += NTHR) {
            size_t pos = base + i;
            idxs[i] = (pos < lim) ? __ldg(&nbr[pos]) : 0;
        }
    }
    __syncthreads();
    int row = tid >> 1, pl = tid & 1;
    bool v = (row0 + row) < n;
    const uint4* basep = pl ? AL : AH;
    // prologue: stage taps 0 and 1
#pragma unroll
    for (int k = 0; k < 2; ++k) {
        unsigned* b = sm + k * BUFU;
        stage_B(b + OFF_B, pack + (size_t)k * 4608, tid);
        const uint4* s = basep + (size_t)idxs[row * 27 + k] * 8;
        unsigned* d = b + (pl ? OFF_AL : 0) + row * AS;
#pragma unroll
        for (int c = 0; c < 8; ++c) cp16(d + c * 4, s + c, v);
        cp_commit();
    }
    float acc[8][4] = {};
    for (int k = 0; k < 27; ++k) {
        if (k < 25) cp_wait<1>(); else cp_wait<0>();
        __syncthreads();        // buffer (k+2)%3's previous mma (tap k-1) done
        if (k + 2 < 27) {
            unsigned* b = sm + ((k + 2) % 3) * BUFU;
            stage_B(b + OFF_B, pack + (size_t)(k + 2) * 4608, tid);
            const uint4* s = basep + (size_t)idxs[row * 27 + k + 2] * 8;
            unsigned* d = b + (pl ? OFF_AL : 0) + row * AS;
#pragma unroll
            for (int c = 0; c < 8; ++c) cp16(d + c * 4, s + c, v);
            cp_commit();
        }
        unsigned* cur = sm + (k % 3) * BUFU;
        mma_compute(cur, cur + OFF_B, acc, wid, lane);
    }
    __syncthreads();
    epilogue_stats(acc, Co, statsg, csum, csq, row0, n, wid, lane, tid);
}

// per-scale (gridDim.y=3): P = exp((relu(bn(P)) - mean[cl]) @ W_w); den += P
__global__ __launch_bounds__(NTHR)
void k_mma_submean_exp(float* __restrict__ bufs, const float* __restrict__ statsb,
                       const float* __restrict__ glw, const float* __restrict__ blw,
                       const unsigned* __restrict__ pack, const float* __restrict__ mean,
                       const float* __restrict__ cnt,
                       const int* __restrict__ cl0, const int* __restrict__ cl1,
                       const int* __restrict__ cl2, float* __restrict__ den, int n) {
    extern __shared__ unsigned buf[];
    __shared__ float coef[128];
    __shared__ int   cls[TM];
    __shared__ float cinv[TM];
    int s = blockIdx.y;
    const int* cl = (s == 0) ? cl0 : ((s == 1) ? cl1 : cl2);
    int soff = c_soff[s];
    float* P = bufs + (size_t)s * ROWSZ;
    int tid = threadIdx.x, wid = tid >> 5, lane = tid & 31;
    int row0 = blockIdx.x * TM;
    load_coef(coef, statsb + s * 128, glw + s * 64, blw + s * 64, n, tid);
    if (tid < 128) {
        int r = row0 + tid;
        int c = (r < n) ? cl[r] : 0;
        cls[tid] = c;
        cinv[tid] = 1.f / fmaxf(cnt[soff + c], 1.f);
    }
    stage_B(buf + OFF_B, pack + (size_t)(3 + s) * 4608, tid);
    cp_commit();
    __syncthreads();
#pragma unroll
    for (int i = 0; i < 8; ++i) {
        int idx = tid + i * NTHR;
        int r = idx >> 4, c4 = idx & 15;
        int grow = row0 + r;
        float4 vv = make_float4(0.f, 0.f, 0.f, 0.f);
        if (grow < n) {
            vv = *(const float4*)(P + (size_t)grow * 64 + c4 * 4);
            float4 ms = *(const float4*)(mean + (size_t)(soff + cls[r]) * 64 + c4 * 4);
            float ci = cinv[r];
            int ch = c4 * 4;
            vv.x = fmaxf(vv.x * coef[ch + 0] + coef[64 + ch + 0], 0.f) - ms.x * ci;
            vv.y = fmaxf(vv.y * coef[ch + 1] + coef[64 + ch + 1], 0.f) - ms.y * ci;
            vv.z = fmaxf(vv.z * coef[ch + 2] + coef[64 + ch + 2], 0.f) - ms.z * ci;
            vv.w = fmaxf(vv.w * coef[ch + 3] + coef[64 + ch + 3], 0.f) - ms.w * ci;
        }
        a_store(buf, r, c4, vv);
    }
    cp_wait<0>();
    __syncthreads();
    float acc[8][4] = {};
    mma_compute(buf, buf + OFF_B, acc, wid, lane);
    int g = lane >> 2, c = lane & 3;
    int lr0 = wid * 16 + g, lr1 = lr0 + 8;
    int r0 = row0 + lr0, r1 = row0 + lr1;
    float* d0 = den + (size_t)(soff + cls[lr0]) * 64;
    float* d1 = den + (size_t)(soff + cls[lr1]) * 64;
#pragma unroll
    for (int nt = 0; nt < 8; ++nt) {
        int ch = nt * 8 + 2 * c;
        if (r0 < n) {
            float e0 = __expf(acc[nt][0]), e1 = __expf(acc[nt][1]);
            *(float2*)(P + (size_t)r0 * 64 + ch) = make_float2(e0, e1);
            red_add_v2(d0 + ch, e0, e1);
        }
        if (r1 < n) {
            float e2 = __expf(acc[nt][2]), e3 = __expf(acc[nt][3]);
            *(float2*)(P + (size_t)r1 * 64 + ch) = make_float2(e2, e3);
            red_add_v2(d1 + ch, e2, e3);
        }
    }
}

// fuse GEMM: Co = relu(bn(Q))@Wf[0:64] + mix@Wf[64:128] + stats
__global__ __launch_bounds__(NTHR)
void k_mma_gemm2(const float* __restrict__ Q, const float* __restrict__ stats,
                 const float* __restrict__ gg, const float* __restrict__ bb,
                 const unsigned* __restrict__ tiles, const float* __restrict__ segS,
                 const int* __restrict__ cl0, const int* __restrict__ cl1,
                 const int* __restrict__ cl2, const float* __restrict__ adp,
                 float* __restrict__ Co, float* __restrict__ statsg, int n) {
    extern __shared__ unsigned buf[];
    __shared__ float csum[64], csq[64];
    __shared__ float coef[128];
    __shared__ int   cls[3][TM];
    __shared__ float sad[3][TM];
    int tid = threadIdx.x, wid = tid >> 5, lane = tid & 31;
    int row0 = blockIdx.x * TM;
    if (tid < 64) { csum[tid] = 0.f; csq[tid] = 0.f; }
    load_coef(coef, stats, gg, bb, n, tid);
    if (tid < 128) {
        int r = row0 + tid;
        bool v = r < n;
        cls[0][tid] = v ? cl0[r] : 0;
        cls[1][tid] = v ? cl1[r] : 0;
        cls[2][tid] = v ? cl2[r] : 0;
        sad[0][tid] = v ? adp[(size_t)r * 3 + 0] : 0.f;
        sad[1][tid] = v ? adp[(size_t)r * 3 + 1] : 0.f;
        sad[2][tid] = v ? adp[(size_t)r * 3 + 2] : 0.f;
    }
    __syncthreads();
    float acc[8][4] = {};
#pragma unroll
    for (int p = 0; p < 2; ++p) {
        stage_B(buf + OFF_B, tiles + (size_t)p * 4608, tid);
        cp_commit();
#pragma unroll
        for (int i = 0; i < 8; ++i) {
            int idx = tid + i * NTHR;
            int r = idx >> 4, c4 = idx & 15;
            int grow = row0 + r;
            float4 vv = make_float4(0.f, 0.f, 0.f, 0.f);
            if (grow < n) {
                if (p == 0) {
                    vv = *(const float4*)(Q + (size_t)grow * 64 + c4 * 4);
                    int ch = c4 * 4;
                    vv.x = fmaxf(vv.x * coef[ch + 0] + coef[64 + ch + 0], 0.f);
                    vv.y = fmaxf(vv.y * coef[ch + 1] + coef[64 + ch + 1], 0.f);
                    vv.z = fmaxf(vv.z * coef[ch + 2] + coef[64 + ch + 2], 0.f);
                    vv.w = fmaxf(vv.w * coef[ch + 3] + coef[64 + ch + 3], 0.f);
                } else {
                    float w0 = sad[0][r], w1 = sad[1][r], w2 = sad[2][r];
                    float4 a = *(const float4*)(segS + (size_t)(0 + cls[0][r]) * 64 + c4 * 4);
                    float4 bv = *(const float4*)(segS + (size_t)(4096 + cls[1][r]) * 64 + c4 * 4);
                    float4 cc = *(const float4*)(segS + (size_t)(36864 + cls[2][r]) * 64 + c4 * 4);
                    vv.x = w0 * a.x + w1 * bv.x + w2 * cc.x;
                    vv.y = w0 * a.y + w1 * bv.y + w2 * cc.y;
                    vv.z = w0 * a.z + w1 * bv.z + w2 * cc.z;
                    vv.w = w0 * a.w + w1 * bv.w + w2 * cc.w;
                }
            }
            a_store(buf, r, c4, vv);
        }
        cp_wait<0>();
        __syncthreads();
        mma_compute(buf, buf + OFF_B, acc, wid, lane);
        __syncthreads();
    }
    epilogue_stats(acc, Co, statsg, csum, csq, row0, n, wid, lane, tid);
}

// ---------------- small / elementwise kernels ----------------
__global__ void k_adp(const float* __restrict__ feat, const float* __restrict__ Wa,
                      float* __restrict__ adp, int n) {
    __shared__ float w[192];
    if (threadIdx.x < 192) w[threadIdx.x] = Wa[threadIdx.x];
    __syncthreads();
    int row = blockIdx.x * blockDim.x + threadIdx.x;
    if (row >= n) return;
    float s0 = 0.f, s1 = 0.f, s2 = 0.f;
    const float* f = feat + (size_t)row * 64;
#pragma unroll 16
    for (int c = 0; c < 64; ++c) {
        float v = f[c];
        s0 += v * w[c * 3 + 0];
        s1 += v * w[c * 3 + 1];
        s2 += v * w[c * 3 + 2];
    }
    float m = fmaxf(s0, fmaxf(s1, s2));
    float e0 = __expf(s0 - m), e1 = __expf(s1 - m), e2 = __expf(s2 - m);
    float inv = 1.f / (e0 + e1 + e2);
    adp[(size_t)row * 3 + 0] = e0 * inv;
    adp[(size_t)row * 3 + 1] = e1 * inv;
    adp[(size_t)row * 3 + 2] = e2 * inv;
}

// per-scale (gridDim.y=3): mean-arena += relu(bn(P)), cnt++
__global__ void k_segsum3(const float* __restrict__ bufs, const float* __restrict__ statsb,
                          const float* __restrict__ glw, const float* __restrict__ blw,
                          const int* __restrict__ cl0, const int* __restrict__ cl1,
                          const int* __restrict__ cl2, float* __restrict__ mean,
                          float* __restrict__ cnt, int n) {
    __shared__ float sc[128];
    int s = blockIdx.y;
    load_coef(sc, statsb + s * 128, glw + s * 64, blw + s * 64, n, threadIdx.x);
    __syncthreads();
    int row = blockIdx.x * blockDim.x + threadIdx.x;
    if (row >= n) return;
    const int* cl = (s == 0) ? cl0 : ((s == 1) ? cl1 : cl2);
    int c = c_soff[s] + cl[row];
    const float* p = bufs + (size_t)s * ROWSZ + (size_t)row * 64;
    float* sg = mean + (size_t)c * 64;
#pragma unroll
    for (int c4 = 0; c4 < 16; ++c4) {
        float4 x = *(const float4*)(p + c4 * 4);
        x.x = fmaxf(x.x * sc[c4 * 4 + 0] + sc[64 + c4 * 4 + 0], 0.f);
        x.y = fmaxf(x.y * sc[c4 * 4 + 1] + sc[64 + c4 * 4 + 1], 0.f);
        x.z = fmaxf(x.z * sc[c4 * 4 + 2] + sc[64 + c4 * 4 + 2], 0.f);
        x.w = fmaxf(x.w * sc[c4 * 4 + 3] + sc[64 + c4 * 4 + 3], 0.f);
        red_add_v4(sg + c4 * 4, x);
    }
    atomicAdd(&cnt[c], 1.f);
}

// per-scale (gridDim.y=3): segS += relu(bn(Q)) * expP / (den[cl]+1e-6)
__global__ void k_pw3(const float* __restrict__ bufs, const float* __restrict__ statsb,
                      const float* __restrict__ gproj, const float* __restrict__ bproj,
                      const float* __restrict__ den,
                      const int* __restrict__ cl0, const int* __restrict__ cl1,
                      const int* __restrict__ cl2, float* __restrict__ segS, int n) {
    __shared__ float sc[128];
    int s = blockIdx.y;
    load_coef(sc, statsb + (3 + s) * 128, gproj + s * 64, bproj + s * 64, n, threadIdx.x);
    __syncthreads();
    int row = blockIdx.x * blockDim.x + threadIdx.x;
    if (row >= n) return;
    const int* cl = (s == 0) ? cl0 : ((s == 1) ? cl1 : cl2);
    int c = c_soff[s] + cl[row];
    const float* q = bufs + (size_t)(3 + s) * ROWSZ + (size_t)row * 64;
    const float* p = bufs + (size_t)s * ROWSZ + (size_t)row * 64;
    const float* d = den + (size_t)c * 64;
    float* sg = segS + (size_t)c * 64;
#pragma unroll
    for (int c4 = 0; c4 < 16; ++c4) {
        float4 qv = *(const float4*)(q + c4 * 4);
        float4 pv = *(const float4*)(p + c4 * 4);
        float4 dv = *(const float4*)(d + c4 * 4);
        float4 o;
        o.x = fmaxf(qv.x * sc[c4 * 4 + 0] + sc[64 + c4 * 4 + 0], 0.f) * pv.x / (dv.x + 1e-6f);
        o.y = fmaxf(qv.y * sc[c4 * 4 + 1] + sc[64 + c4 * 4 + 1], 0.f) * pv.y / (dv.y + 1e-6f);
        o.z = fmaxf(qv.z * sc[c4 * 4 + 2] + sc[64 + c4 * 4 + 2], 0.f) * pv.z / (dv.z + 1e-6f);
        o.w = fmaxf(qv.w * sc[c4 * 4 + 3] + sc[64 + c4 * 4 + 3], 0.f) * pv.w / (dv.w + 1e-6f);
        red_add_v4(sg + c4 * 4, o);
    }
}

// out = relu(bn(H) + F)
__global__ void k_final(const float* __restrict__ H, const float* __restrict__ stats,
                        const float* __restrict__ g, const float* __restrict__ b,
                        const float* __restrict__ F, float* __restrict__ out,
                        int n, int total4) {
    __shared__ float sc[128];
    load_coef(sc, stats, g, b, n, threadIdx.x);
    __syncthreads();
    int i = blockIdx.x * 256 + threadIdx.x;
    if (i >= total4) return;
    int ch = (i & 15) * 4;
    float4 x = ((const float4*)H)[i];
    float4 r = ((const float4*)F)[i];
    x.x = fmaxf(x.x * sc[ch + 0] + sc[64 + ch + 0] + r.x, 0.f);
    x.y = fmaxf(x.y * sc[ch + 1] + sc[64 + ch + 1] + r.y, 0.f);
    x.z = fmaxf(x.z * sc[ch + 2] + sc[64 + ch + 2] + r.z, 0.f);
    x.w = fmaxf(x.w * sc[ch + 3] + sc[64 + ch + 3] + r.w, 0.f);
    ((float4*)out)[i] = x;
}

// ---------------------------------------------------------------------------
extern "C" void kernel_launch(void* const* d_in, const int* in_sizes, int n_in,
                              void* d_out, int out_size) {
    const float* feat   = (const float*)d_in[0];
    const int*   cl0    = (const int*)d_in[1];
    const int*   cl1    = (const int*)d_in[2];
    const int*   cl2    = (const int*)d_in[3];
    const int*   nbr    = (const int*)d_in[4];
    const float* W_lw   = (const float*)d_in[5];
    const float* g_lw   = (const float*)d_in[6];
    const float* b_lw   = (const float*)d_in[7];
    const float* W_w    = (const float*)d_in[8];
    const float* W_proj = (const float*)d_in[9];
    const float* g_proj = (const float*)d_in[10];
    const float* b_proj = (const float*)d_in[11];
    const float* W_adp  = (const float*)d_in[12];
    const float* W_fuse = (const float*)d_in[13];
    const float* g_fuse = (const float*)d_in[14];
    const float* b_fuse = (const float*)d_in[15];
    const float* W_c1   = (const float*)d_in[16];
    const float* g_c1   = (const float*)d_in[17];
    const float* b_c1   = (const float*)d_in[18];
    const float* W_c2   = (const float*)d_in[19];
    const float* g_c2   = (const float*)d_in[20];
    const float* b_c2   = (const float*)d_in[21];
    float* out = (float*)d_out;
    int n = in_sizes[1];

    float *pBufs, *pF, *pMean, *pDen, *pSegS, *pCnt, *pStats, *pAdp;
    __nv_bfloat162 *pH, *pL;
    unsigned *pPack;
    cudaGetSymbolAddress((void**)&pBufs, g_bufs);
    cudaGetSymbolAddress((void**)&pF, g_bufF);
    cudaGetSymbolAddress((void**)&pH, g_pH);
    cudaGetSymbolAddress((void**)&pL, g_pL);
    cudaGetSymbolAddress((void**)&pMean, g_segMean);
    cudaGetSymbolAddress((void**)&pDen, g_segDen);
    cudaGetSymbolAddress((void**)&pSegS, g_segS);
    cudaGetSymbolAddress((void**)&pCnt, g_cnt);
    cudaGetSymbolAddress((void**)&pStats, g_statsA);
    cudaGetSymbolAddress((void**)&pAdp, g_adpv);
    cudaGetSymbolAddress((void**)&pPack, g_wpack);

    const int GB = (n + TM - 1) / TM;
    const int EB = (n + 255) / 256;
    const int total4 = n * 16;
    const int SB = (total4 + 255) / 256;
    const int SM_G7 = 18432 * 4;                    // 73728B
    const int SM_1  = BUFU * 4;                     // 55296B
    const int SM_CV = BUFU * 12 + TM * 27 * 4;      // 3 buffers + idx = 179712B

    cudaFuncSetAttribute(k_mma_gemm7, cudaFuncAttributeMaxDynamicSharedMemorySize, SM_G7);
    cudaFuncSetAttribute(k_mma_submean_exp, cudaFuncAttributeMaxDynamicSharedMemorySize, SM_1);
    cudaFuncSetAttribute(k_mma_gemm2, cudaFuncAttributeMaxDynamicSharedMemorySize, SM_1);
    cudaFuncSetAttribute(k_mma_conv, cudaFuncAttributeMaxDynamicSharedMemorySize, SM_CV);

    const uint4* AH = (const uint4*)pH;
    const uint4* AL = (const uint4*)pL;
    float* Qb3 = pBufs + 6 * ROWSZ;

    k_prepack<<<66, 256>>>(W_lw, W_w, W_proj, W_fuse, W_c1, W_c2, pPack);
    k_adp<<<EB, 256>>>(feat, W_adp, pAdp, n);

    // 7 feat-GEMMs (feat converted in staging)
    cudaMemsetAsync(pStats, 0, 7 * 128 * sizeof(float));
    k_mma_gemm7<<<GB, NTHR, SM_G7>>>(feat, pPack, pBufs, pStats, n);

    // cluster attention, all 3 scales batched
    cudaMemsetAsync(pMean, 0, (size_t)SEGTOT * 64 * sizeof(float));
    cudaMemsetAsync(pCnt, 0, (size_t)SEGTOT * sizeof(float));
    k_segsum3<<<dim3(EB, 3), 256>>>(pBufs, pStats, g_lw, b_lw, cl0, cl1, cl2,
                                    pMean, pCnt, n);
    cudaMemsetAsync(pDen, 0, (size_t)SEGTOT * 64 * sizeof(float));
    k_mma_submean_exp<<<dim3(GB, 3), NTHR, SM_1>>>(pBufs, pStats, g_lw, b_lw, pPack,
                                                   pMean, pCnt, cl0, cl1, cl2, pDen, n);
    cudaMemsetAsync(pSegS, 0, (size_t)SEGTOT * 64 * sizeof(float));
    k_pw3<<<dim3(EB, 3), 256>>>(pBufs, pStats, g_proj, b_proj, pDen,
                                cl0, cl1, cl2, pSegS, n);

    // fused = relu(bn([relu(bn(Q3)), mix] @ W_fuse)) + feat
    cudaMemsetAsync(pStats + 7 * 128, 0, 128 * sizeof(float));
    k_mma_gemm2<<<GB, NTHR, SM_1>>>(Qb3, pStats + 6 * 128, g_proj + 192, b_proj + 192,
                                    pPack + (size_t)10 * 4608, pSegS,
                                    cl0, cl1, cl2, pAdp, pF, pStats + 7 * 128, n);
    k_bnrelu_add_split<<<SB, 256>>>(pF, pStats + 7 * 128, g_fuse, b_fuse, feat,
                                    pH, pL, n, total4);
    // conv1 -> split ; conv2 -> final
    cudaMemsetAsync(pStats + 8 * 128, 0, 128 * sizeof(float));
    k_mma_conv<<<GB, NTHR, SM_CV>>>(AH, AL, nbr, pPack + (size_t)12 * 4608,
                                    pBufs, pStats + 8 * 128, n);
    k_bnrelu_split<<<SB, 256>>>(pBufs, pStats + 8 * 128, g_c1, b_c1, pH, pL, n, total4);
    cudaMemsetAsync(pStats + 9 * 128, 0, 128 * sizeof(float));
    k_mma_conv<<<GB, NTHR, SM_CV>>>(AH, AL, nbr, pPack + (size_t)39 * 4608,
                                    pBufs + ROWSZ, pStats + 9 * 128, n);
    k_final<<<SB, 256>>>(pBufs + ROWSZ, pStats + 9 * 128, g_c2, b_c2, pF, out, n, total4);
}

// round 9
// speedup vs baseline: 1.8756x; 1.8756x over previous
#include <cuda_runtime.h>
#include <cuda_bf16.h>
#include <cuda_fp16.h>

// ---------------------------------------------------------------------------
// OACNNs block, round 9.
//  - convs switched to fp16 single-plane MMA (cp.async op count halved,
//    MMA count 3x lower; conv was LSU-issue-bound per round-8 postmortem).
//  - conv pipeline reverted to round-7 double-buffer (measured best) + idx cache.
//  - attention/GEMM chain unchanged (bf16 hi/lo split, known 7e-6 accurate).
// ---------------------------------------------------------------------------

#define NPTS_MAX 500000
#define SEGTOT   167936     // 4096 + 32768 + 131072
#define TM   128
#define NTHR 256
#define AS   36             // uints per row (144B stride, LDSM conflict-free)
#define OFF_AL 4608        // TM*AS   (A lo plane)
#define OFF_B  9216        // 2*TM*AS (B region within a bf16 tile buffer)
#define CBUF   6912        // uints per fp16 conv buffer (A 4608 + B 2304)
#define COFF_B 4608
#define ROWSZ  ((size_t)NPTS_MAX * 64)

// scratch (device globals: allocation-free rule)
__device__ float          g_bufs[7 * ROWSZ];     // P0,P1,P2,Q0,Q1,Q2,Q3
__device__ float          g_bufF[ROWSZ];
__device__ unsigned       g_fph[NPTS_MAX * 32];  // fp16 plane of conv input
__device__ float          g_segMean[SEGTOT * 64];
__device__ float          g_segDen [SEGTOT * 64];
__device__ float          g_segS   [SEGTOT * 64];
__device__ float          g_cnt    [SEGTOT];
__device__ float          g_adpv[NPTS_MAX * 3];
__device__ float          g_statsA[10 * 128];    // 0-6 gemm7, 7 fuse, 8 c1, 9 c2
__device__ unsigned       g_wpack[12 * 4608];    // bf16 hi/lo tiles (lw,w,proj,fuse)
__device__ unsigned       g_wpackc[54 * 2304];   // fp16 conv tiles

__device__ __constant__ int c_soff[3] = {0, 4096, 36864};

// ---------------- helpers ----------------
__device__ __forceinline__ void red_add_v4(float* addr, float4 v) {
    asm volatile("red.global.add.v4.f32 [%0], {%1,%2,%3,%4};"
                 :: "l"(addr), "f"(v.x), "f"(v.y), "f"(v.z), "f"(v.w)
                 : "memory");
}
__device__ __forceinline__ void red_add_v2(float* addr, float x, float y) {
    asm volatile("red.global.add.v2.f32 [%0], {%1,%2};"
                 :: "l"(addr), "f"(x), "f"(y) : "memory");
}
__device__ __forceinline__ void cp16(unsigned* dst, const void* src, bool v) {
    unsigned d = (unsigned)__cvta_generic_to_shared(dst);
    int sz = v ? 16 : 0;
    asm volatile("cp.async.cg.shared.global [%0], [%1], 16, %2;"
                 :: "r"(d), "l"(src), "r"(sz) : "memory");
}
__device__ __forceinline__ void cp_commit() {
    asm volatile("cp.async.commit_group;" ::: "memory");
}
template <int N> __device__ __forceinline__ void cp_wait() {
    asm volatile("cp.async.wait_group %0;" :: "n"(N) : "memory");
}

__device__ __forceinline__ void split2(float x, float y, unsigned& h, unsigned& l) {
    __nv_bfloat16 hx = __float2bfloat16(x), hy = __float2bfloat16(y);
    float lx = x - __bfloat162float(hx);
    float ly = y - __bfloat162float(hy);
    __nv_bfloat162 hp; hp.x = hx; hp.y = hy;
    __nv_bfloat162 lp; lp.x = __float2bfloat16(lx); lp.y = __float2bfloat16(ly);
    h = *reinterpret_cast<unsigned*>(&hp);
    l = *reinterpret_cast<unsigned*>(&lp);
}
__device__ __forceinline__ unsigned packh2(float x, float y) {
    __half2 h; h.x = __float2half(x); h.y = __float2half(y);
    return *reinterpret_cast<unsigned*>(&h);
}

__device__ __forceinline__ void mma16816(float* d, unsigned a0, unsigned a1,
                                         unsigned a2, unsigned a3,
                                         unsigned b0, unsigned b1) {
    asm volatile(
        "mma.sync.aligned.m16n8k16.row.col.f32.bf16.bf16.f32 "
        "{%0,%1,%2,%3}, {%4,%5,%6,%7}, {%8,%9}, {%0,%1,%2,%3};"
        : "+f"(d[0]), "+f"(d[1]), "+f"(d[2]), "+f"(d[3])
        : "r"(a0), "r"(a1), "r"(a2), "r"(a3), "r"(b0), "r"(b1));
}
__device__ __forceinline__ void mma16816h(float* d, unsigned a0, unsigned a1,
                                          unsigned a2, unsigned a3,
                                          unsigned b0, unsigned b1) {
    asm volatile(
        "mma.sync.aligned.m16n8k16.row.col.f32.f16.f16.f32 "
        "{%0,%1,%2,%3}, {%4,%5,%6,%7}, {%8,%9}, {%0,%1,%2,%3};"
        : "+f"(d[0]), "+f"(d[1]), "+f"(d[2]), "+f"(d[3])
        : "r"(a0), "r"(a1), "r"(a2), "r"(a3), "r"(b0), "r"(b1));
}
__device__ __forceinline__ void ldsm4(unsigned& r0, unsigned& r1, unsigned& r2,
                                      unsigned& r3, const unsigned* p) {
    unsigned a = (unsigned)__cvta_generic_to_shared(p);
    asm volatile("ldmatrix.sync.aligned.m8n8.x4.shared.b16 {%0,%1,%2,%3}, [%4];"
                 : "=r"(r0), "=r"(r1), "=r"(r2), "=r"(r3) : "r"(a));
}

__device__ __forceinline__ void a_store(unsigned* buf, int r, int c4, float4 v) {
    unsigned h0, l0, h1, l1;
    split2(v.x, v.y, h0, l0);
    split2(v.z, v.w, h1, l1);
    int w = r * AS + c4 * 2;
    *reinterpret_cast<uint2*>(buf + w)          = make_uint2(h0, h1);
    *reinterpret_cast<uint2*>(buf + OFF_AL + w) = make_uint2(l0, l1);
}

__device__ __forceinline__ void stage_B(unsigned* Bdst, const unsigned* tile, int tid) {
    const uint4* s = reinterpret_cast<const uint4*>(tile);
    for (int i = tid; i < 1152; i += NTHR) cp16(Bdst + i * 4, s + i, true);
}
__device__ __forceinline__ void stage_Bc(unsigned* Bdst, const unsigned* tile, int tid) {
    const uint4* s = reinterpret_cast<const uint4*>(tile);
    for (int i = tid; i < 576; i += NTHR) cp16(Bdst + i * 4, s + i, true);
}

// 128x64x64 (x3 split) bf16 mma sweep via ldmatrix
__device__ __forceinline__ void mma_compute(const unsigned* Areg, const unsigned* Breg,
                                            float acc[8][4], int wid, int lane) {
    const unsigned* Ah = Areg;
    const unsigned* Al = Areg + OFF_AL;
    const unsigned* Bh = Breg;
    const unsigned* Bl = Breg + 2304;
    int alr = lane & 15;
    int acol = (lane >> 4) * 4;
    const unsigned* aph = Ah + (wid * 16 + alr) * AS + acol;
    const unsigned* apl = Al + (wid * 16 + alr) * AS + acol;
    int brow = lane & 7;
    const unsigned* bp = ((lane & 16) ? Bl : Bh) + brow * AS + ((lane & 8) ? 4 : 0);
#pragma unroll
    for (int kk = 0; kk < 4; ++kk) {
        int ko = kk * 8;
        unsigned a0h, a1h, a2h, a3h, a0l, a1l, a2l, a3l;
        ldsm4(a0h, a1h, a2h, a3h, aph + ko);
        ldsm4(a0l, a1l, a2l, a3l, apl + ko);
#pragma unroll
        for (int nt = 0; nt < 8; ++nt) {
            unsigned b0h, b1h, b0l, b1l;
            ldsm4(b0h, b1h, b0l, b1l, bp + nt * 8 * AS + ko);
            mma16816(acc[nt], a0h, a1h, a2h, a3h, b0h, b1h);
            mma16816(acc[nt], a0l, a1l, a2l, a3l, b0h, b1h);
            mma16816(acc[nt], a0h, a1h, a2h, a3h, b0l, b1l);
        }
    }
}

// 128x64x64 fp16 single-plane mma sweep (conv path)
__device__ __forceinline__ void mma_compute_h(const unsigned* buf, float acc[8][4],
                                              int wid, int lane) {
    const unsigned* Ap = buf;
    const unsigned* Bp = buf + COFF_B;
    const unsigned* aph = Ap + (wid * 16 + (lane & 15)) * AS + (lane >> 4) * 4;
    // B x4 ldsm: lanes 0-7 (nt0,k0), 8-15 (nt0,k1), 16-23 (nt1,k0), 24-31 (nt1,k1)
    int brow = lane & 7;
    int koff = ((lane >> 3) & 1) * 4;
    int ntoff = ((lane >> 4) & 1) * 8 * AS;
#pragma unroll
    for (int kk = 0; kk < 4; ++kk) {
        int ko = kk * 8;
        unsigned a0, a1, a2, a3;
        ldsm4(a0, a1, a2, a3, aph + ko);
#pragma unroll
        for (int np = 0; np < 4; ++np) {
            unsigned b0, b1, b2, b3;
            ldsm4(b0, b1, b2, b3, Bp + (np * 16 + brow) * AS + ntoff + ko + koff);
            mma16816h(acc[2 * np], a0, a1, a2, a3, b0, b1);
            mma16816h(acc[2 * np + 1], a0, a1, a2, a3, b2, b3);
        }
    }
}

__device__ __forceinline__ void epilogue_stats(float acc[8][4], float* __restrict__ Co,
                                               float* __restrict__ statsg,
                                               float* csum, float* csq,
                                               int row0, int n, int wid, int lane, int tid) {
    int g = lane >> 2, c = lane & 3;
    int r0 = row0 + wid * 16 + g, r1 = r0 + 8;
#pragma unroll
    for (int nt = 0; nt < 8; ++nt) {
        int ch = nt * 8 + 2 * c;
        if (r0 < n) *(float2*)(Co + (size_t)r0 * 64 + ch) = make_float2(acc[nt][0], acc[nt][1]);
        if (r1 < n) *(float2*)(Co + (size_t)r1 * 64 + ch) = make_float2(acc[nt][2], acc[nt][3]);
        float s0 = acc[nt][0] + acc[nt][2];
        float s1 = acc[nt][1] + acc[nt][3];
        float q0 = acc[nt][0] * acc[nt][0] + acc[nt][2] * acc[nt][2];
        float q1 = acc[nt][1] * acc[nt][1] + acc[nt][3] * acc[nt][3];
#pragma unroll
        for (int d = 4; d < 32; d <<= 1) {
            s0 += __shfl_xor_sync(0xffffffffu, s0, d);
            s1 += __shfl_xor_sync(0xffffffffu, s1, d);
            q0 += __shfl_xor_sync(0xffffffffu, q0, d);
            q1 += __shfl_xor_sync(0xffffffffu, q1, d);
        }
        if (lane < 4) {
            atomicAdd(&csum[ch], s0);
            atomicAdd(&csum[ch + 1], s1);
            atomicAdd(&csq[ch], q0);
            atomicAdd(&csq[ch + 1], q1);
        }
    }
    __syncthreads();
    if (tid < 64)       atomicAdd(&statsg[tid], csum[tid]);
    else if (tid < 128) atomicAdd(&statsg[tid], csq[tid - 64]);
}

__device__ __forceinline__ void load_coef(float* sc, const float* __restrict__ stats,
                                          const float* __restrict__ g,
                                          const float* __restrict__ b, int n, int tid) {
    if (tid < 64) {
        float inv_n = 1.f / (float)n;
        float mean = stats[tid] * inv_n;
        float var = stats[64 + tid] * inv_n - mean * mean;
        float a = g[tid] * rsqrtf(var + 1e-3f);
        sc[tid] = a;
        sc[64 + tid] = b[tid] - mean * a;
    }
}

// ---------------- prepack ----------------
__global__ void k_prepack(const float* __restrict__ Wlw, const float* __restrict__ Ww,
                          const float* __restrict__ Wproj, const float* __restrict__ Wfuse,
                          unsigned* __restrict__ pack) {
    int t = blockIdx.x;     // 0..11
    const float* src;
    if (t < 3)       src = Wlw  + t * 4096;
    else if (t < 6)  src = Ww   + (t - 3) * 4096;
    else if (t < 10) src = Wproj+ (t - 6) * 4096;
    else             src = Wfuse+ (t - 10) * 4096;
    unsigned* ph = pack + (size_t)t * 4608;
    unsigned* pl = ph + 2304;
    for (int idx = threadIdx.x; idx < 2048; idx += 256) {
        int cout = idx & 63, p = idx >> 6;
        unsigned h, l;
        split2(src[2 * p * 64 + cout], src[(2 * p + 1) * 64 + cout], h, l);
        ph[cout * AS + p] = h;
        pl[cout * AS + p] = l;
    }
}
__global__ void k_prepackc(const float* __restrict__ Wc1, const float* __restrict__ Wc2,
                           unsigned* __restrict__ packc) {
    int t = blockIdx.x;     // 0..53
    const float* src = (t < 27) ? Wc1 + t * 4096 : Wc2 + (t - 27) * 4096;
    unsigned* ph = packc + (size_t)t * 2304;
    for (int idx = threadIdx.x; idx < 2048; idx += 256) {
        int cout = idx & 63, p = idx >> 6;
        ph[cout * AS + p] = packh2(src[2 * p * 64 + cout], src[(2 * p + 1) * 64 + cout]);
    }
}

// F = relu(bn(rawF)) + feat; emit fp16 plane of F
__global__ void k_bnrelu_add_split(float* __restrict__ F, const float* __restrict__ stats,
                                   const float* __restrict__ g, const float* __restrict__ b,
                                   const float* __restrict__ feat,
                                   unsigned* __restrict__ Hp, int n, int total4) {
    __shared__ float sc[128];
    load_coef(sc, stats, g, b, n, threadIdx.x);
    __syncthreads();
    int i = blockIdx.x * 256 + threadIdx.x;
    if (i >= total4) return;
    int ch = (i & 15) * 4;
    float4 x = ((const float4*)F)[i];
    float4 r = ((const float4*)feat)[i];
    x.x = fmaxf(x.x * sc[ch + 0] + sc[64 + ch + 0], 0.f) + r.x;
    x.y = fmaxf(x.y * sc[ch + 1] + sc[64 + ch + 1], 0.f) + r.y;
    x.z = fmaxf(x.z * sc[ch + 2] + sc[64 + ch + 2], 0.f) + r.z;
    x.w = fmaxf(x.w * sc[ch + 3] + sc[64 + ch + 3], 0.f) + r.w;
    ((float4*)F)[i] = x;
    ((uint2*)Hp)[i] = make_uint2(packh2(x.x, x.y), packh2(x.z, x.w));
}

// fp16 plane = relu(bn(P))
__global__ void k_bnrelu_split(const float* __restrict__ P, const float* __restrict__ stats,
                               const float* __restrict__ g, const float* __restrict__ b,
                               unsigned* __restrict__ Hp, int n, int total4) {
    __shared__ float sc[128];
    load_coef(sc, stats, g, b, n, threadIdx.x);
    __syncthreads();
    int i = blockIdx.x * 256 + threadIdx.x;
    if (i >= total4) return;
    int ch = (i & 15) * 4;
    float4 x = ((const float4*)P)[i];
    x.x = fmaxf(x.x * sc[ch + 0] + sc[64 + ch + 0], 0.f);
    x.y = fmaxf(x.y * sc[ch + 1] + sc[64 + ch + 1], 0.f);
    x.z = fmaxf(x.z * sc[ch + 2] + sc[64 + ch + 2], 0.f);
    x.w = fmaxf(x.w * sc[ch + 3] + sc[64 + ch + 3], 0.f);
    ((uint2*)Hp)[i] = make_uint2(packh2(x.x, x.y), packh2(x.z, x.w));
}

// ---------------- tensor-core kernels ----------------
// 7 GEMMs sharing A=feat (converted in staging): outputs P0..P2,Q0..Q3 + stats
__global__ __launch_bounds__(NTHR)
void k_mma_gemm7(const float* __restrict__ feat, const unsigned* __restrict__ pack,
                 float* __restrict__ bufs, float* __restrict__ statsg, int n) {
    extern __shared__ unsigned sm[];     // A:[0,9216) B0:[9216,13824) B1:[13824,18432)
    __shared__ float csum[64], csq[64];
    const int tidx[7] = {0, 1, 2, 6, 7, 8, 9};
    int tid = threadIdx.x, wid = tid >> 5, lane = tid & 31;
    int row0 = blockIdx.x * TM;
    stage_B(sm + OFF_B, pack + (size_t)tidx[0] * 4608, tid);
    cp_commit();
#pragma unroll
    for (int i = 0; i < 8; ++i) {   // convert feat -> hi/lo planes
        int idx = tid + i * NTHR;
        int r = idx >> 4, c4 = idx & 15;
        int grow = row0 + r;
        float4 v = make_float4(0.f, 0.f, 0.f, 0.f);
        if (grow < n) v = *(const float4*)(feat + (size_t)grow * 64 + c4 * 4);
        a_store(sm, r, c4, v);
    }
    for (int t = 0; t < 7; ++t) {
        unsigned* bcur = sm + OFF_B + (t & 1) * 4608;
        if (t + 1 < 7) {
            stage_B(sm + OFF_B + ((t + 1) & 1) * 4608, pack + (size_t)tidx[t + 1] * 4608, tid);
            cp_commit();
            cp_wait<1>();
        } else {
            cp_wait<0>();
        }
        if (tid < 64) { csum[tid] = 0.f; csq[tid] = 0.f; }
        __syncthreads();
        float acc[8][4] = {};
        mma_compute(sm, bcur, acc, wid, lane);
        epilogue_stats(acc, bufs + (size_t)t * ROWSZ, statsg + t * 128,
                       csum, csq, row0, n, wid, lane, tid);
        __syncthreads();
    }
}

// gather conv (fp16 single-plane), round-7 double-buffer + idx cache; + stats
__global__ __launch_bounds__(NTHR)
void k_mma_convh(const uint4* __restrict__ AF, const int* __restrict__ nbr,
                 const unsigned* __restrict__ packc,
                 float* __restrict__ Co, float* __restrict__ statsg, int n) {
    extern __shared__ unsigned sm[];          // 2 x CBUF + idx cache
    int* idxs = (int*)(sm + 2 * CBUF);        // [TM*27]
    __shared__ float csum[64], csq[64];
    int tid = threadIdx.x, wid = tid >> 5, lane = tid & 31;
    int row0 = blockIdx.x * TM;
    if (tid < 64) { csum[tid] = 0.f; csq[tid] = 0.f; }
    {   // coalesced preload of neighbor indices
        size_t base = (size_t)row0 * 27;
        size_t lim = (size_t)n * 27;
        for (int i = tid; i < TM * 27; i += NTHR) {
            size_t pos = base + i;
            idxs[i] = (pos < lim) ? __ldg(&nbr[pos]) : 0;
        }
    }
    __syncthreads();
    int row = tid >> 1, pl = tid & 1;
    bool v = (row0 + row) < n;
    {   // prologue: tap 0
        unsigned* b0 = sm;
        stage_Bc(b0 + COFF_B, packc, tid);
        const uint4* s = AF + (size_t)idxs[row * 27] * 8 + pl * 4;
        unsigned* d = b0 + row * AS + pl * 16;
#pragma unroll
        for (int c = 0; c < 4; ++c) cp16(d + c * 4, s + c, v);
        cp_commit();
    }
    float acc[8][4] = {};
    for (int k = 0; k < 27; ++k) {
        unsigned* cur = sm + (k & 1) * CBUF;
        if (k + 1 < 27) {
            unsigned* nb = sm + ((k + 1) & 1) * CBUF;
            stage_Bc(nb + COFF_B, packc + (size_t)(k + 1) * 2304, tid);
            const uint4* s = AF + (size_t)idxs[row * 27 + k + 1] * 8 + pl * 4;
            unsigned* d = nb + row * AS + pl * 16;
#pragma unroll
            for (int c = 0; c < 4; ++c) cp16(d + c * 4, s + c, v);
            cp_commit();
            cp_wait<1>();
        } else {
            cp_wait<0>();
        }
        __syncthreads();
        mma_compute_h(cur, acc, wid, lane);
        __syncthreads();
    }
    epilogue_stats(acc, Co, statsg, csum, csq, row0, n, wid, lane, tid);
}

// per-scale (gridDim.y=3): P = exp((relu(bn(P)) - mean[cl]) @ W_w); den += P
__global__ __launch_bounds__(NTHR)
void k_mma_submean_exp(float* __restrict__ bufs, const float* __restrict__ statsb,
                       const float* __restrict__ glw, const float* __restrict__ blw,
                       const unsigned* __restrict__ pack, const float* __restrict__ mean,
                       const float* __restrict__ cnt,
                       const int* __restrict__ cl0, const int* __restrict__ cl1,
                       const int* __restrict__ cl2, float* __restrict__ den, int n) {
    extern __shared__ unsigned buf[];
    __shared__ float coef[128];
    __shared__ int   cls[TM];
    __shared__ float cinv[TM];
    int s = blockIdx.y;
    const int* cl = (s == 0) ? cl0 : ((s == 1) ? cl1 : cl2);
    int soff = c_soff[s];
    float* P = bufs + (size_t)s * ROWSZ;
    int tid = threadIdx.x, wid = tid >> 5, lane = tid & 31;
    int row0 = blockIdx.x * TM;
    load_coef(coef, statsb + s * 128, glw + s * 64, blw + s * 64, n, tid);
    if (tid < 128) {
        int r = row0 + tid;
        int c = (r < n) ? cl[r] : 0;
        cls[tid] = c;
        cinv[tid] = 1.f / fmaxf(cnt[soff + c], 1.f);
    }
    stage_B(buf + OFF_B, pack + (size_t)(3 + s) * 4608, tid);
    cp_commit();
    __syncthreads();
#pragma unroll
    for (int i = 0; i < 8; ++i) {
        int idx = tid + i * NTHR;
        int r = idx >> 4, c4 = idx & 15;
        int grow = row0 + r;
        float4 vv = make_float4(0.f, 0.f, 0.f, 0.f);
        if (grow < n) {
            vv = *(const float4*)(P + (size_t)grow * 64 + c4 * 4);
            float4 ms = *(const float4*)(mean + (size_t)(soff + cls[r]) * 64 + c4 * 4);
            float ci = cinv[r];
            int ch = c4 * 4;
            vv.x = fmaxf(vv.x * coef[ch + 0] + coef[64 + ch + 0], 0.f) - ms.x * ci;
            vv.y = fmaxf(vv.y * coef[ch + 1] + coef[64 + ch + 1], 0.f) - ms.y * ci;
            vv.z = fmaxf(vv.z * coef[ch + 2] + coef[64 + ch + 2], 0.f) - ms.z * ci;
            vv.w = fmaxf(vv.w * coef[ch + 3] + coef[64 + ch + 3], 0.f) - ms.w * ci;
        }
        a_store(buf, r, c4, vv);
    }
    cp_wait<0>();
    __syncthreads();
    float acc[8][4] = {};
    mma_compute(buf, buf + OFF_B, acc, wid, lane);
    int g = lane >> 2, c = lane & 3;
    int lr0 = wid * 16 + g, lr1 = lr0 + 8;
    int r0 = row0 + lr0, r1 = row0 + lr1;
    float* d0 = den + (size_t)(soff + cls[lr0]) * 64;
    float* d1 = den + (size_t)(soff + cls[lr1]) * 64;
#pragma unroll
    for (int nt = 0; nt < 8; ++nt) {
        int ch = nt * 8 + 2 * c;
        if (r0 < n) {
            float e0 = __expf(acc[nt][0]), e1 = __expf(acc[nt][1]);
            *(float2*)(P + (size_t)r0 * 64 + ch) = make_float2(e0, e1);
            red_add_v2(d0 + ch, e0, e1);
        }
        if (r1 < n) {
            float e2 = __expf(acc[nt][2]), e3 = __expf(acc[nt][3]);
            *(float2*)(P + (size_t)r1 * 64 + ch) = make_float2(e2, e3);
            red_add_v2(d1 + ch, e2, e3);
        }
    }
}

// fuse GEMM: Co = relu(bn(Q))@Wf[0:64] + mix@Wf[64:128] + stats
__global__ __launch_bounds__(NTHR)
void k_mma_gemm2(const float* __restrict__ Q, const float* __restrict__ stats,
                 const float* __restrict__ gg, const float* __restrict__ bb,
                 const unsigned* __restrict__ tiles, const float* __restrict__ segS,
                 const int* __restrict__ cl0, const int* __restrict__ cl1,
                 const int* __restrict__ cl2, const float* __restrict__ adp,
                 float* __restrict__ Co, float* __restrict__ statsg, int n) {
    extern __shared__ unsigned buf[];
    __shared__ float csum[64], csq[64];
    __shared__ float coef[128];
    __shared__ int   cls[3][TM];
    __shared__ float sad[3][TM];
    int tid = threadIdx.x, wid = tid >> 5, lane = tid & 31;
    int row0 = blockIdx.x * TM;
    if (tid < 64) { csum[tid] = 0.f; csq[tid] = 0.f; }
    load_coef(coef, stats, gg, bb, n, tid);
    if (tid < 128) {
        int r = row0 + tid;
        bool v = r < n;
        cls[0][tid] = v ? cl0[r] : 0;
        cls[1][tid] = v ? cl1[r] : 0;
        cls[2][tid] = v ? cl2[r] : 0;
        sad[0][tid] = v ? adp[(size_t)r * 3 + 0] : 0.f;
        sad[1][tid] = v ? adp[(size_t)r * 3 + 1] : 0.f;
        sad[2][tid] = v ? adp[(size_t)r * 3 + 2] : 0.f;
    }
    __syncthreads();
    float acc[8][4] = {};
#pragma unroll
    for (int p = 0; p < 2; ++p) {
        stage_B(buf + OFF_B, tiles + (size_t)p * 4608, tid);
        cp_commit();
#pragma unroll
        for (int i = 0; i < 8; ++i) {
            int idx = tid + i * NTHR;
            int r = idx >> 4, c4 = idx & 15;
            int grow = row0 + r;
            float4 vv = make_float4(0.f, 0.f, 0.f, 0.f);
            if (grow < n) {
                if (p == 0) {
                    vv = *(const float4*)(Q + (size_t)grow * 64 + c4 * 4);
                    int ch = c4 * 4;
                    vv.x = fmaxf(vv.x * coef[ch + 0] + coef[64 + ch + 0], 0.f);
                    vv.y = fmaxf(vv.y * coef[ch + 1] + coef[64 + ch + 1], 0.f);
                    vv.z = fmaxf(vv.z * coef[ch + 2] + coef[64 + ch + 2], 0.f);
                    vv.w = fmaxf(vv.w * coef[ch + 3] + coef[64 + ch + 3], 0.f);
                } else {
                    float w0 = sad[0][r], w1 = sad[1][r], w2 = sad[2][r];
                    float4 a = *(const float4*)(segS + (size_t)(0 + cls[0][r]) * 64 + c4 * 4);
                    float4 bv = *(const float4*)(segS + (size_t)(4096 + cls[1][r]) * 64 + c4 * 4);
                    float4 cc = *(const float4*)(segS + (size_t)(36864 + cls[2][r]) * 64 + c4 * 4);
                    vv.x = w0 * a.x + w1 * bv.x + w2 * cc.x;
                    vv.y = w0 * a.y + w1 * bv.y + w2 * cc.y;
                    vv.z = w0 * a.z + w1 * bv.z + w2 * cc.z;
                    vv.w = w0 * a.w + w1 * bv.w + w2 * cc.w;
                }
            }
            a_store(buf, r, c4, vv);
        }
        cp_wait<0>();
        __syncthreads();
        mma_compute(buf, buf + OFF_B, acc, wid, lane);
        __syncthreads();
    }
    epilogue_stats(acc, Co, statsg, csum, csq, row0, n, wid, lane, tid);
}

// ---------------- small / elementwise kernels ----------------
__global__ void k_adp(const float* __restrict__ feat, const float* __restrict__ Wa,
                      float* __restrict__ adp, int n) {
    __shared__ float w[192];
    if (threadIdx.x < 192) w[threadIdx.x] = Wa[threadIdx.x];
    __syncthreads();
    int row = blockIdx.x * blockDim.x + threadIdx.x;
    if (row >= n) return;
    float s0 = 0.f, s1 = 0.f, s2 = 0.f;
    const float* f = feat + (size_t)row * 64;
#pragma unroll 16
    for (int c = 0; c < 64; ++c) {
        float v = f[c];
        s0 += v * w[c * 3 + 0];
        s1 += v * w[c * 3 + 1];
        s2 += v * w[c * 3 + 2];
    }
    float m = fmaxf(s0, fmaxf(s1, s2));
    float e0 = __expf(s0 - m), e1 = __expf(s1 - m), e2 = __expf(s2 - m);
    float inv = 1.f / (e0 + e1 + e2);
    adp[(size_t)row * 3 + 0] = e0 * inv;
    adp[(size_t)row * 3 + 1] = e1 * inv;
    adp[(size_t)row * 3 + 2] = e2 * inv;
}

// per-scale (gridDim.y=3): mean-arena += relu(bn(P)), cnt++
__global__ void k_segsum3(const float* __restrict__ bufs, const float* __restrict__ statsb,
                          const float* __restrict__ glw, const float* __restrict__ blw,
                          const int* __restrict__ cl0, const int* __restrict__ cl1,
                          const int* __restrict__ cl2, float* __restrict__ mean,
                          float* __restrict__ cnt, int n) {
    __shared__ float sc[128];
    int s = blockIdx.y;
    load_coef(sc, statsb + s * 128, glw + s * 64, blw + s * 64, n, threadIdx.x);
    __syncthreads();
    int row = blockIdx.x * blockDim.x + threadIdx.x;
    if (row >= n) return;
    const int* cl = (s == 0) ? cl0 : ((s == 1) ? cl1 : cl2);
    int c = c_soff[s] + cl[row];
    const float* p = bufs + (size_t)s * ROWSZ + (size_t)row * 64;
    float* sg = mean + (size_t)c * 64;
#pragma unroll
    for (int c4 = 0; c4 < 16; ++c4) {
        float4 x = *(const float4*)(p + c4 * 4);
        x.x = fmaxf(x.x * sc[c4 * 4 + 0] + sc[64 + c4 * 4 + 0], 0.f);
        x.y = fmaxf(x.y * sc[c4 * 4 + 1] + sc[64 + c4 * 4 + 1], 0.f);
        x.z = fmaxf(x.z * sc[c4 * 4 + 2] + sc[64 + c4 * 4 + 2], 0.f);
        x.w = fmaxf(x.w * sc[c4 * 4 + 3] + sc[64 + c4 * 4 + 3], 0.f);
        red_add_v4(sg + c4 * 4, x);
    }
    atomicAdd(&cnt[c], 1.f);
}

// per-scale (gridDim.y=3): segS += relu(bn(Q)) * expP / (den[cl]+1e-6)
__global__ void k_pw3(const float* __restrict__ bufs, const float* __restrict__ statsb,
                      const float* __restrict__ gproj, const float* __restrict__ bproj,
                      const float* __restrict__ den,
                      const int* __restrict__ cl0, const int* __restrict__ cl1,
                      const int* __restrict__ cl2, float* __restrict__ segS, int n) {
    __shared__ float sc[128];
    int s = blockIdx.y;
    load_coef(sc, statsb + (3 + s) * 128, gproj + s * 64, bproj + s * 64, n, threadIdx.x);
    __syncthreads();
    int row = blockIdx.x * blockDim.x + threadIdx.x;
    if (row >= n) return;
    const int* cl = (s == 0) ? cl0 : ((s == 1) ? cl1 : cl2);
    int c = c_soff[s] + cl[row];
    const float* q = bufs + (size_t)(3 + s) * ROWSZ + (size_t)row * 64;
    const float* p = bufs + (size_t)s * ROWSZ + (size_t)row * 64;
    const float* d = den + (size_t)c * 64;
    float* sg = segS + (size_t)c * 64;
#pragma unroll
    for (int c4 = 0; c4 < 16; ++c4) {
        float4 qv = *(const float4*)(q + c4 * 4);
        float4 pv = *(const float4*)(p + c4 * 4);
        float4 dv = *(const float4*)(d + c4 * 4);
        float4 o;
        o.x = fmaxf(qv.x * sc[c4 * 4 + 0] + sc[64 + c4 * 4 + 0], 0.f) * pv.x / (dv.x + 1e-6f);
        o.y = fmaxf(qv.y * sc[c4 * 4 + 1] + sc[64 + c4 * 4 + 1], 0.f) * pv.y / (dv.y + 1e-6f);
        o.z = fmaxf(qv.z * sc[c4 * 4 + 2] + sc[64 + c4 * 4 + 2], 0.f) * pv.z / (dv.z + 1e-6f);
        o.w = fmaxf(qv.w * sc[c4 * 4 + 3] + sc[64 + c4 * 4 + 3], 0.f) * pv.w / (dv.w + 1e-6f);
        red_add_v4(sg + c4 * 4, o);
    }
}

// out = relu(bn(H) + F)
__global__ void k_final(const float* __restrict__ H, const float* __restrict__ stats,
                        const float* __restrict__ g, const float* __restrict__ b,
                        const float* __restrict__ F, float* __restrict__ out,
                        int n, int total4) {
    __shared__ float sc[128];
    load_coef(sc, stats, g, b, n, threadIdx.x);
    __syncthreads();
    int i = blockIdx.x * 256 + threadIdx.x;
    if (i >= total4) return;
    int ch = (i & 15) * 4;
    float4 x = ((const float4*)H)[i];
    float4 r = ((const float4*)F)[i];
    x.x = fmaxf(x.x * sc[ch + 0] + sc[64 + ch + 0] + r.x, 0.f);
    x.y = fmaxf(x.y * sc[ch + 1] + sc[64 + ch + 1] + r.y, 0.f);
    x.z = fmaxf(x.z * sc[ch + 2] + sc[64 + ch + 2] + r.z, 0.f);
    x.w = fmaxf(x.w * sc[ch + 3] + sc[64 + ch + 3] + r.w, 0.f);
    ((float4*)out)[i] = x;
}

// ---------------------------------------------------------------------------
extern "C" void kernel_launch(void* const* d_in, const int* in_sizes, int n_in,
                              void* d_out, int out_size) {
    const float* feat   = (const float*)d_in[0];
    const int*   cl0    = (const int*)d_in[1];
    const int*   cl1    = (const int*)d_in[2];
    const int*   cl2    = (const int*)d_in[3];
    const int*   nbr    = (const int*)d_in[4];
    const float* W_lw   = (const float*)d_in[5];
    const float* g_lw   = (const float*)d_in[6];
    const float* b_lw   = (const float*)d_in[7];
    const float* W_w    = (const float*)d_in[8];
    const float* W_proj = (const float*)d_in[9];
    const float* g_proj = (const float*)d_in[10];
    const float* b_proj = (const float*)d_in[11];
    const float* W_adp  = (const float*)d_in[12];
    const float* W_fuse = (const float*)d_in[13];
    const float* g_fuse = (const float*)d_in[14];
    const float* b_fuse = (const float*)d_in[15];
    const float* W_c1   = (const float*)d_in[16];
    const float* g_c1   = (const float*)d_in[17];
    const float* b_c1   = (const float*)d_in[18];
    const float* W_c2   = (const float*)d_in[19];
    const float* g_c2   = (const float*)d_in[20];
    const float* b_c2   = (const float*)d_in[21];
    float* out = (float*)d_out;
    int n = in_sizes[1];

    float *pBufs, *pF, *pMean, *pDen, *pSegS, *pCnt, *pStats, *pAdp;
    unsigned *pPack, *pPackC, *pFph;
    cudaGetSymbolAddress((void**)&pBufs, g_bufs);
    cudaGetSymbolAddress((void**)&pF, g_bufF);
    cudaGetSymbolAddress((void**)&pFph, g_fph);
    cudaGetSymbolAddress((void**)&pMean, g_segMean);
    cudaGetSymbolAddress((void**)&pDen, g_segDen);
    cudaGetSymbolAddress((void**)&pSegS, g_segS);
    cudaGetSymbolAddress((void**)&pCnt, g_cnt);
    cudaGetSymbolAddress((void**)&pStats, g_statsA);
    cudaGetSymbolAddress((void**)&pAdp, g_adpv);
    cudaGetSymbolAddress((void**)&pPack, g_wpack);
    cudaGetSymbolAddress((void**)&pPackC, g_wpackc);

    const int GB = (n + TM - 1) / TM;
    const int EB = (n + 255) / 256;
    const int total4 = n * 16;
    const int SB = (total4 + 255) / 256;
    const int SM_G7 = 18432 * 4;                    // 73728B
    const int SM_1  = 13824 * 4;                    // 55296B
    const int SM_CV = (2 * CBUF + TM * 27) * 4;     // 69120B

    cudaFuncSetAttribute(k_mma_gemm7, cudaFuncAttributeMaxDynamicSharedMemorySize, SM_G7);
    cudaFuncSetAttribute(k_mma_submean_exp, cudaFuncAttributeMaxDynamicSharedMemorySize, SM_1);
    cudaFuncSetAttribute(k_mma_gemm2, cudaFuncAttributeMaxDynamicSharedMemorySize, SM_1);
    cudaFuncSetAttribute(k_mma_convh, cudaFuncAttributeMaxDynamicSharedMemorySize, SM_CV);

    const uint4* AF = (const uint4*)pFph;
    float* Qb3 = pBufs + 6 * ROWSZ;

    k_prepack<<<12, 256>>>(W_lw, W_w, W_proj, W_fuse, pPack);
    k_prepackc<<<54, 256>>>(W_c1, W_c2, pPackC);
    k_adp<<<EB, 256>>>(feat, W_adp, pAdp, n);

    // 7 feat-GEMMs (feat converted in staging)
    cudaMemsetAsync(pStats, 0, 7 * 128 * sizeof(float));
    k_mma_gemm7<<<GB, NTHR, SM_G7>>>(feat, pPack, pBufs, pStats, n);

    // cluster attention, all 3 scales batched
    cudaMemsetAsync(pMean, 0, (size_t)SEGTOT * 64 * sizeof(float));
    cudaMemsetAsync(pCnt, 0, (size_t)SEGTOT * sizeof(float));
    k_segsum3<<<dim3(EB, 3), 256>>>(pBufs, pStats, g_lw, b_lw, cl0, cl1, cl2,
                                    pMean, pCnt, n);
    cudaMemsetAsync(pDen, 0, (size_t)SEGTOT * 64 * sizeof(float));
    k_mma_submean_exp<<<dim3(GB, 3), NTHR, SM_1>>>(pBufs, pStats, g_lw, b_lw, pPack,
                                                   pMean, pCnt, cl0, cl1, cl2, pDen, n);
    cudaMemsetAsync(pSegS, 0, (size_t)SEGTOT * 64 * sizeof(float));
    k_pw3<<<dim3(EB, 3), 256>>>(pBufs, pStats, g_proj, b_proj, pDen,
                                cl0, cl1, cl2, pSegS, n);

    // fused = relu(bn([relu(bn(Q3)), mix] @ W_fuse)) + feat
    cudaMemsetAsync(pStats + 7 * 128, 0, 128 * sizeof(float));
    k_mma_gemm2<<<GB, NTHR, SM_1>>>(Qb3, pStats + 6 * 128, g_proj + 192, b_proj + 192,
                                    pPack + (size_t)10 * 4608, pSegS,
                                    cl0, cl1, cl2, pAdp, pF, pStats + 7 * 128, n);
    k_bnrelu_add_split<<<SB, 256>>>(pF, pStats + 7 * 128, g_fuse, b_fuse, feat,
                                    pFph, n, total4);
    // conv1 -> split ; conv2 -> final
    cudaMemsetAsync(pStats + 8 * 128, 0, 128 * sizeof(float));
    k_mma_convh<<<GB, NTHR, SM_CV>>>(AF, nbr, pPackC, pBufs, pStats + 8 * 128, n);
    k_bnrelu_split<<<SB, 256>>>(pBufs, pStats + 8 * 128, g_c1, b_c1, pFph, n, total4);
    cudaMemsetAsync(pStats + 9 * 128, 0, 128 * sizeof(float));
    k_mma_convh<<<GB, NTHR, SM_CV>>>(AF, nbr, pPackC + (size_t)27 * 2304,
                                     pBufs + ROWSZ, pStats + 9 * 128, n);
    k_final<<<SB, 256>>>(pBufs + ROWSZ, pStats + 9 * 128, g_c2, b_c2, pF, out, n, total4);
}

// round 10
// speedup vs baseline: 1.9495x; 1.0394x over previous
#include <cuda_runtime.h>
#include <cuda_bf16.h>
#include <cuda_fp16.h>

// ---------------------------------------------------------------------------
// OACNNs block, round 10.
//  - conv staging switched from per-16B cp.async (1600 ops/tap, LSU-bound)
//    to cp.async.bulk + mbarrier (129 ops/tap): one 128B bulk per gathered
//    A row, one 9216B bulk per B tile.
//  - everything else identical to round 9 (3037us, rel_err 2.9e-4).
// ---------------------------------------------------------------------------

#define NPTS_MAX 500000
#define SEGTOT   167936     // 4096 + 32768 + 131072
#define TM   128
#define NTHR 256
#define AS   36             // uints per row (144B stride, LDSM conflict-free)
#define OFF_AL 4608        // TM*AS   (A lo plane)
#define OFF_B  9216        // 2*TM*AS (B region within a bf16 tile buffer)
#define CBUF   6912        // uints per fp16 conv buffer (A 4608 + B 2304)
#define COFF_B 4608
#define ROWSZ  ((size_t)NPTS_MAX * 64)
#define CONV_TX 25600u     // 128 rows * 128B + 9216B B tile

// scratch (device globals: allocation-free rule)
__device__ float          g_bufs[7 * ROWSZ];     // P0,P1,P2,Q0,Q1,Q2,Q3
__device__ float          g_bufF[ROWSZ];
__device__ unsigned       g_fph[NPTS_MAX * 32];  // fp16 plane of conv input
__device__ float          g_segMean[SEGTOT * 64];
__device__ float          g_segDen [SEGTOT * 64];
__device__ float          g_segS   [SEGTOT * 64];
__device__ float          g_cnt    [SEGTOT];
__device__ float          g_adpv[NPTS_MAX * 3];
__device__ float          g_statsA[10 * 128];    // 0-6 gemm7, 7 fuse, 8 c1, 9 c2
__device__ unsigned       g_wpack[12 * 4608];    // bf16 hi/lo tiles (lw,w,proj,fuse)
__device__ unsigned       g_wpackc[54 * 2304];   // fp16 conv tiles

__device__ __constant__ int c_soff[3] = {0, 4096, 36864};

// ---------------- helpers ----------------
__device__ __forceinline__ void red_add_v4(float* addr, float4 v) {
    asm volatile("red.global.add.v4.f32 [%0], {%1,%2,%3,%4};"
                 :: "l"(addr), "f"(v.x), "f"(v.y), "f"(v.z), "f"(v.w)
                 : "memory");
}
__device__ __forceinline__ void red_add_v2(float* addr, float x, float y) {
    asm volatile("red.global.add.v2.f32 [%0], {%1,%2};"
                 :: "l"(addr), "f"(x), "f"(y) : "memory");
}
__device__ __forceinline__ void cp16(unsigned* dst, const void* src, bool v) {
    unsigned d = (unsigned)__cvta_generic_to_shared(dst);
    int sz = v ? 16 : 0;
    asm volatile("cp.async.cg.shared.global [%0], [%1], 16, %2;"
                 :: "r"(d), "l"(src), "r"(sz) : "memory");
}
__device__ __forceinline__ void cp_commit() {
    asm volatile("cp.async.commit_group;" ::: "memory");
}
template <int N> __device__ __forceinline__ void cp_wait() {
    asm volatile("cp.async.wait_group %0;" :: "n"(N) : "memory");
}
__device__ __forceinline__ void cpbulk(unsigned dst, const void* src,
                                       unsigned bytes, unsigned mba) {
    asm volatile(
        "cp.async.bulk.shared::cluster.global.mbarrier::complete_tx::bytes "
        "[%0], [%1], %2, [%3];"
        :: "r"(dst), "l"(src), "r"(bytes), "r"(mba) : "memory");
}
__device__ __forceinline__ void mbar_init(unsigned mba, unsigned cnt) {
    asm volatile("mbarrier.init.shared.b64 [%0], %1;" :: "r"(mba), "r"(cnt) : "memory");
}
__device__ __forceinline__ void mbar_expect(unsigned mba, unsigned bytes) {
    asm volatile("mbarrier.arrive.expect_tx.shared.b64 _, [%0], %1;"
                 :: "r"(mba), "r"(bytes) : "memory");
}
__device__ __forceinline__ void mbar_wait(unsigned mba, int phase) {
    asm volatile(
        "{\n\t"
        ".reg .pred P;\n\t"
        "LAB_%=:\n\t"
        "mbarrier.try_wait.parity.acquire.cta.shared::cta.b64 P, [%0], %1;\n\t"
        "@!P bra LAB_%=;\n\t"
        "}"
        :: "r"(mba), "r"(phase) : "memory");
}

__device__ __forceinline__ void split2(float x, float y, unsigned& h, unsigned& l) {
    __nv_bfloat16 hx = __float2bfloat16(x), hy = __float2bfloat16(y);
    float lx = x - __bfloat162float(hx);
    float ly = y - __bfloat162float(hy);
    __nv_bfloat162 hp; hp.x = hx; hp.y = hy;
    __nv_bfloat162 lp; lp.x = __float2bfloat16(lx); lp.y = __float2bfloat16(ly);
    h = *reinterpret_cast<unsigned*>(&hp);
    l = *reinterpret_cast<unsigned*>(&lp);
}
__device__ __forceinline__ unsigned packh2(float x, float y) {
    __half2 h; h.x = __float2half(x); h.y = __float2half(y);
    return *reinterpret_cast<unsigned*>(&h);
}

__device__ __forceinline__ void mma16816(float* d, unsigned a0, unsigned a1,
                                         unsigned a2, unsigned a3,
                                         unsigned b0, unsigned b1) {
    asm volatile(
        "mma.sync.aligned.m16n8k16.row.col.f32.bf16.bf16.f32 "
        "{%0,%1,%2,%3}, {%4,%5,%6,%7}, {%8,%9}, {%0,%1,%2,%3};"
        : "+f"(d[0]), "+f"(d[1]), "+f"(d[2]), "+f"(d[3])
        : "r"(a0), "r"(a1), "r"(a2), "r"(a3), "r"(b0), "r"(b1));
}
__device__ __forceinline__ void mma16816h(float* d, unsigned a0, unsigned a1,
                                          unsigned a2, unsigned a3,
                                          unsigned b0, unsigned b1) {
    asm volatile(
        "mma.sync.aligned.m16n8k16.row.col.f32.f16.f16.f32 "
        "{%0,%1,%2,%3}, {%4,%5,%6,%7}, {%8,%9}, {%0,%1,%2,%3};"
        : "+f"(d[0]), "+f"(d[1]), "+f"(d[2]), "+f"(d[3])
        : "r"(a0), "r"(a1), "r"(a2), "r"(a3), "r"(b0), "r"(b1));
}
__device__ __forceinline__ void ldsm4(unsigned& r0, unsigned& r1, unsigned& r2,
                                      unsigned& r3, const unsigned* p) {
    unsigned a = (unsigned)__cvta_generic_to_shared(p);
    asm volatile("ldmatrix.sync.aligned.m8n8.x4.shared.b16 {%0,%1,%2,%3}, [%4];"
                 : "=r"(r0), "=r"(r1), "=r"(r2), "=r"(r3) : "r"(a));
}

__device__ __forceinline__ void a_store(unsigned* buf, int r, int c4, float4 v) {
    unsigned h0, l0, h1, l1;
    split2(v.x, v.y, h0, l0);
    split2(v.z, v.w, h1, l1);
    int w = r * AS + c4 * 2;
    *reinterpret_cast<uint2*>(buf + w)          = make_uint2(h0, h1);
    *reinterpret_cast<uint2*>(buf + OFF_AL + w) = make_uint2(l0, l1);
}

__device__ __forceinline__ void stage_B(unsigned* Bdst, const unsigned* tile, int tid) {
    const uint4* s = reinterpret_cast<const uint4*>(tile);
    for (int i = tid; i < 1152; i += NTHR) cp16(Bdst + i * 4, s + i, true);
}

// 128x64x64 (x3 split) bf16 mma sweep via ldmatrix
__device__ __forceinline__ void mma_compute(const unsigned* Areg, const unsigned* Breg,
                                            float acc[8][4], int wid, int lane) {
    const unsigned* Ah = Areg;
    const unsigned* Al = Areg + OFF_AL;
    const unsigned* Bh = Breg;
    const unsigned* Bl = Breg + 2304;
    int alr = lane & 15;
    int acol = (lane >> 4) * 4;
    const unsigned* aph = Ah + (wid * 16 + alr) * AS + acol;
    const unsigned* apl = Al + (wid * 16 + alr) * AS + acol;
    int brow = lane & 7;
    const unsigned* bp = ((lane & 16) ? Bl : Bh) + brow * AS + ((lane & 8) ? 4 : 0);
#pragma unroll
    for (int kk = 0; kk < 4; ++kk) {
        int ko = kk * 8;
        unsigned a0h, a1h, a2h, a3h, a0l, a1l, a2l, a3l;
        ldsm4(a0h, a1h, a2h, a3h, aph + ko);
        ldsm4(a0l, a1l, a2l, a3l, apl + ko);
#pragma unroll
        for (int nt = 0; nt < 8; ++nt) {
            unsigned b0h, b1h, b0l, b1l;
            ldsm4(b0h, b1h, b0l, b1l, bp + nt * 8 * AS + ko);
            mma16816(acc[nt], a0h, a1h, a2h, a3h, b0h, b1h);
            mma16816(acc[nt], a0l, a1l, a2l, a3l, b0h, b1h);
            mma16816(acc[nt], a0h, a1h, a2h, a3h, b0l, b1l);
        }
    }
}

// 128x64x64 fp16 single-plane mma sweep (conv path)
__device__ __forceinline__ void mma_compute_h(const unsigned* buf, float acc[8][4],
                                              int wid, int lane) {
    const unsigned* Ap = buf;
    const unsigned* Bp = buf + COFF_B;
    const unsigned* aph = Ap + (wid * 16 + (lane & 15)) * AS + (lane >> 4) * 4;
    int brow = lane & 7;
    int koff = ((lane >> 3) & 1) * 4;
    int ntoff = ((lane >> 4) & 1) * 8 * AS;
#pragma unroll
    for (int kk = 0; kk < 4; ++kk) {
        int ko = kk * 8;
        unsigned a0, a1, a2, a3;
        ldsm4(a0, a1, a2, a3, aph + ko);
#pragma unroll
        for (int np = 0; np < 4; ++np) {
            unsigned b0, b1, b2, b3;
            ldsm4(b0, b1, b2, b3, Bp + (np * 16 + brow) * AS + ntoff + ko + koff);
            mma16816h(acc[2 * np], a0, a1, a2, a3, b0, b1);
            mma16816h(acc[2 * np + 1], a0, a1, a2, a3, b2, b3);
        }
    }
}

__device__ __forceinline__ void epilogue_stats(float acc[8][4], float* __restrict__ Co,
                                               float* __restrict__ statsg,
                                               float* csum, float* csq,
                                               int row0, int n, int wid, int lane, int tid) {
    int g = lane >> 2, c = lane & 3;
    int r0 = row0 + wid * 16 + g, r1 = r0 + 8;
#pragma unroll
    for (int nt = 0; nt < 8; ++nt) {
        int ch = nt * 8 + 2 * c;
        if (r0 < n) *(float2*)(Co + (size_t)r0 * 64 + ch) = make_float2(acc[nt][0], acc[nt][1]);
        if (r1 < n) *(float2*)(Co + (size_t)r1 * 64 + ch) = make_float2(acc[nt][2], acc[nt][3]);
        float s0 = acc[nt][0] + acc[nt][2];
        float s1 = acc[nt][1] + acc[nt][3];
        float q0 = acc[nt][0] * acc[nt][0] + acc[nt][2] * acc[nt][2];
        float q1 = acc[nt][1] * acc[nt][1] + acc[nt][3] * acc[nt][3];
#pragma unroll
        for (int d = 4; d < 32; d <<= 1) {
            s0 += __shfl_xor_sync(0xffffffffu, s0, d);
            s1 += __shfl_xor_sync(0xffffffffu, s1, d);
            q0 += __shfl_xor_sync(0xffffffffu, q0, d);
            q1 += __shfl_xor_sync(0xffffffffu, q1, d);
        }
        if (lane < 4) {
            atomicAdd(&csum[ch], s0);
            atomicAdd(&csum[ch + 1], s1);
            atomicAdd(&csq[ch], q0);
            atomicAdd(&csq[ch + 1], q1);
        }
    }
    __syncthreads();
    if (tid < 64)       atomicAdd(&statsg[tid], csum[tid]);
    else if (tid < 128) atomicAdd(&statsg[tid], csq[tid - 64]);
}

__device__ __forceinline__ void load_coef(float* sc, const float* __restrict__ stats,
                                          const float* __restrict__ g,
                                          const float* __restrict__ b, int n, int tid) {
    if (tid < 64) {
        float inv_n = 1.f / (float)n;
        float mean = stats[tid] * inv_n;
        float var = stats[64 + tid] * inv_n - mean * mean;
        float a = g[tid] * rsqrtf(var + 1e-3f);
        sc[tid] = a;
        sc[64 + tid] = b[tid] - mean * a;
    }
}

// ---------------- prepack ----------------
__global__ void k_prepack(const float* __restrict__ Wlw, const float* __restrict__ Ww,
                          const float* __restrict__ Wproj, const float* __restrict__ Wfuse,
                          unsigned* __restrict__ pack) {
    int t = blockIdx.x;     // 0..11
    const float* src;
    if (t < 3)       src = Wlw  + t * 4096;
    else if (t < 6)  src = Ww   + (t - 3) * 4096;
    else if (t < 10) src = Wproj+ (t - 6) * 4096;
    else             src = Wfuse+ (t - 10) * 4096;
    unsigned* ph = pack + (size_t)t * 4608;
    unsigned* pl = ph + 2304;
    for (int idx = threadIdx.x; idx < 2048; idx += 256) {
        int cout = idx & 63, p = idx >> 6;
        unsigned h, l;
        split2(src[2 * p * 64 + cout], src[(2 * p + 1) * 64 + cout], h, l);
        ph[cout * AS + p] = h;
        pl[cout * AS + p] = l;
    }
}
__global__ void k_prepackc(const float* __restrict__ Wc1, const float* __restrict__ Wc2,
                           unsigned* __restrict__ packc) {
    int t = blockIdx.x;     // 0..53
    const float* src = (t < 27) ? Wc1 + t * 4096 : Wc2 + (t - 27) * 4096;
    unsigned* ph = packc + (size_t)t * 2304;
    for (int idx = threadIdx.x; idx < 2048; idx += 256) {
        int cout = idx & 63, p = idx >> 6;
        ph[cout * AS + p] = packh2(src[2 * p * 64 + cout], src[(2 * p + 1) * 64 + cout]);
    }
}

// F = relu(bn(rawF)) + feat; emit fp16 plane of F
__global__ void k_bnrelu_add_split(float* __restrict__ F, const float* __restrict__ stats,
                                   const float* __restrict__ g, const float* __restrict__ b,
                                   const float* __restrict__ feat,
                                   unsigned* __restrict__ Hp, int n, int total4) {
    __shared__ float sc[128];
    load_coef(sc, stats, g, b, n, threadIdx.x);
    __syncthreads();
    int i = blockIdx.x * 256 + threadIdx.x;
    if (i >= total4) return;
    int ch = (i & 15) * 4;
    float4 x = ((const float4*)F)[i];
    float4 r = ((const float4*)feat)[i];
    x.x = fmaxf(x.x * sc[ch + 0] + sc[64 + ch + 0], 0.f) + r.x;
    x.y = fmaxf(x.y * sc[ch + 1] + sc[64 + ch + 1], 0.f) + r.y;
    x.z = fmaxf(x.z * sc[ch + 2] + sc[64 + ch + 2], 0.f) + r.z;
    x.w = fmaxf(x.w * sc[ch + 3] + sc[64 + ch + 3], 0.f) + r.w;
    ((float4*)F)[i] = x;
    ((uint2*)Hp)[i] = make_uint2(packh2(x.x, x.y), packh2(x.z, x.w));
}

// fp16 plane = relu(bn(P))
__global__ void k_bnrelu_split(const float* __restrict__ P, const float* __restrict__ stats,
                               const float* __restrict__ g, const float* __restrict__ b,
                               unsigned* __restrict__ Hp, int n, int total4) {
    __shared__ float sc[128];
    load_coef(sc, stats, g, b, n, threadIdx.x);
    __syncthreads();
    int i = blockIdx.x * 256 + threadIdx.x;
    if (i >= total4) return;
    int ch = (i & 15) * 4;
    float4 x = ((const float4*)P)[i];
    x.x = fmaxf(x.x * sc[ch + 0] + sc[64 + ch + 0], 0.f);
    x.y = fmaxf(x.y * sc[ch + 1] + sc[64 + ch + 1], 0.f);
    x.z = fmaxf(x.z * sc[ch + 2] + sc[64 + ch + 2], 0.f);
    x.w = fmaxf(x.w * sc[ch + 3] + sc[64 + ch + 3], 0.f);
    ((uint2*)Hp)[i] = make_uint2(packh2(x.x, x.y), packh2(x.z, x.w));
}

// ---------------- tensor-core kernels ----------------
// 7 GEMMs sharing A=feat (converted in staging): outputs P0..P2,Q0..Q3 + stats
__global__ __launch_bounds__(NTHR)
void k_mma_gemm7(const float* __restrict__ feat, const unsigned* __restrict__ pack,
                 float* __restrict__ bufs, float* __restrict__ statsg, int n) {
    extern __shared__ unsigned sm[];     // A:[0,9216) B0:[9216,13824) B1:[13824,18432)
    __shared__ float csum[64], csq[64];
    const int tidx[7] = {0, 1, 2, 6, 7, 8, 9};
    int tid = threadIdx.x, wid = tid >> 5, lane = tid & 31;
    int row0 = blockIdx.x * TM;
    stage_B(sm + OFF_B, pack + (size_t)tidx[0] * 4608, tid);
    cp_commit();
#pragma unroll
    for (int i = 0; i < 8; ++i) {   // convert feat -> hi/lo planes
        int idx = tid + i * NTHR;
        int r = idx >> 4, c4 = idx & 15;
        int grow = row0 + r;
        float4 v = make_float4(0.f, 0.f, 0.f, 0.f);
        if (grow < n) v = *(const float4*)(feat + (size_t)grow * 64 + c4 * 4);
        a_store(sm, r, c4, v);
    }
    for (int t = 0; t < 7; ++t) {
        unsigned* bcur = sm + OFF_B + (t & 1) * 4608;
        if (t + 1 < 7) {
            stage_B(sm + OFF_B + ((t + 1) & 1) * 4608, pack + (size_t)tidx[t + 1] * 4608, tid);
            cp_commit();
            cp_wait<1>();
        } else {
            cp_wait<0>();
        }
        if (tid < 64) { csum[tid] = 0.f; csq[tid] = 0.f; }
        __syncthreads();
        float acc[8][4] = {};
        mma_compute(sm, bcur, acc, wid, lane);
        epilogue_stats(acc, bufs + (size_t)t * ROWSZ, statsg + t * 128,
                       csum, csq, row0, n, wid, lane, tid);
        __syncthreads();
    }
}

// stage one conv tap via cp.async.bulk into buffer `buf` tracked by mbar `mba`
__device__ __forceinline__ void conv_stage(unsigned smb, int buf, int k,
                                           const uint4* __restrict__ AF,
                                           const int* __restrict__ idxs,
                                           const unsigned* __restrict__ packc,
                                           unsigned mba, int tid) {
    unsigned bbase = smb + (unsigned)buf * (CBUF * 4);
    if (tid < 128) {
        const void* src = AF + (size_t)idxs[tid * 27 + k] * 8;
        cpbulk(bbase + tid * (AS * 4), src, 128, mba);
    } else if (tid == 128) {
        mbar_expect(mba, CONV_TX);
        cpbulk(bbase + COFF_B * 4, packc + (size_t)k * 2304, 9216, mba);
    }
}

// gather conv (fp16 single-plane), bulk-copy double-buffer pipeline; + stats
__global__ __launch_bounds__(NTHR)
void k_mma_convh(const uint4* __restrict__ AF, const int* __restrict__ nbr,
                 const unsigned* __restrict__ packc,
                 float* __restrict__ Co, float* __restrict__ statsg, int n) {
    extern __shared__ unsigned sm[];          // 2 x CBUF + idx cache
    int* idxs = (int*)(sm + 2 * CBUF);        // [TM*27]
    __shared__ float csum[64], csq[64];
    __shared__ unsigned long long mbar[2];
    int tid = threadIdx.x, wid = tid >> 5, lane = tid & 31;
    int row0 = blockIdx.x * TM;
    unsigned mb0 = (unsigned)__cvta_generic_to_shared(&mbar[0]);
    unsigned mb1 = (unsigned)__cvta_generic_to_shared(&mbar[1]);
    unsigned smb = (unsigned)__cvta_generic_to_shared(sm);
    if (tid < 64) { csum[tid] = 0.f; csq[tid] = 0.f; }
    if (tid == 0) { mbar_init(mb0, 1); mbar_init(mb1, 1); }
    {   // coalesced preload of neighbor indices
        size_t base = (size_t)row0 * 27;
        size_t lim = (size_t)n * 27;
        for (int i = tid; i < TM * 27; i += NTHR) {
            size_t pos = base + i;
            idxs[i] = (pos < lim) ? __ldg(&nbr[pos]) : 0;
        }
    }
    __syncthreads();
    int ph0 = 0, ph1 = 0;
    conv_stage(smb, 0, 0, AF, idxs, packc, mb0, tid);
    float acc[8][4] = {};
    for (int k = 0; k < 27; ++k) {
        if (k + 1 < 27)
            conv_stage(smb, (k + 1) & 1, k + 1, AF, idxs, packc,
                       (k & 1) ? mb0 : mb1, tid);
        if (k & 1) { mbar_wait(mb1, ph1); ph1 ^= 1; }
        else       { mbar_wait(mb0, ph0); ph0 ^= 1; }
        mma_compute_h(sm + (k & 1) * CBUF, acc, wid, lane);
        __syncthreads();
    }
    epilogue_stats(acc, Co, statsg, csum, csq, row0, n, wid, lane, tid);
}

// per-scale (gridDim.y=3): P = exp((relu(bn(P)) - mean[cl]) @ W_w); den += P
__global__ __launch_bounds__(NTHR)
void k_mma_submean_exp(float* __restrict__ bufs, const float* __restrict__ statsb,
                       const float* __restrict__ glw, const float* __restrict__ blw,
                       const unsigned* __restrict__ pack, const float* __restrict__ mean,
                       const float* __restrict__ cnt,
                       const int* __restrict__ cl0, const int* __restrict__ cl1,
                       const int* __restrict__ cl2, float* __restrict__ den, int n) {
    extern __shared__ unsigned buf[];
    __shared__ float coef[128];
    __shared__ int   cls[TM];
    __shared__ float cinv[TM];
    int s = blockIdx.y;
    const int* cl = (s == 0) ? cl0 : ((s == 1) ? cl1 : cl2);
    int soff = c_soff[s];
    float* P = bufs + (size_t)s * ROWSZ;
    int tid = threadIdx.x, wid = tid >> 5, lane = tid & 31;
    int row0 = blockIdx.x * TM;
    load_coef(coef, statsb + s * 128, glw + s * 64, blw + s * 64, n, tid);
    if (tid < 128) {
        int r = row0 + tid;
        int c = (r < n) ? cl[r] : 0;
        cls[tid] = c;
        cinv[tid] = 1.f / fmaxf(cnt[soff + c], 1.f);
    }
    stage_B(buf + OFF_B, pack + (size_t)(3 + s) * 4608, tid);
    cp_commit();
    __syncthreads();
#pragma unroll
    for (int i = 0; i < 8; ++i) {
        int idx = tid + i * NTHR;
        int r = idx >> 4, c4 = idx & 15;
        int grow = row0 + r;
        float4 vv = make_float4(0.f, 0.f, 0.f, 0.f);
        if (grow < n) {
            vv = *(const float4*)(P + (size_t)grow * 64 + c4 * 4);
            float4 ms = *(const float4*)(mean + (size_t)(soff + cls[r]) * 64 + c4 * 4);
            float ci = cinv[r];
            int ch = c4 * 4;
            vv.x = fmaxf(vv.x * coef[ch + 0] + coef[64 + ch + 0], 0.f) - ms.x * ci;
            vv.y = fmaxf(vv.y * coef[ch + 1] + coef[64 + ch + 1], 0.f) - ms.y * ci;
            vv.z = fmaxf(vv.z * coef[ch + 2] + coef[64 + ch + 2], 0.f) - ms.z * ci;
            vv.w = fmaxf(vv.w * coef[ch + 3] + coef[64 + ch + 3], 0.f) - ms.w * ci;
        }
        a_store(buf, r, c4, vv);
    }
    cp_wait<0>();
    __syncthreads();
    float acc[8][4] = {};
    mma_compute(buf, buf + OFF_B, acc, wid, lane);
    int g = lane >> 2, c = lane & 3;
    int lr0 = wid * 16 + g, lr1 = lr0 + 8;
    int r0 = row0 + lr0, r1 = row0 + lr1;
    float* d0 = den + (size_t)(soff + cls[lr0]) * 64;
    float* d1 = den + (size_t)(soff + cls[lr1]) * 64;
#pragma unroll
    for (int nt = 0; nt < 8; ++nt) {
        int ch = nt * 8 + 2 * c;
        if (r0 < n) {
            float e0 = __expf(acc[nt][0]), e1 = __expf(acc[nt][1]);
            *(float2*)(P + (size_t)r0 * 64 + ch) = make_float2(e0, e1);
            red_add_v2(d0 + ch, e0, e1);
        }
        if (r1 < n) {
            float e2 = __expf(acc[nt][2]), e3 = __expf(acc[nt][3]);
            *(float2*)(P + (size_t)r1 * 64 + ch) = make_float2(e2, e3);
            red_add_v2(d1 + ch, e2, e3);
        }
    }
}

// fuse GEMM: Co = relu(bn(Q))@Wf[0:64] + mix@Wf[64:128] + stats
__global__ __launch_bounds__(NTHR)
void k_mma_gemm2(const float* __restrict__ Q, const float* __restrict__ stats,
                 const float* __restrict__ gg, const float* __restrict__ bb,
                 const unsigned* __restrict__ tiles, const float* __restrict__ segS,
                 const int* __restrict__ cl0, const int* __restrict__ cl1,
                 const int* __restrict__ cl2, const float* __restrict__ adp,
                 float* __restrict__ Co, float* __restrict__ statsg, int n) {
    extern __shared__ unsigned buf[];
    __shared__ float csum[64], csq[64];
    __shared__ float coef[128];
    __shared__ int   cls[3][TM];
    __shared__ float sad[3][TM];
    int tid = threadIdx.x, wid = tid >> 5, lane = tid & 31;
    int row0 = blockIdx.x * TM;
    if (tid < 64) { csum[tid] = 0.f; csq[tid] = 0.f; }
    load_coef(coef, stats, gg, bb, n, tid);
    if (tid < 128) {
        int r = row0 + tid;
        bool v = r < n;
        cls[0][tid] = v ? cl0[r] : 0;
        cls[1][tid] = v ? cl1[r] : 0;
        cls[2][tid] = v ? cl2[r] : 0;
        sad[0][tid] = v ? adp[(size_t)r * 3 + 0] : 0.f;
        sad[1][tid] = v ? adp[(size_t)r * 3 + 1] : 0.f;
        sad[2][tid] = v ? adp[(size_t)r * 3 + 2] : 0.f;
    }
    __syncthreads();
    float acc[8][4] = {};
#pragma unroll
    for (int p = 0; p < 2; ++p) {
        stage_B(buf + OFF_B, tiles + (size_t)p * 4608, tid);
        cp_commit();
#pragma unroll
        for (int i = 0; i < 8; ++i) {
            int idx = tid + i * NTHR;
            int r = idx >> 4, c4 = idx & 15;
            int grow = row0 + r;
            float4 vv = make_float4(0.f, 0.f, 0.f, 0.f);
            if (grow < n) {
                if (p == 0) {
                    vv = *(const float4*)(Q + (size_t)grow * 64 + c4 * 4);
                    int ch = c4 * 4;
                    vv.x = fmaxf(vv.x * coef[ch + 0] + coef[64 + ch + 0], 0.f);
                    vv.y = fmaxf(vv.y * coef[ch + 1] + coef[64 + ch + 1], 0.f);
                    vv.z = fmaxf(vv.z * coef[ch + 2] + coef[64 + ch + 2], 0.f);
                    vv.w = fmaxf(vv.w * coef[ch + 3] + coef[64 + ch + 3], 0.f);
                } else {
                    float w0 = sad[0][r], w1 = sad[1][r], w2 = sad[2][r];
                    float4 a = *(const float4*)(segS + (size_t)(0 + cls[0][r]) * 64 + c4 * 4);
                    float4 bv = *(const float4*)(segS + (size_t)(4096 + cls[1][r]) * 64 + c4 * 4);
                    float4 cc = *(const float4*)(segS + (size_t)(36864 + cls[2][r]) * 64 + c4 * 4);
                    vv.x = w0 * a.x + w1 * bv.x + w2 * cc.x;
                    vv.y = w0 * a.y + w1 * bv.y + w2 * cc.y;
                    vv.z = w0 * a.z + w1 * bv.z + w2 * cc.z;
                    vv.w = w0 * a.w + w1 * bv.w + w2 * cc.w;
                }
            }
            a_store(buf, r, c4, vv);
        }
        cp_wait<0>();
        __syncthreads();
        mma_compute(buf, buf + OFF_B, acc, wid, lane);
        __syncthreads();
    }
    epilogue_stats(acc, Co, statsg, csum, csq, row0, n, wid, lane, tid);
}

// ---------------- small / elementwise kernels ----------------
__global__ void k_adp(const float* __restrict__ feat, const float* __restrict__ Wa,
                      float* __restrict__ adp, int n) {
    __shared__ float w[192];
    if (threadIdx.x < 192) w[threadIdx.x] = Wa[threadIdx.x];
    __syncthreads();
    int row = blockIdx.x * blockDim.x + threadIdx.x;
    if (row >= n) return;
    float s0 = 0.f, s1 = 0.f, s2 = 0.f;
    const float* f = feat + (size_t)row * 64;
#pragma unroll 16
    for (int c = 0; c < 64; ++c) {
        float v = f[c];
        s0 += v * w[c * 3 + 0];
        s1 += v * w[c * 3 + 1];
        s2 += v * w[c * 3 + 2];
    }
    float m = fmaxf(s0, fmaxf(s1, s2));
    float e0 = __expf(s0 - m), e1 = __expf(s1 - m), e2 = __expf(s2 - m);
    float inv = 1.f / (e0 + e1 + e2);
    adp[(size_t)row * 3 + 0] = e0 * inv;
    adp[(size_t)row * 3 + 1] = e1 * inv;
    adp[(size_t)row * 3 + 2] = e2 * inv;
}

// per-scale (gridDim.y=3): mean-arena += relu(bn(P)), cnt++
__global__ void k_segsum3(const float* __restrict__ bufs, const float* __restrict__ statsb,
                          const float* __restrict__ glw, const float* __restrict__ blw,
                          const int* __restrict__ cl0, const int* __restrict__ cl1,
                          const int* __restrict__ cl2, float* __restrict__ mean,
                          float* __restrict__ cnt, int n) {
    __shared__ float sc[128];
    int s = blockIdx.y;
    load_coef(sc, statsb + s * 128, glw + s * 64, blw + s * 64, n, threadIdx.x);
    __syncthreads();
    int row = blockIdx.x * blockDim.x + threadIdx.x;
    if (row >= n) return;
    const int* cl = (s == 0) ? cl0 : ((s == 1) ? cl1 : cl2);
    int c = c_soff[s] + cl[row];
    const float* p = bufs + (size_t)s * ROWSZ + (size_t)row * 64;
    float* sg = mean + (size_t)c * 64;
#pragma unroll
    for (int c4 = 0; c4 < 16; ++c4) {
        float4 x = *(const float4*)(p + c4 * 4);
        x.x = fmaxf(x.x * sc[c4 * 4 + 0] + sc[64 + c4 * 4 + 0], 0.f);
        x.y = fmaxf(x.y * sc[c4 * 4 + 1] + sc[64 + c4 * 4 + 1], 0.f);
        x.z = fmaxf(x.z * sc[c4 * 4 + 2] + sc[64 + c4 * 4 + 2], 0.f);
        x.w = fmaxf(x.w * sc[c4 * 4 + 3] + sc[64 + c4 * 4 + 3], 0.f);
        red_add_v4(sg + c4 * 4, x);
    }
    atomicAdd(&cnt[c], 1.f);
}

// per-scale (gridDim.y=3): segS += relu(bn(Q)) * expP / (den[cl]+1e-6)
__global__ void k_pw3(const float* __restrict__ bufs, const float* __restrict__ statsb,
                      const float* __restrict__ gproj, const float* __restrict__ bproj,
                      const float* __restrict__ den,
                      const int* __restrict__ cl0, const int* __restrict__ cl1,
                      const int* __restrict__ cl2, float* __restrict__ segS, int n) {
    __shared__ float sc[128];
    int s = blockIdx.y;
    load_coef(sc, statsb + (3 + s) * 128, gproj + s * 64, bproj + s * 64, n, threadIdx.x);
    __syncthreads();
    int row = blockIdx.x * blockDim.x + threadIdx.x;
    if (row >= n) return;
    const int* cl = (s == 0) ? cl0 : ((s == 1) ? cl1 : cl2);
    int c = c_soff[s] + cl[row];
    const float* q = bufs + (size_t)(3 + s) * ROWSZ + (size_t)row * 64;
    const float* p = bufs + (size_t)s * ROWSZ + (size_t)row * 64;
    const float* d = den + (size_t)c * 64;
    float* sg = segS + (size_t)c * 64;
#pragma unroll
    for (int c4 = 0; c4 < 16; ++c4) {
        float4 qv = *(const float4*)(q + c4 * 4);
        float4 pv = *(const float4*)(p + c4 * 4);
        float4 dv = *(const float4*)(d + c4 * 4);
        float4 o;
        o.x = fmaxf(qv.x * sc[c4 * 4 + 0] + sc[64 + c4 * 4 + 0], 0.f) * pv.x / (dv.x + 1e-6f);
        o.y = fmaxf(qv.y * sc[c4 * 4 + 1] + sc[64 + c4 * 4 + 1], 0.f) * pv.y / (dv.y + 1e-6f);
        o.z = fmaxf(qv.z * sc[c4 * 4 + 2] + sc[64 + c4 * 4 + 2], 0.f) * pv.z / (dv.z + 1e-6f);
        o.w = fmaxf(qv.w * sc[c4 * 4 + 3] + sc[64 + c4 * 4 + 3], 0.f) * pv.w / (dv.w + 1e-6f);
        red_add_v4(sg + c4 * 4, o);
    }
}

// out = relu(bn(H) + F)
__global__ void k_final(const float* __restrict__ H, const float* __restrict__ stats,
                        const float* __restrict__ g, const float* __restrict__ b,
                        const float* __restrict__ F, float* __restrict__ out,
                        int n, int total4) {
    __shared__ float sc[128];
    load_coef(sc, stats, g, b, n, threadIdx.x);
    __syncthreads();
    int i = blockIdx.x * 256 + threadIdx.x;
    if (i >= total4) return;
    int ch = (i & 15) * 4;
    float4 x = ((const float4*)H)[i];
    float4 r = ((const float4*)F)[i];
    x.x = fmaxf(x.x * sc[ch + 0] + sc[64 + ch + 0] + r.x, 0.f);
    x.y = fmaxf(x.y * sc[ch + 1] + sc[64 + ch + 1] + r.y, 0.f);
    x.z = fmaxf(x.z * sc[ch + 2] + sc[64 + ch + 2] + r.z, 0.f);
    x.w = fmaxf(x.w * sc[ch + 3] + sc[64 + ch + 3] + r.w, 0.f);
    ((float4*)out)[i] = x;
}

// ---------------------------------------------------------------------------
extern "C" void kernel_launch(void* const* d_in, const int* in_sizes, int n_in,
                              void* d_out, int out_size) {
    const float* feat   = (const float*)d_in[0];
    const int*   cl0    = (const int*)d_in[1];
    const int*   cl1    = (const int*)d_in[2];
    const int*   cl2    = (const int*)d_in[3];
    const int*   nbr    = (const int*)d_in[4];
    const float* W_lw   = (const float*)d_in[5];
    const float* g_lw   = (const float*)d_in[6];
    const float* b_lw   = (const float*)d_in[7];
    const float* W_w    = (const float*)d_in[8];
    const float* W_proj = (const float*)d_in[9];
    const float* g_proj = (const float*)d_in[10];
    const float* b_proj = (const float*)d_in[11];
    const float* W_adp  = (const float*)d_in[12];
    const float* W_fuse = (const float*)d_in[13];
    const float* g_fuse = (const float*)d_in[14];
    const float* b_fuse = (const float*)d_in[15];
    const float* W_c1   = (const float*)d_in[16];
    const float* g_c1   = (const float*)d_in[17];
    const float* b_c1   = (const float*)d_in[18];
    const float* W_c2   = (const float*)d_in[19];
    const float* g_c2   = (const float*)d_in[20];
    const float* b_c2   = (const float*)d_in[21];
    float* out = (float*)d_out;
    int n = in_sizes[1];

    float *pBufs, *pF, *pMean, *pDen, *pSegS, *pCnt, *pStats, *pAdp;
    unsigned *pPack, *pPackC, *pFph;
    cudaGetSymbolAddress((void**)&pBufs, g_bufs);
    cudaGetSymbolAddress((void**)&pF, g_bufF);
    cudaGetSymbolAddress((void**)&pFph, g_fph);
    cudaGetSymbolAddress((void**)&pMean, g_segMean);
    cudaGetSymbolAddress((void**)&pDen, g_segDen);
    cudaGetSymbolAddress((void**)&pSegS, g_segS);
    cudaGetSymbolAddress((void**)&pCnt, g_cnt);
    cudaGetSymbolAddress((void**)&pStats, g_statsA);
    cudaGetSymbolAddress((void**)&pAdp, g_adpv);
    cudaGetSymbolAddress((void**)&pPack, g_wpack);
    cudaGetSymbolAddress((void**)&pPackC, g_wpackc);

    const int GB = (n + TM - 1) / TM;
    const int EB = (n + 255) / 256;
    const int total4 = n * 16;
    const int SB = (total4 + 255) / 256;
    const int SM_G7 = 18432 * 4;                    // 73728B
    const int SM_1  = 13824 * 4;                    // 55296B
    const int SM_CV = (2 * CBUF + TM * 27) * 4;     // 69120B

    cudaFuncSetAttribute(k_mma_gemm7, cudaFuncAttributeMaxDynamicSharedMemorySize, SM_G7);
    cudaFuncSetAttribute(k_mma_submean_exp, cudaFuncAttributeMaxDynamicSharedMemorySize, SM_1);
    cudaFuncSetAttribute(k_mma_gemm2, cudaFuncAttributeMaxDynamicSharedMemorySize, SM_1);
    cudaFuncSetAttribute(k_mma_convh, cudaFuncAttributeMaxDynamicSharedMemorySize, SM_CV);

    const uint4* AF = (const uint4*)pFph;
    float* Qb3 = pBufs + 6 * ROWSZ;

    k_prepack<<<12, 256>>>(W_lw, W_w, W_proj, W_fuse, pPack);
    k_prepackc<<<54, 256>>>(W_c1, W_c2, pPackC);
    k_adp<<<EB, 256>>>(feat, W_adp, pAdp, n);

    // 7 feat-GEMMs (feat converted in staging)
    cudaMemsetAsync(pStats, 0, 7 * 128 * sizeof(float));
    k_mma_gemm7<<<GB, NTHR, SM_G7>>>(feat, pPack, pBufs, pStats, n);

    // cluster attention, all 3 scales batched
    cudaMemsetAsync(pMean, 0, (size_t)SEGTOT * 64 * sizeof(float));
    cudaMemsetAsync(pCnt, 0, (size_t)SEGTOT * sizeof(float));
    k_segsum3<<<dim3(EB, 3), 256>>>(pBufs, pStats, g_lw, b_lw, cl0, cl1, cl2,
                                    pMean, pCnt, n);
    cudaMemsetAsync(pDen, 0, (size_t)SEGTOT * 64 * sizeof(float));
    k_mma_submean_exp<<<dim3(GB, 3), NTHR, SM_1>>>(pBufs, pStats, g_lw, b_lw, pPack,
                                                   pMean, pCnt, cl0, cl1, cl2, pDen, n);
    cudaMemsetAsync(pSegS, 0, (size_t)SEGTOT * 64 * sizeof(float));
    k_pw3<<<dim3(EB, 3), 256>>>(pBufs, pStats, g_proj, b_proj, pDen,
                                cl0, cl1, cl2, pSegS, n);

    // fused = relu(bn([relu(bn(Q3)), mix] @ W_fuse)) + feat
    cudaMemsetAsync(pStats + 7 * 128, 0, 128 * sizeof(float));
    k_mma_gemm2<<<GB, NTHR, SM_1>>>(Qb3, pStats + 6 * 128, g_proj + 192, b_proj + 192,
                                    pPack + (size_t)10 * 4608, pSegS,
                                    cl0, cl1, cl2, pAdp, pF, pStats + 7 * 128, n);
    k_bnrelu_add_split<<<SB, 256>>>(pF, pStats + 7 * 128, g_fuse, b_fuse, feat,
                                    pFph, n, total4);
    // conv1 -> split ; conv2 -> final
    cudaMemsetAsync(pStats + 8 * 128, 0, 128 * sizeof(float));
    k_mma_convh<<<GB, NTHR, SM_CV>>>(AF, nbr, pPackC, pBufs, pStats + 8 * 128, n);
    k_bnrelu_split<<<SB, 256>>>(pBufs, pStats + 8 * 128, g_c1, b_c1, pFph, n, total4);
    cudaMemsetAsync(pStats + 9 * 128, 0, 128 * sizeof(float));
    k_mma_convh<<<GB, NTHR, SM_CV>>>(AF, nbr, pPackC + (size_t)27 * 2304,
                                     pBufs + ROWSZ, pStats + 9 * 128, n);
    k_final<<<SB, 256>>>(pBufs + ROWSZ, pStats + 9 * 128, g_c2, b_c2, pF, out, n, total4);
}

// round 11
// speedup vs baseline: 2.0311x; 1.0419x over previous
#include <cuda_runtime.h>
#include <cuda_bf16.h>
#include <cuda_fp16.h>

// ---------------------------------------------------------------------------
// OACNNs block, round 11.
//  - epilogue BN-stats masked for rows >= n (fixes tail-row contamination
//    introduced by bulk gathers; restores accuracy margin).
//  - gemm7: single B buffer (55.3KB smem) + launch_bounds(256,4) -> 4 CTAs/SM;
//    k_adp fused into gemm7 A-staging (one less full feat read pass).
//  - conv path unchanged from round 10 (bulk gathers, measured best).
// ---------------------------------------------------------------------------

#define NPTS_MAX 500000
#define SEGTOT   167936     // 4096 + 32768 + 131072
#define TM   128
#define NTHR 256
#define AS   36             // uints per row (144B stride, LDSM conflict-free)
#define OFF_AL 4608        // TM*AS   (A lo plane)
#define OFF_B  9216        // 2*TM*AS (B region within a bf16 tile buffer)
#define CBUF   6912        // uints per fp16 conv buffer (A 4608 + B 2304)
#define COFF_B 4608
#define ROWSZ  ((size_t)NPTS_MAX * 64)
#define CONV_TX 25600u     // 128 rows * 128B + 9216B B tile

// scratch (device globals: allocation-free rule)
__device__ float          g_bufs[7 * ROWSZ];     // P0,P1,P2,Q0,Q1,Q2,Q3
__device__ float          g_bufF[ROWSZ];
__device__ unsigned       g_fph[NPTS_MAX * 32];  // fp16 plane of conv input
__device__ float          g_segMean[SEGTOT * 64];
__device__ float          g_segDen [SEGTOT * 64];
__device__ float          g_segS   [SEGTOT * 64];
__device__ float          g_cnt    [SEGTOT];
__device__ float          g_adpv[NPTS_MAX * 3];
__device__ float          g_statsA[10 * 128];    // 0-6 gemm7, 7 fuse, 8 c1, 9 c2
__device__ unsigned       g_wpack[12 * 4608];    // bf16 hi/lo tiles (lw,w,proj,fuse)
__device__ unsigned       g_wpackc[54 * 2304];   // fp16 conv tiles

__device__ __constant__ int c_soff[3] = {0, 4096, 36864};

// ---------------- helpers ----------------
__device__ __forceinline__ void red_add_v4(float* addr, float4 v) {
    asm volatile("red.global.add.v4.f32 [%0], {%1,%2,%3,%4};"
                 :: "l"(addr), "f"(v.x), "f"(v.y), "f"(v.z), "f"(v.w)
                 : "memory");
}
__device__ __forceinline__ void red_add_v2(float* addr, float x, float y) {
    asm volatile("red.global.add.v2.f32 [%0], {%1,%2};"
                 :: "l"(addr), "f"(x), "f"(y) : "memory");
}
__device__ __forceinline__ void cp16(unsigned* dst, const void* src, bool v) {
    unsigned d = (unsigned)__cvta_generic_to_shared(dst);
    int sz = v ? 16 : 0;
    asm volatile("cp.async.cg.shared.global [%0], [%1], 16, %2;"
                 :: "r"(d), "l"(src), "r"(sz) : "memory");
}
__device__ __forceinline__ void cp_commit() {
    asm volatile("cp.async.commit_group;" ::: "memory");
}
template <int N> __device__ __forceinline__ void cp_wait() {
    asm volatile("cp.async.wait_group %0;" :: "n"(N) : "memory");
}
__device__ __forceinline__ void cpbulk(unsigned dst, const void* src,
                                       unsigned bytes, unsigned mba) {
    asm volatile(
        "cp.async.bulk.shared::cluster.global.mbarrier::complete_tx::bytes "
        "[%0], [%1], %2, [%3];"
        :: "r"(dst), "l"(src), "r"(bytes), "r"(mba) : "memory");
}
__device__ __forceinline__ void mbar_init(unsigned mba, unsigned cnt) {
    asm volatile("mbarrier.init.shared.b64 [%0], %1;" :: "r"(mba), "r"(cnt) : "memory");
}
__device__ __forceinline__ void mbar_expect(unsigned mba, unsigned bytes) {
    asm volatile("mbarrier.arrive.expect_tx.shared.b64 _, [%0], %1;"
                 :: "r"(mba), "r"(bytes) : "memory");
}
__device__ __forceinline__ void mbar_wait(unsigned mba, int phase) {
    asm volatile(
        "{\n\t"
        ".reg .pred P;\n\t"
        "LAB_%=:\n\t"
        "mbarrier.try_wait.parity.acquire.cta.shared::cta.b64 P, [%0], %1;\n\t"
        "@!P bra LAB_%=;\n\t"
        "}"
        :: "r"(mba), "r"(phase) : "memory");
}

__device__ __forceinline__ void split2(float x, float y, unsigned& h, unsigned& l) {
    __nv_bfloat16 hx = __float2bfloat16(x), hy = __float2bfloat16(y);
    float lx = x - __bfloat162float(hx);
    float ly = y - __bfloat162float(hy);
    __nv_bfloat162 hp; hp.x = hx; hp.y = hy;
    __nv_bfloat162 lp; lp.x = __float2bfloat16(lx); lp.y = __float2bfloat16(ly);
    h = *reinterpret_cast<unsigned*>(&hp);
    l = *reinterpret_cast<unsigned*>(&lp);
}
__device__ __forceinline__ unsigned packh2(float x, float y) {
    __half2 h; h.x = __float2half(x); h.y = __float2half(y);
    return *reinterpret_cast<unsigned*>(&h);
}

__device__ __forceinline__ void mma16816(float* d, unsigned a0, unsigned a1,
                                         unsigned a2, unsigned a3,
                                         unsigned b0, unsigned b1) {
    asm volatile(
        "mma.sync.aligned.m16n8k16.row.col.f32.bf16.bf16.f32 "
        "{%0,%1,%2,%3}, {%4,%5,%6,%7}, {%8,%9}, {%0,%1,%2,%3};"
        : "+f"(d[0]), "+f"(d[1]), "+f"(d[2]), "+f"(d[3])
        : "r"(a0), "r"(a1), "r"(a2), "r"(a3), "r"(b0), "r"(b1));
}
__device__ __forceinline__ void mma16816h(float* d, unsigned a0, unsigned a1,
                                          unsigned a2, unsigned a3,
                                          unsigned b0, unsigned b1) {
    asm volatile(
        "mma.sync.aligned.m16n8k16.row.col.f32.f16.f16.f32 "
        "{%0,%1,%2,%3}, {%4,%5,%6,%7}, {%8,%9}, {%0,%1,%2,%3};"
        : "+f"(d[0]), "+f"(d[1]), "+f"(d[2]), "+f"(d[3])
        : "r"(a0), "r"(a1), "r"(a2), "r"(a3), "r"(b0), "r"(b1));
}
__device__ __forceinline__ void ldsm4(unsigned& r0, unsigned& r1, unsigned& r2,
                                      unsigned& r3, const unsigned* p) {
    unsigned a = (unsigned)__cvta_generic_to_shared(p);
    asm volatile("ldmatrix.sync.aligned.m8n8.x4.shared.b16 {%0,%1,%2,%3}, [%4];"
                 : "=r"(r0), "=r"(r1), "=r"(r2), "=r"(r3) : "r"(a));
}

__device__ __forceinline__ void a_store(unsigned* buf, int r, int c4, float4 v) {
    unsigned h0, l0, h1, l1;
    split2(v.x, v.y, h0, l0);
    split2(v.z, v.w, h1, l1);
    int w = r * AS + c4 * 2;
    *reinterpret_cast<uint2*>(buf + w)          = make_uint2(h0, h1);
    *reinterpret_cast<uint2*>(buf + OFF_AL + w) = make_uint2(l0, l1);
}

__device__ __forceinline__ void stage_B(unsigned* Bdst, const unsigned* tile, int tid) {
    const uint4* s = reinterpret_cast<const uint4*>(tile);
    for (int i = tid; i < 1152; i += NTHR) cp16(Bdst + i * 4, s + i, true);
}

// 128x64x64 (x3 split) bf16 mma sweep via ldmatrix
__device__ __forceinline__ void mma_compute(const unsigned* Areg, const unsigned* Breg,
                                            float acc[8][4], int wid, int lane) {
    const unsigned* Ah = Areg;
    const unsigned* Al = Areg + OFF_AL;
    const unsigned* Bh = Breg;
    const unsigned* Bl = Breg + 2304;
    int alr = lane & 15;
    int acol = (lane >> 4) * 4;
    const unsigned* aph = Ah + (wid * 16 + alr) * AS + acol;
    const unsigned* apl = Al + (wid * 16 + alr) * AS + acol;
    int brow = lane & 7;
    const unsigned* bp = ((lane & 16) ? Bl : Bh) + brow * AS + ((lane & 8) ? 4 : 0);
#pragma unroll
    for (int kk = 0; kk < 4; ++kk) {
        int ko = kk * 8;
        unsigned a0h, a1h, a2h, a3h, a0l, a1l, a2l, a3l;
        ldsm4(a0h, a1h, a2h, a3h, aph + ko);
        ldsm4(a0l, a1l, a2l, a3l, apl + ko);
#pragma unroll
        for (int nt = 0; nt < 8; ++nt) {
            unsigned b0h, b1h, b0l, b1l;
            ldsm4(b0h, b1h, b0l, b1l, bp + nt * 8 * AS + ko);
            mma16816(acc[nt], a0h, a1h, a2h, a3h, b0h, b1h);
            mma16816(acc[nt], a0l, a1l, a2l, a3l, b0h, b1h);
            mma16816(acc[nt], a0h, a1h, a2h, a3h, b0l, b1l);
        }
    }
}

// 128x64x64 fp16 single-plane mma sweep (conv path)
__device__ __forceinline__ void mma_compute_h(const unsigned* buf, float acc[8][4],
                                              int wid, int lane) {
    const unsigned* Ap = buf;
    const unsigned* Bp = buf + COFF_B;
    const unsigned* aph = Ap + (wid * 16 + (lane & 15)) * AS + (lane >> 4) * 4;
    int brow = lane & 7;
    int koff = ((lane >> 3) & 1) * 4;
    int ntoff = ((lane >> 4) & 1) * 8 * AS;
#pragma unroll
    for (int kk = 0; kk < 4; ++kk) {
        int ko = kk * 8;
        unsigned a0, a1, a2, a3;
        ldsm4(a0, a1, a2, a3, aph + ko);
#pragma unroll
        for (int np = 0; np < 4; ++np) {
            unsigned b0, b1, b2, b3;
            ldsm4(b0, b1, b2, b3, Bp + (np * 16 + brow) * AS + ntoff + ko + koff);
            mma16816h(acc[2 * np], a0, a1, a2, a3, b0, b1);
            mma16816h(acc[2 * np + 1], a0, a1, a2, a3, b2, b3);
        }
    }
}

// store + shuffle-reduced stats; rows >= n masked out of stats
__device__ __forceinline__ void epilogue_stats(float acc[8][4], float* __restrict__ Co,
                                               float* __restrict__ statsg,
                                               float* csum, float* csq,
                                               int row0, int n, int wid, int lane, int tid) {
    int g = lane >> 2, c = lane & 3;
    int r0 = row0 + wid * 16 + g, r1 = r0 + 8;
    bool v0 = r0 < n, v1 = r1 < n;
#pragma unroll
    for (int nt = 0; nt < 8; ++nt) {
        int ch = nt * 8 + 2 * c;
        float a0 = v0 ? acc[nt][0] : 0.f;
        float a1 = v0 ? acc[nt][1] : 0.f;
        float a2 = v1 ? acc[nt][2] : 0.f;
        float a3 = v1 ? acc[nt][3] : 0.f;
        if (v0) *(float2*)(Co + (size_t)r0 * 64 + ch) = make_float2(a0, a1);
        if (v1) *(float2*)(Co + (size_t)r1 * 64 + ch) = make_float2(a2, a3);
        float s0 = a0 + a2;
        float s1 = a1 + a3;
        float q0 = a0 * a0 + a2 * a2;
        float q1 = a1 * a1 + a3 * a3;
#pragma unroll
        for (int d = 4; d < 32; d <<= 1) {
            s0 += __shfl_xor_sync(0xffffffffu, s0, d);
            s1 += __shfl_xor_sync(0xffffffffu, s1, d);
            q0 += __shfl_xor_sync(0xffffffffu, q0, d);
            q1 += __shfl_xor_sync(0xffffffffu, q1, d);
        }
        if (lane < 4) {
            atomicAdd(&csum[ch], s0);
            atomicAdd(&csum[ch + 1], s1);
            atomicAdd(&csq[ch], q0);
            atomicAdd(&csq[ch + 1], q1);
        }
    }
    __syncthreads();
    if (tid < 64)       atomicAdd(&statsg[tid], csum[tid]);
    else if (tid < 128) atomicAdd(&statsg[tid], csq[tid - 64]);
}

__device__ __forceinline__ void load_coef(float* sc, const float* __restrict__ stats,
                                          const float* __restrict__ g,
                                          const float* __restrict__ b, int n, int tid) {
    if (tid < 64) {
        float inv_n = 1.f / (float)n;
        float mean = stats[tid] * inv_n;
        float var = stats[64 + tid] * inv_n - mean * mean;
        float a = g[tid] * rsqrtf(var + 1e-3f);
        sc[tid] = a;
        sc[64 + tid] = b[tid] - mean * a;
    }
}

// ---------------- prepack ----------------
__global__ void k_prepack(const float* __restrict__ Wlw, const float* __restrict__ Ww,
                          const float* __restrict__ Wproj, const float* __restrict__ Wfuse,
                          unsigned* __restrict__ pack) {
    int t = blockIdx.x;     // 0..11
    const float* src;
    if (t < 3)       src = Wlw  + t * 4096;
    else if (t < 6)  src = Ww   + (t - 3) * 4096;
    else if (t < 10) src = Wproj+ (t - 6) * 4096;
    else             src = Wfuse+ (t - 10) * 4096;
    unsigned* ph = pack + (size_t)t * 4608;
    unsigned* pl = ph + 2304;
    for (int idx = threadIdx.x; idx < 2048; idx += 256) {
        int cout = idx & 63, p = idx >> 6;
        unsigned h, l;
        split2(src[2 * p * 64 + cout], src[(2 * p + 1) * 64 + cout], h, l);
        ph[cout * AS + p] = h;
        pl[cout * AS + p] = l;
    }
}
__global__ void k_prepackc(const float* __restrict__ Wc1, const float* __restrict__ Wc2,
                           unsigned* __restrict__ packc) {
    int t = blockIdx.x;     // 0..53
    const float* src = (t < 27) ? Wc1 + t * 4096 : Wc2 + (t - 27) * 4096;
    unsigned* ph = packc + (size_t)t * 2304;
    for (int idx = threadIdx.x; idx < 2048; idx += 256) {
        int cout = idx & 63, p = idx >> 6;
        ph[cout * AS + p] = packh2(src[2 * p * 64 + cout], src[(2 * p + 1) * 64 + cout]);
    }
}

// F = relu(bn(rawF)) + feat; emit fp16 plane of F
__global__ void k_bnrelu_add_split(float* __restrict__ F, const float* __restrict__ stats,
                                   const float* __restrict__ g, const float* __restrict__ b,
                                   const float* __restrict__ feat,
                                   unsigned* __restrict__ Hp, int n, int total4) {
    __shared__ float sc[128];
    load_coef(sc, stats, g, b, n, threadIdx.x);
    __syncthreads();
    int i = blockIdx.x * 256 + threadIdx.x;
    if (i >= total4) return;
    int ch = (i & 15) * 4;
    float4 x = ((const float4*)F)[i];
    float4 r = ((const float4*)feat)[i];
    x.x = fmaxf(x.x * sc[ch + 0] + sc[64 + ch + 0], 0.f) + r.x;
    x.y = fmaxf(x.y * sc[ch + 1] + sc[64 + ch + 1], 0.f) + r.y;
    x.z = fmaxf(x.z * sc[ch + 2] + sc[64 + ch + 2], 0.f) + r.z;
    x.w = fmaxf(x.w * sc[ch + 3] + sc[64 + ch + 3], 0.f) + r.w;
    ((float4*)F)[i] = x;
    ((uint2*)Hp)[i] = make_uint2(packh2(x.x, x.y), packh2(x.z, x.w));
}

// fp16 plane = relu(bn(P))
__global__ void k_bnrelu_split(const float* __restrict__ P, const float* __restrict__ stats,
                               const float* __restrict__ g, const float* __restrict__ b,
                               unsigned* __restrict__ Hp, int n, int total4) {
    __shared__ float sc[128];
    load_coef(sc, stats, g, b, n, threadIdx.x);
    __syncthreads();
    int i = blockIdx.x * 256 + threadIdx.x;
    if (i >= total4) return;
    int ch = (i & 15) * 4;
    float4 x = ((const float4*)P)[i];
    x.x = fmaxf(x.x * sc[ch + 0] + sc[64 + ch + 0], 0.f);
    x.y = fmaxf(x.y * sc[ch + 1] + sc[64 + ch + 1], 0.f);
    x.z = fmaxf(x.z * sc[ch + 2] + sc[64 + ch + 2], 0.f);
    x.w = fmaxf(x.w * sc[ch + 3] + sc[64 + ch + 3], 0.f);
    ((uint2*)Hp)[i] = make_uint2(packh2(x.x, x.y), packh2(x.z, x.w));
}

// ---------------- tensor-core kernels ----------------
// 7 GEMMs sharing A=feat (converted in staging) + fused adp softmax.
// Single B buffer; launch_bounds(256,4) for 4 CTAs/SM.
__global__ __launch_bounds__(NTHR, 4)
void k_mma_gemm7(const float* __restrict__ feat, const float* __restrict__ Wa,
                 const unsigned* __restrict__ pack, float* __restrict__ bufs,
                 float* __restrict__ adp, float* __restrict__ statsg, int n) {
    extern __shared__ unsigned sm[];     // A:[0,9216) B:[9216,13824)
    __shared__ float csum[64], csq[64];
    __shared__ float wa[192];
    const int tidx[7] = {0, 1, 2, 6, 7, 8, 9};
    int tid = threadIdx.x, wid = tid >> 5, lane = tid & 31;
    int row0 = blockIdx.x * TM;
    if (tid < 192) wa[tid] = Wa[tid];
    stage_B(sm + OFF_B, pack + (size_t)tidx[0] * 4608, tid);
    cp_commit();
    __syncthreads();     // wa visible
#pragma unroll
    for (int i = 0; i < 8; ++i) {   // convert feat -> hi/lo planes, fused adp
        int idx = tid + i * NTHR;
        int r = idx >> 4, c4 = idx & 15;
        int grow = row0 + r;
        float4 v = make_float4(0.f, 0.f, 0.f, 0.f);
        if (grow < n) v = *(const float4*)(feat + (size_t)grow * 64 + c4 * 4);
        a_store(sm, r, c4, v);
        int ch = c4 * 4;
        float s0 = v.x * wa[ch * 3 + 0] + v.y * wa[ch * 3 + 3] +
                   v.z * wa[ch * 3 + 6] + v.w * wa[ch * 3 + 9];
        float s1 = v.x * wa[ch * 3 + 1] + v.y * wa[ch * 3 + 4] +
                   v.z * wa[ch * 3 + 7] + v.w * wa[ch * 3 + 10];
        float s2 = v.x * wa[ch * 3 + 2] + v.y * wa[ch * 3 + 5] +
                   v.z * wa[ch * 3 + 8] + v.w * wa[ch * 3 + 11];
#pragma unroll
        for (int d = 1; d < 16; d <<= 1) {
            s0 += __shfl_xor_sync(0xffffffffu, s0, d);
            s1 += __shfl_xor_sync(0xffffffffu, s1, d);
            s2 += __shfl_xor_sync(0xffffffffu, s2, d);
        }
        if ((lane & 15) == 0 && grow < n) {
            float m = fmaxf(s0, fmaxf(s1, s2));
            float e0 = __expf(s0 - m), e1 = __expf(s1 - m), e2 = __expf(s2 - m);
            float inv = 1.f / (e0 + e1 + e2);
            adp[(size_t)grow * 3 + 0] = e0 * inv;
            adp[(size_t)grow * 3 + 1] = e1 * inv;
            adp[(size_t)grow * 3 + 2] = e2 * inv;
        }
    }
    cp_wait<0>();
    __syncthreads();
    for (int t = 0; t < 7; ++t) {
        if (tid < 64) { csum[tid] = 0.f; csq[tid] = 0.f; }
        __syncthreads();
        float acc[8][4] = {};
        mma_compute(sm, sm + OFF_B, acc, wid, lane);
        epilogue_stats(acc, bufs + (size_t)t * ROWSZ, statsg + t * 128,
                       csum, csq, row0, n, wid, lane, tid);
        if (t + 1 < 7) {    // all B reads done (epilogue's internal sync)
            stage_B(sm + OFF_B, pack + (size_t)tidx[t + 1] * 4608, tid);
            cp_commit();
            cp_wait<0>();
        }
    }
}

// stage one conv tap via cp.async.bulk into buffer `buf` tracked by mbar `mba`
__device__ __forceinline__ void conv_stage(unsigned smb, int buf, int k,
                                           const uint4* __restrict__ AF,
                                           const int* __restrict__ idxs,
                                           const unsigned* __restrict__ packc,
                                           unsigned mba, int tid) {
    unsigned bbase = smb + (unsigned)buf * (CBUF * 4);
    if (tid < 128) {
        const void* src = AF + (size_t)idxs[tid * 27 + k] * 8;
        cpbulk(bbase + tid * (AS * 4), src, 128, mba);
    } else if (tid == 128) {
        mbar_expect(mba, CONV_TX);
        cpbulk(bbase + COFF_B * 4, packc + (size_t)k * 2304, 9216, mba);
    }
}

// gather conv (fp16 single-plane), bulk-copy double-buffer pipeline; + stats
__global__ __launch_bounds__(NTHR)
void k_mma_convh(const uint4* __restrict__ AF, const int* __restrict__ nbr,
                 const unsigned* __restrict__ packc,
                 float* __restrict__ Co, float* __restrict__ statsg, int n) {
    extern __shared__ unsigned sm[];          // 2 x CBUF + idx cache
    int* idxs = (int*)(sm + 2 * CBUF);        // [TM*27]
    __shared__ float csum[64], csq[64];
    __shared__ unsigned long long mbar[2];
    int tid = threadIdx.x, wid = tid >> 5, lane = tid & 31;
    int row0 = blockIdx.x * TM;
    unsigned mb0 = (unsigned)__cvta_generic_to_shared(&mbar[0]);
    unsigned mb1 = (unsigned)__cvta_generic_to_shared(&mbar[1]);
    unsigned smb = (unsigned)__cvta_generic_to_shared(sm);
    if (tid < 64) { csum[tid] = 0.f; csq[tid] = 0.f; }
    if (tid == 0) { mbar_init(mb0, 1); mbar_init(mb1, 1); }
    {   // coalesced preload of neighbor indices
        size_t base = (size_t)row0 * 27;
        size_t lim = (size_t)n * 27;
        for (int i = tid; i < TM * 27; i += NTHR) {
            size_t pos = base + i;
            idxs[i] = (pos < lim) ? __ldg(&nbr[pos]) : 0;
        }
    }
    __syncthreads();
    int ph0 = 0, ph1 = 0;
    conv_stage(smb, 0, 0, AF, idxs, packc, mb0, tid);
    float acc[8][4] = {};
    for (int k = 0; k < 27; ++k) {
        if (k + 1 < 27)
            conv_stage(smb, (k + 1) & 1, k + 1, AF, idxs, packc,
                       (k & 1) ? mb0 : mb1, tid);
        if (k & 1) { mbar_wait(mb1, ph1); ph1 ^= 1; }
        else       { mbar_wait(mb0, ph0); ph0 ^= 1; }
        mma_compute_h(sm + (k & 1) * CBUF, acc, wid, lane);
        __syncthreads();
    }
    epilogue_stats(acc, Co, statsg, csum, csq, row0, n, wid, lane, tid);
}

// per-scale (gridDim.y=3): P = exp((relu(bn(P)) - mean[cl]) @ W_w); den += P
__global__ __launch_bounds__(NTHR)
void k_mma_submean_exp(float* __restrict__ bufs, const float* __restrict__ statsb,
                       const float* __restrict__ glw, const float* __restrict__ blw,
                       const unsigned* __restrict__ pack, const float* __restrict__ mean,
                       const float* __restrict__ cnt,
                       const int* __restrict__ cl0, const int* __restrict__ cl1,
                       const int* __restrict__ cl2, float* __restrict__ den, int n) {
    extern __shared__ unsigned buf[];
    __shared__ float coef[128];
    __shared__ int   cls[TM];
    __shared__ float cinv[TM];
    int s = blockIdx.y;
    const int* cl = (s == 0) ? cl0 : ((s == 1) ? cl1 : cl2);
    int soff = c_soff[s];
    float* P = bufs + (size_t)s * ROWSZ;
    int tid = threadIdx.x, wid = tid >> 5, lane = tid & 31;
    int row0 = blockIdx.x * TM;
    load_coef(coef, statsb + s * 128, glw + s * 64, blw + s * 64, n, tid);
    if (tid < 128) {
        int r = row0 + tid;
        int c = (r < n) ? cl[r] : 0;
        cls[tid] = c;
        cinv[tid] = 1.f / fmaxf(cnt[soff + c], 1.f);
    }
    stage_B(buf + OFF_B, pack + (size_t)(3 + s) * 4608, tid);
    cp_commit();
    __syncthreads();
#pragma unroll
    for (int i = 0; i < 8; ++i) {
        int idx = tid + i * NTHR;
        int r = idx >> 4, c4 = idx & 15;
        int grow = row0 + r;
        float4 vv = make_float4(0.f, 0.f, 0.f, 0.f);
        if (grow < n) {
            vv = *(const float4*)(P + (size_t)grow * 64 + c4 * 4);
            float4 ms = *(const float4*)(mean + (size_t)(soff + cls[r]) * 64 + c4 * 4);
            float ci = cinv[r];
            int ch = c4 * 4;
            vv.x = fmaxf(vv.x * coef[ch + 0] + coef[64 + ch + 0], 0.f) - ms.x * ci;
            vv.y = fmaxf(vv.y * coef[ch + 1] + coef[64 + ch + 1], 0.f) - ms.y * ci;
            vv.z = fmaxf(vv.z * coef[ch + 2] + coef[64 + ch + 2], 0.f) - ms.z * ci;
            vv.w = fmaxf(vv.w * coef[ch + 3] + coef[64 + ch + 3], 0.f) - ms.w * ci;
        }
        a_store(buf, r, c4, vv);
    }
    cp_wait<0>();
    __syncthreads();
    float acc[8][4] = {};
    mma_compute(buf, buf + OFF_B, acc, wid, lane);
    int g = lane >> 2, c = lane & 3;
    int lr0 = wid * 16 + g, lr1 = lr0 + 8;
    int r0 = row0 + lr0, r1 = row0 + lr1;
    float* d0 = den + (size_t)(soff + cls[lr0]) * 64;
    float* d1 = den + (size_t)(soff + cls[lr1]) * 64;
#pragma unroll
    for (int nt = 0; nt < 8; ++nt) {
        int ch = nt * 8 + 2 * c;
        if (r0 < n) {
            float e0 = __expf(acc[nt][0]), e1 = __expf(acc[nt][1]);
            *(float2*)(P + (size_t)r0 * 64 + ch) = make_float2(e0, e1);
            red_add_v2(d0 + ch, e0, e1);
        }
        if (r1 < n) {
            float e2 = __expf(acc[nt][2]), e3 = __expf(acc[nt][3]);
            *(float2*)(P + (size_t)r1 * 64 + ch) = make_float2(e2, e3);
            red_add_v2(d1 + ch, e2, e3);
        }
    }
}

// fuse GEMM: Co = relu(bn(Q))@Wf[0:64] + mix@Wf[64:128] + stats
__global__ __launch_bounds__(NTHR)
void k_mma_gemm2(const float* __restrict__ Q, const float* __restrict__ stats,
                 const float* __restrict__ gg, const float* __restrict__ bb,
                 const unsigned* __restrict__ tiles, const float* __restrict__ segS,
                 const int* __restrict__ cl0, const int* __restrict__ cl1,
                 const int* __restrict__ cl2, const float* __restrict__ adp,
                 float* __restrict__ Co, float* __restrict__ statsg, int n) {
    extern __shared__ unsigned buf[];
    __shared__ float csum[64], csq[64];
    __shared__ float coef[128];
    __shared__ int   cls[3][TM];
    __shared__ float sad[3][TM];
    int tid = threadIdx.x, wid = tid >> 5, lane = tid & 31;
    int row0 = blockIdx.x * TM;
    if (tid < 64) { csum[tid] = 0.f; csq[tid] = 0.f; }
    load_coef(coef, stats, gg, bb, n, tid);
    if (tid < 128) {
        int r = row0 + tid;
        bool v = r < n;
        cls[0][tid] = v ? cl0[r] : 0;
        cls[1][tid] = v ? cl1[r] : 0;
        cls[2][tid] = v ? cl2[r] : 0;
        sad[0][tid] = v ? adp[(size_t)r * 3 + 0] : 0.f;
        sad[1][tid] = v ? adp[(size_t)r * 3 + 1] : 0.f;
        sad[2][tid] = v ? adp[(size_t)r * 3 + 2] : 0.f;
    }
    __syncthreads();
    float acc[8][4] = {};
#pragma unroll
    for (int p = 0; p < 2; ++p) {
        stage_B(buf + OFF_B, tiles + (size_t)p * 4608, tid);
        cp_commit();
#pragma unroll
        for (int i = 0; i < 8; ++i) {
            int idx = tid + i * NTHR;
            int r = idx >> 4, c4 = idx & 15;
            int grow = row0 + r;
            float4 vv = make_float4(0.f, 0.f, 0.f, 0.f);
            if (grow < n) {
                if (p == 0) {
                    vv = *(const float4*)(Q + (size_t)grow * 64 + c4 * 4);
                    int ch = c4 * 4;
                    vv.x = fmaxf(vv.x * coef[ch + 0] + coef[64 + ch + 0], 0.f);
                    vv.y = fmaxf(vv.y * coef[ch + 1] + coef[64 + ch + 1], 0.f);
                    vv.z = fmaxf(vv.z * coef[ch + 2] + coef[64 + ch + 2], 0.f);
                    vv.w = fmaxf(vv.w * coef[ch + 3] + coef[64 + ch + 3], 0.f);
                } else {
                    float w0 = sad[0][r], w1 = sad[1][r], w2 = sad[2][r];
                    float4 a = *(const float4*)(segS + (size_t)(0 + cls[0][r]) * 64 + c4 * 4);
                    float4 bv = *(const float4*)(segS + (size_t)(4096 + cls[1][r]) * 64 + c4 * 4);
                    float4 cc = *(const float4*)(segS + (size_t)(36864 + cls[2][r]) * 64 + c4 * 4);
                    vv.x = w0 * a.x + w1 * bv.x + w2 * cc.x;
                    vv.y = w0 * a.y + w1 * bv.y + w2 * cc.y;
                    vv.z = w0 * a.z + w1 * bv.z + w2 * cc.z;
                    vv.w = w0 * a.w + w1 * bv.w + w2 * cc.w;
                }
            }
            a_store(buf, r, c4, vv);
        }
        cp_wait<0>();
        __syncthreads();
        mma_compute(buf, buf + OFF_B, acc, wid, lane);
        __syncthreads();
    }
    epilogue_stats(acc, Co, statsg, csum, csq, row0, n, wid, lane, tid);
}

// ---------------- small / elementwise kernels ----------------
// per-scale (gridDim.y=3): mean-arena += relu(bn(P)), cnt++
__global__ void k_segsum3(const float* __restrict__ bufs, const float* __restrict__ statsb,
                          const float* __restrict__ glw, const float* __restrict__ blw,
                          const int* __restrict__ cl0, const int* __restrict__ cl1,
                          const int* __restrict__ cl2, float* __restrict__ mean,
                          float* __restrict__ cnt, int n) {
    __shared__ float sc[128];
    int s = blockIdx.y;
    load_coef(sc, statsb + s * 128, glw + s * 64, blw + s * 64, n, threadIdx.x);
    __syncthreads();
    int row = blockIdx.x * blockDim.x + threadIdx.x;
    if (row >= n) return;
    const int* cl = (s == 0) ? cl0 : ((s == 1) ? cl1 : cl2);
    int c = c_soff[s] + cl[row];
    const float* p = bufs + (size_t)s * ROWSZ + (size_t)row * 64;
    float* sg = mean + (size_t)c * 64;
#pragma unroll
    for (int c4 = 0; c4 < 16; ++c4) {
        float4 x = *(const float4*)(p + c4 * 4);
        x.x = fmaxf(x.x * sc[c4 * 4 + 0] + sc[64 + c4 * 4 + 0], 0.f);
        x.y = fmaxf(x.y * sc[c4 * 4 + 1] + sc[64 + c4 * 4 + 1], 0.f);
        x.z = fmaxf(x.z * sc[c4 * 4 + 2] + sc[64 + c4 * 4 + 2], 0.f);
        x.w = fmaxf(x.w * sc[c4 * 4 + 3] + sc[64 + c4 * 4 + 3], 0.f);
        red_add_v4(sg + c4 * 4, x);
    }
    atomicAdd(&cnt[c], 1.f);
}

// per-scale (gridDim.y=3): segS += relu(bn(Q)) * expP / (den[cl]+1e-6)
__global__ void k_pw3(const float* __restrict__ bufs, const float* __restrict__ statsb,
                      const float* __restrict__ gproj, const float* __restrict__ bproj,
                      const float* __restrict__ den,
                      const int* __restrict__ cl0, const int* __restrict__ cl1,
                      const int* __restrict__ cl2, float* __restrict__ segS, int n) {
    __shared__ float sc[128];
    int s = blockIdx.y;
    load_coef(sc, statsb + (3 + s) * 128, gproj + s * 64, bproj + s * 64, n, threadIdx.x);
    __syncthreads();
    int row = blockIdx.x * blockDim.x + threadIdx.x;
    if (row >= n) return;
    const int* cl = (s == 0) ? cl0 : ((s == 1) ? cl1 : cl2);
    int c = c_soff[s] + cl[row];
    const float* q = bufs + (size_t)(3 + s) * ROWSZ + (size_t)row * 64;
    const float* p = bufs + (size_t)s * ROWSZ + (size_t)row * 64;
    const float* d = den + (size_t)c * 64;
    float* sg = segS + (size_t)c * 64;
#pragma unroll
    for (int c4 = 0; c4 < 16; ++c4) {
        float4 qv = *(const float4*)(q + c4 * 4);
        float4 pv = *(const float4*)(p + c4 * 4);
        float4 dv = *(const float4*)(d + c4 * 4);
        float4 o;
        o.x = fmaxf(qv.x * sc[c4 * 4 + 0] + sc[64 + c4 * 4 + 0], 0.f) * pv.x / (dv.x + 1e-6f);
        o.y = fmaxf(qv.y * sc[c4 * 4 + 1] + sc[64 + c4 * 4 + 1], 0.f) * pv.y / (dv.y + 1e-6f);
        o.z = fmaxf(qv.z * sc[c4 * 4 + 2] + sc[64 + c4 * 4 + 2], 0.f) * pv.z / (dv.z + 1e-6f);
        o.w = fmaxf(qv.w * sc[c4 * 4 + 3] + sc[64 + c4 * 4 + 3], 0.f) * pv.w / (dv.w + 1e-6f);
        red_add_v4(sg + c4 * 4, o);
    }
}

// out = relu(bn(H) + F)
__global__ void k_final(const float* __restrict__ H, const float* __restrict__ stats,
                        const float* __restrict__ g, const float* __restrict__ b,
                        const float* __restrict__ F, float* __restrict__ out,
                        int n, int total4) {
    __shared__ float sc[128];
    load_coef(sc, stats, g, b, n, threadIdx.x);
    __syncthreads();
    int i = blockIdx.x * 256 + threadIdx.x;
    if (i >= total4) return;
    int ch = (i & 15) * 4;
    float4 x = ((const float4*)H)[i];
    float4 r = ((const float4*)F)[i];
    x.x = fmaxf(x.x * sc[ch + 0] + sc[64 + ch + 0] + r.x, 0.f);
    x.y = fmaxf(x.y * sc[ch + 1] + sc[64 + ch + 1] + r.y, 0.f);
    x.z = fmaxf(x.z * sc[ch + 2] + sc[64 + ch + 2] + r.z, 0.f);
    x.w = fmaxf(x.w * sc[ch + 3] + sc[64 + ch + 3] + r.w, 0.f);
    ((float4*)out)[i] = x;
}

// ---------------------------------------------------------------------------
extern "C" void kernel_launch(void* const* d_in, const int* in_sizes, int n_in,
                              void* d_out, int out_size) {
    const float* feat   = (const float*)d_in[0];
    const int*   cl0    = (const int*)d_in[1];
    const int*   cl1    = (const int*)d_in[2];
    const int*   cl2    = (const int*)d_in[3];
    const int*   nbr    = (const int*)d_in[4];
    const float* W_lw   = (const float*)d_in[5];
    const float* g_lw   = (const float*)d_in[6];
    const float* b_lw   = (const float*)d_in[7];
    const float* W_w    = (const float*)d_in[8];
    const float* W_proj = (const float*)d_in[9];
    const float* g_proj = (const float*)d_in[10];
    const float* b_proj = (const float*)d_in[11];
    const float* W_adp  = (const float*)d_in[12];
    const float* W_fuse = (const float*)d_in[13];
    const float* g_fuse = (const float*)d_in[14];
    const float* b_fuse = (const float*)d_in[15];
    const float* W_c1   = (const float*)d_in[16];
    const float* g_c1   = (const float*)d_in[17];
    const float* b_c1   = (const float*)d_in[18];
    const float* W_c2   = (const float*)d_in[19];
    const float* g_c2   = (const float*)d_in[20];
    const float* b_c2   = (const float*)d_in[21];
    float* out = (float*)d_out;
    int n = in_sizes[1];

    float *pBufs, *pF, *pMean, *pDen, *pSegS, *pCnt, *pStats, *pAdp;
    unsigned *pPack, *pPackC, *pFph;
    cudaGetSymbolAddress((void**)&pBufs, g_bufs);
    cudaGetSymbolAddress((void**)&pF, g_bufF);
    cudaGetSymbolAddress((void**)&pFph, g_fph);
    cudaGetSymbolAddress((void**)&pMean, g_segMean);
    cudaGetSymbolAddress((void**)&pDen, g_segDen);
    cudaGetSymbolAddress((void**)&pSegS, g_segS);
    cudaGetSymbolAddress((void**)&pCnt, g_cnt);
    cudaGetSymbolAddress((void**)&pStats, g_statsA);
    cudaGetSymbolAddress((void**)&pAdp, g_adpv);
    cudaGetSymbolAddress((void**)&pPack, g_wpack);
    cudaGetSymbolAddress((void**)&pPackC, g_wpackc);

    const int GB = (n + TM - 1) / TM;
    const int EB = (n + 255) / 256;
    const int total4 = n * 16;
    const int SB = (total4 + 255) / 256;
    const int SM_G7 = 13824 * 4;                    // 55296B (A + single B)
    const int SM_1  = 13824 * 4;                    // 55296B
    const int SM_CV = (2 * CBUF + TM * 27) * 4;     // 69120B

    cudaFuncSetAttribute(k_mma_gemm7, cudaFuncAttributeMaxDynamicSharedMemorySize, SM_G7);
    cudaFuncSetAttribute(k_mma_submean_exp, cudaFuncAttributeMaxDynamicSharedMemorySize, SM_1);
    cudaFuncSetAttribute(k_mma_gemm2, cudaFuncAttributeMaxDynamicSharedMemorySize, SM_1);
    cudaFuncSetAttribute(k_mma_convh, cudaFuncAttributeMaxDynamicSharedMemorySize, SM_CV);

    const uint4* AF = (const uint4*)pFph;
    float* Qb3 = pBufs + 6 * ROWSZ;

    k_prepack<<<12, 256>>>(W_lw, W_w, W_proj, W_fuse, pPack);
    k_prepackc<<<54, 256>>>(W_c1, W_c2, pPackC);

    // 7 feat-GEMMs (feat converted in staging) + fused adp
    cudaMemsetAsync(pStats, 0, 7 * 128 * sizeof(float));
    k_mma_gemm7<<<GB, NTHR, SM_G7>>>(feat, W_adp, pPack, pBufs, pAdp, pStats, n);

    // cluster attention, all 3 scales batched
    cudaMemsetAsync(pMean, 0, (size_t)SEGTOT * 64 * sizeof(float));
    cudaMemsetAsync(pCnt, 0, (size_t)SEGTOT * sizeof(float));
    k_segsum3<<<dim3(EB, 3), 256>>>(pBufs, pStats, g_lw, b_lw, cl0, cl1, cl2,
                                    pMean, pCnt, n);
    cudaMemsetAsync(pDen, 0, (size_t)SEGTOT * 64 * sizeof(float));
    k_mma_submean_exp<<<dim3(GB, 3), NTHR, SM_1>>>(pBufs, pStats, g_lw, b_lw, pPack,
                                                   pMean, pCnt, cl0, cl1, cl2, pDen, n);
    cudaMemsetAsync(pSegS, 0, (size_t)SEGTOT * 64 * sizeof(float));
    k_pw3<<<dim3(EB, 3), 256>>>(pBufs, pStats, g_proj, b_proj, pDen,
                                cl0, cl1, cl2, pSegS, n);

    // fused = relu(bn([relu(bn(Q3)), mix] @ W_fuse)) + feat
    cudaMemsetAsync(pStats + 7 * 128, 0, 128 * sizeof(float));
    k_mma_gemm2<<<GB, NTHR, SM_1>>>(Qb3, pStats + 6 * 128, g_proj + 192, b_proj + 192,
                                    pPack + (size_t)10 * 4608, pSegS,
                                    cl0, cl1, cl2, pAdp, pF, pStats + 7 * 128, n);
    k_bnrelu_add_split<<<SB, 256>>>(pF, pStats + 7 * 128, g_fuse, b_fuse, feat,
                                    pFph, n, total4);
    // conv1 -> split ; conv2 -> final
    cudaMemsetAsync(pStats + 8 * 128, 0, 128 * sizeof(float));
    k_mma_convh<<<GB, NTHR, SM_CV>>>(AF, nbr, pPackC, pBufs, pStats + 8 * 128, n);
    k_bnrelu_split<<<SB, 256>>>(pBufs, pStats + 8 * 128, g_c1, b_c1, pFph, n, total4);
    cudaMemsetAsync(pStats + 9 * 128, 0, 128 * sizeof(float));
    k_mma_convh<<<GB, NTHR, SM_CV>>>(AF, nbr, pPackC + (size_t)27 * 2304,
                                     pBufs + ROWSZ, pStats + 9 * 128, n);
    k_final<<<SB, 256>>>(pBufs + ROWSZ, pStats + 9 * 128, g_c2, b_c2, pF, out, n, total4);
}

// round 12
// speedup vs baseline: 2.1512x; 1.0591x over previous
#include <cuda_runtime.h>
#include <cuda_bf16.h>
#include <cuda_fp16.h>

// ---------------------------------------------------------------------------
// OACNNs block, round 12.
//  - ALL matmuls now fp16 single-plane mma (attention GEMMs converted; convs
//    already were). 3x fewer MMA + 2x less staging in gemm7/submean/gemm2.
//  - fp32 accumulate + fp32 intermediate buffers retained; BN stats fp32.
//  - conv + scatter path unchanged from round 11 (2805us, rel_err 2.86e-4).
// ---------------------------------------------------------------------------

#define NPTS_MAX 500000
#define SEGTOT   167936     // 4096 + 32768 + 131072
#define TM   128
#define NTHR 256
#define AS   36             // uints per row (144B stride, LDSM conflict-free)
#define CBUF   6912        // uints per fp16 buffer (A 4608 + B 2304)
#define COFF_B 4608
#define ROWSZ  ((size_t)NPTS_MAX * 64)
#define CONV_TX 25600u     // 128 rows * 128B + 9216B B tile

// scratch (device globals: allocation-free rule)
__device__ float          g_bufs[7 * ROWSZ];     // P0,P1,P2,Q0,Q1,Q2,Q3
__device__ float          g_bufF[ROWSZ];
__device__ unsigned       g_fph[NPTS_MAX * 32];  // fp16 plane of conv input
__device__ float          g_segMean[SEGTOT * 64];
__device__ float          g_segDen [SEGTOT * 64];
__device__ float          g_segS   [SEGTOT * 64];
__device__ float          g_cnt    [SEGTOT];
__device__ float          g_adpv[NPTS_MAX * 3];
__device__ float          g_statsA[10 * 128];    // 0-6 gemm7, 7 fuse, 8 c1, 9 c2
__device__ unsigned       g_wpack[12 * 2304];    // fp16 tiles (lw,w,proj,fuse)
__device__ unsigned       g_wpackc[54 * 2304];   // fp16 conv tiles

__device__ __constant__ int c_soff[3] = {0, 4096, 36864};

// ---------------- helpers ----------------
__device__ __forceinline__ void red_add_v4(float* addr, float4 v) {
    asm volatile("red.global.add.v4.f32 [%0], {%1,%2,%3,%4};"
                 :: "l"(addr), "f"(v.x), "f"(v.y), "f"(v.z), "f"(v.w)
                 : "memory");
}
__device__ __forceinline__ void red_add_v2(float* addr, float x, float y) {
    asm volatile("red.global.add.v2.f32 [%0], {%1,%2};"
                 :: "l"(addr), "f"(x), "f"(y) : "memory");
}
__device__ __forceinline__ void cp16(unsigned* dst, const void* src, bool v) {
    unsigned d = (unsigned)__cvta_generic_to_shared(dst);
    int sz = v ? 16 : 0;
    asm volatile("cp.async.cg.shared.global [%0], [%1], 16, %2;"
                 :: "r"(d), "l"(src), "r"(sz) : "memory");
}
__device__ __forceinline__ void cp_commit() {
    asm volatile("cp.async.commit_group;" ::: "memory");
}
template <int N> __device__ __forceinline__ void cp_wait() {
    asm volatile("cp.async.wait_group %0;" :: "n"(N) : "memory");
}
__device__ __forceinline__ void cpbulk(unsigned dst, const void* src,
                                       unsigned bytes, unsigned mba) {
    asm volatile(
        "cp.async.bulk.shared::cluster.global.mbarrier::complete_tx::bytes "
        "[%0], [%1], %2, [%3];"
        :: "r"(dst), "l"(src), "r"(bytes), "r"(mba) : "memory");
}
__device__ __forceinline__ void mbar_init(unsigned mba, unsigned cnt) {
    asm volatile("mbarrier.init.shared.b64 [%0], %1;" :: "r"(mba), "r"(cnt) : "memory");
}
__device__ __forceinline__ void mbar_expect(unsigned mba, unsigned bytes) {
    asm volatile("mbarrier.arrive.expect_tx.shared.b64 _, [%0], %1;"
                 :: "r"(mba), "r"(bytes) : "memory");
}
__device__ __forceinline__ void mbar_wait(unsigned mba, int phase) {
    asm volatile(
        "{\n\t"
        ".reg .pred P;\n\t"
        "LAB_%=:\n\t"
        "mbarrier.try_wait.parity.acquire.cta.shared::cta.b64 P, [%0], %1;\n\t"
        "@!P bra LAB_%=;\n\t"
        "}"
        :: "r"(mba), "r"(phase) : "memory");
}

__device__ __forceinline__ unsigned packh2(float x, float y) {
    __half2 h; h.x = __float2half(x); h.y = __float2half(y);
    return *reinterpret_cast<unsigned*>(&h);
}

__device__ __forceinline__ void mma16816h(float* d, unsigned a0, unsigned a1,
                                          unsigned a2, unsigned a3,
                                          unsigned b0, unsigned b1) {
    asm volatile(
        "mma.sync.aligned.m16n8k16.row.col.f32.f16.f16.f32 "
        "{%0,%1,%2,%3}, {%4,%5,%6,%7}, {%8,%9}, {%0,%1,%2,%3};"
        : "+f"(d[0]), "+f"(d[1]), "+f"(d[2]), "+f"(d[3])
        : "r"(a0), "r"(a1), "r"(a2), "r"(a3), "r"(b0), "r"(b1));
}
__device__ __forceinline__ void ldsm4(unsigned& r0, unsigned& r1, unsigned& r2,
                                      unsigned& r3, const unsigned* p) {
    unsigned a = (unsigned)__cvta_generic_to_shared(p);
    asm volatile("ldmatrix.sync.aligned.m8n8.x4.shared.b16 {%0,%1,%2,%3}, [%4];"
                 : "=r"(r0), "=r"(r1), "=r"(r2), "=r"(r3) : "r"(a));
}

// fp16 A store: one plane, uint2 per float4
__device__ __forceinline__ void a_storeh(unsigned* buf, int r, int c4, float4 v) {
    *reinterpret_cast<uint2*>(buf + r * AS + c4 * 2) =
        make_uint2(packh2(v.x, v.y), packh2(v.z, v.w));
}

// fp16 B tile staging (2304 uints = 9216B)
__device__ __forceinline__ void stage_Bc(unsigned* Bdst, const unsigned* tile, int tid) {
    const uint4* s = reinterpret_cast<const uint4*>(tile);
    for (int i = tid; i < 576; i += NTHR) cp16(Bdst + i * 4, s + i, true);
}

// 128x64x64 fp16 single-plane mma sweep
__device__ __forceinline__ void mma_compute_h(const unsigned* buf, float acc[8][4],
                                              int wid, int lane) {
    const unsigned* Ap = buf;
    const unsigned* Bp = buf + COFF_B;
    const unsigned* aph = Ap + (wid * 16 + (lane & 15)) * AS + (lane >> 4) * 4;
    int brow = lane & 7;
    int koff = ((lane >> 3) & 1) * 4;
    int ntoff = ((lane >> 4) & 1) * 8 * AS;
#pragma unroll
    for (int kk = 0; kk < 4; ++kk) {
        int ko = kk * 8;
        unsigned a0, a1, a2, a3;
        ldsm4(a0, a1, a2, a3, aph + ko);
#pragma unroll
        for (int np = 0; np < 4; ++np) {
            unsigned b0, b1, b2, b3;
            ldsm4(b0, b1, b2, b3, Bp + (np * 16 + brow) * AS + ntoff + ko + koff);
            mma16816h(acc[2 * np], a0, a1, a2, a3, b0, b1);
            mma16816h(acc[2 * np + 1], a0, a1, a2, a3, b2, b3);
        }
    }
}

// store + shuffle-reduced stats; rows >= n masked out of stats
__device__ __forceinline__ void epilogue_stats(float acc[8][4], float* __restrict__ Co,
                                               float* __restrict__ statsg,
                                               float* csum, float* csq,
                                               int row0, int n, int wid, int lane, int tid) {
    int g = lane >> 2, c = lane & 3;
    int r0 = row0 + wid * 16 + g, r1 = r0 + 8;
    bool v0 = r0 < n, v1 = r1 < n;
#pragma unroll
    for (int nt = 0; nt < 8; ++nt) {
        int ch = nt * 8 + 2 * c;
        float a0 = v0 ? acc[nt][0] : 0.f;
        float a1 = v0 ? acc[nt][1] : 0.f;
        float a2 = v1 ? acc[nt][2] : 0.f;
        float a3 = v1 ? acc[nt][3] : 0.f;
        if (v0) *(float2*)(Co + (size_t)r0 * 64 + ch) = make_float2(a0, a1);
        if (v1) *(float2*)(Co + (size_t)r1 * 64 + ch) = make_float2(a2, a3);
        float s0 = a0 + a2;
        float s1 = a1 + a3;
        float q0 = a0 * a0 + a2 * a2;
        float q1 = a1 * a1 + a3 * a3;
#pragma unroll
        for (int d = 4; d < 32; d <<= 1) {
            s0 += __shfl_xor_sync(0xffffffffu, s0, d);
            s1 += __shfl_xor_sync(0xffffffffu, s1, d);
            q0 += __shfl_xor_sync(0xffffffffu, q0, d);
            q1 += __shfl_xor_sync(0xffffffffu, q1, d);
        }
        if (lane < 4) {
            atomicAdd(&csum[ch], s0);
            atomicAdd(&csum[ch + 1], s1);
            atomicAdd(&csq[ch], q0);
            atomicAdd(&csq[ch + 1], q1);
        }
    }
    __syncthreads();
    if (tid < 64)       atomicAdd(&statsg[tid], csum[tid]);
    else if (tid < 128) atomicAdd(&statsg[tid], csq[tid - 64]);
}

__device__ __forceinline__ void load_coef(float* sc, const float* __restrict__ stats,
                                          const float* __restrict__ g,
                                          const float* __restrict__ b, int n, int tid) {
    if (tid < 64) {
        float inv_n = 1.f / (float)n;
        float mean = stats[tid] * inv_n;
        float var = stats[64 + tid] * inv_n - mean * mean;
        float a = g[tid] * rsqrtf(var + 1e-3f);
        sc[tid] = a;
        sc[64 + tid] = b[tid] - mean * a;
    }
}

// ---------------- prepack (all fp16 n-major tiles) ----------------
__global__ void k_prepack(const float* __restrict__ Wlw, const float* __restrict__ Ww,
                          const float* __restrict__ Wproj, const float* __restrict__ Wfuse,
                          unsigned* __restrict__ pack) {
    int t = blockIdx.x;     // 0..11
    const float* src;
    if (t < 3)       src = Wlw  + t * 4096;
    else if (t < 6)  src = Ww   + (t - 3) * 4096;
    else if (t < 10) src = Wproj+ (t - 6) * 4096;
    else             src = Wfuse+ (t - 10) * 4096;
    unsigned* ph = pack + (size_t)t * 2304;
    for (int idx = threadIdx.x; idx < 2048; idx += 256) {
        int cout = idx & 63, p = idx >> 6;
        ph[cout * AS + p] = packh2(src[2 * p * 64 + cout], src[(2 * p + 1) * 64 + cout]);
    }
}
__global__ void k_prepackc(const float* __restrict__ Wc1, const float* __restrict__ Wc2,
                           unsigned* __restrict__ packc) {
    int t = blockIdx.x;     // 0..53
    const float* src = (t < 27) ? Wc1 + t * 4096 : Wc2 + (t - 27) * 4096;
    unsigned* ph = packc + (size_t)t * 2304;
    for (int idx = threadIdx.x; idx < 2048; idx += 256) {
        int cout = idx & 63, p = idx >> 6;
        ph[cout * AS + p] = packh2(src[2 * p * 64 + cout], src[(2 * p + 1) * 64 + cout]);
    }
}

// F = relu(bn(rawF)) + feat; emit fp16 plane of F
__global__ void k_bnrelu_add_split(float* __restrict__ F, const float* __restrict__ stats,
                                   const float* __restrict__ g, const float* __restrict__ b,
                                   const float* __restrict__ feat,
                                   unsigned* __restrict__ Hp, int n, int total4) {
    __shared__ float sc[128];
    load_coef(sc, stats, g, b, n, threadIdx.x);
    __syncthreads();
    int i = blockIdx.x * 256 + threadIdx.x;
    if (i >= total4) return;
    int ch = (i & 15) * 4;
    float4 x = ((const float4*)F)[i];
    float4 r = ((const float4*)feat)[i];
    x.x = fmaxf(x.x * sc[ch + 0] + sc[64 + ch + 0], 0.f) + r.x;
    x.y = fmaxf(x.y * sc[ch + 1] + sc[64 + ch + 1], 0.f) + r.y;
    x.z = fmaxf(x.z * sc[ch + 2] + sc[64 + ch + 2], 0.f) + r.z;
    x.w = fmaxf(x.w * sc[ch + 3] + sc[64 + ch + 3], 0.f) + r.w;
    ((float4*)F)[i] = x;
    ((uint2*)Hp)[i] = make_uint2(packh2(x.x, x.y), packh2(x.z, x.w));
}

// fp16 plane = relu(bn(P))
__global__ void k_bnrelu_split(const float* __restrict__ P, const float* __restrict__ stats,
                               const float* __restrict__ g, const float* __restrict__ b,
                               unsigned* __restrict__ Hp, int n, int total4) {
    __shared__ float sc[128];
    load_coef(sc, stats, g, b, n, threadIdx.x);
    __syncthreads();
    int i = blockIdx.x * 256 + threadIdx.x;
    if (i >= total4) return;
    int ch = (i & 15) * 4;
    float4 x = ((const float4*)P)[i];
    x.x = fmaxf(x.x * sc[ch + 0] + sc[64 + ch + 0], 0.f);
    x.y = fmaxf(x.y * sc[ch + 1] + sc[64 + ch + 1], 0.f);
    x.z = fmaxf(x.z * sc[ch + 2] + sc[64 + ch + 2], 0.f);
    x.w = fmaxf(x.w * sc[ch + 3] + sc[64 + ch + 3], 0.f);
    ((uint2*)Hp)[i] = make_uint2(packh2(x.x, x.y), packh2(x.z, x.w));
}

// ---------------- tensor-core kernels ----------------
// 7 GEMMs sharing A=feat (fp16-converted in staging) + fused adp softmax.
__global__ __launch_bounds__(NTHR, 4)
void k_mma_gemm7(const float* __restrict__ feat, const float* __restrict__ Wa,
                 const unsigned* __restrict__ pack, float* __restrict__ bufs,
                 float* __restrict__ adp, float* __restrict__ statsg, int n) {
    extern __shared__ unsigned sm[];     // A:[0,4608) B:[4608,6912)
    __shared__ float csum[64], csq[64];
    __shared__ float wa[192];
    const int tidx[7] = {0, 1, 2, 6, 7, 8, 9};
    int tid = threadIdx.x, wid = tid >> 5, lane = tid & 31;
    int row0 = blockIdx.x * TM;
    if (tid < 192) wa[tid] = Wa[tid];
    stage_Bc(sm + COFF_B, pack + (size_t)tidx[0] * 2304, tid);
    cp_commit();
    __syncthreads();     // wa visible
#pragma unroll
    for (int i = 0; i < 8; ++i) {   // convert feat -> fp16 plane, fused adp
        int idx = tid + i * NTHR;
        int r = idx >> 4, c4 = idx & 15;
        int grow = row0 + r;
        float4 v = make_float4(0.f, 0.f, 0.f, 0.f);
        if (grow < n) v = *(const float4*)(feat + (size_t)grow * 64 + c4 * 4);
        a_storeh(sm, r, c4, v);
        int ch = c4 * 4;
        float s0 = v.x * wa[ch * 3 + 0] + v.y * wa[ch * 3 + 3] +
                   v.z * wa[ch * 3 + 6] + v.w * wa[ch * 3 + 9];
        float s1 = v.x * wa[ch * 3 + 1] + v.y * wa[ch * 3 + 4] +
                   v.z * wa[ch * 3 + 7] + v.w * wa[ch * 3 + 10];
        float s2 = v.x * wa[ch * 3 + 2] + v.y * wa[ch * 3 + 5] +
                   v.z * wa[ch * 3 + 8] + v.w * wa[ch * 3 + 11];
#pragma unroll
        for (int d = 1; d < 16; d <<= 1) {
            s0 += __shfl_xor_sync(0xffffffffu, s0, d);
            s1 += __shfl_xor_sync(0xffffffffu, s1, d);
            s2 += __shfl_xor_sync(0xffffffffu, s2, d);
        }
        if ((lane & 15) == 0 && grow < n) {
            float m = fmaxf(s0, fmaxf(s1, s2));
            float e0 = __expf(s0 - m), e1 = __expf(s1 - m), e2 = __expf(s2 - m);
            float inv = 1.f / (e0 + e1 + e2);
            adp[(size_t)grow * 3 + 0] = e0 * inv;
            adp[(size_t)grow * 3 + 1] = e1 * inv;
            adp[(size_t)grow * 3 + 2] = e2 * inv;
        }
    }
    cp_wait<0>();
    __syncthreads();
    for (int t = 0; t < 7; ++t) {
        if (tid < 64) { csum[tid] = 0.f; csq[tid] = 0.f; }
        __syncthreads();
        float acc[8][4] = {};
        mma_compute_h(sm, acc, wid, lane);
        epilogue_stats(acc, bufs + (size_t)t * ROWSZ, statsg + t * 128,
                       csum, csq, row0, n, wid, lane, tid);
        if (t + 1 < 7) {    // all B reads done (epilogue's internal sync)
            stage_Bc(sm + COFF_B, pack + (size_t)tidx[t + 1] * 2304, tid);
            cp_commit();
            cp_wait<0>();
        }
    }
}

// stage one conv tap via cp.async.bulk into buffer `buf` tracked by mbar `mba`
__device__ __forceinline__ void conv_stage(unsigned smb, int buf, int k,
                                           const uint4* __restrict__ AF,
                                           const int* __restrict__ idxs,
                                           const unsigned* __restrict__ packc,
                                           unsigned mba, int tid) {
    unsigned bbase = smb + (unsigned)buf * (CBUF * 4);
    if (tid < 128) {
        const void* src = AF + (size_t)idxs[tid * 27 + k] * 8;
        cpbulk(bbase + tid * (AS * 4), src, 128, mba);
    } else if (tid == 128) {
        mbar_expect(mba, CONV_TX);
        cpbulk(bbase + COFF_B * 4, packc + (size_t)k * 2304, 9216, mba);
    }
}

// gather conv (fp16 single-plane), bulk-copy double-buffer pipeline; + stats
__global__ __launch_bounds__(NTHR)
void k_mma_convh(const uint4* __restrict__ AF, const int* __restrict__ nbr,
                 const unsigned* __restrict__ packc,
                 float* __restrict__ Co, float* __restrict__ statsg, int n) {
    extern __shared__ unsigned sm[];          // 2 x CBUF + idx cache
    int* idxs = (int*)(sm + 2 * CBUF);        // [TM*27]
    __shared__ float csum[64], csq[64];
    __shared__ unsigned long long mbar[2];
    int tid = threadIdx.x, wid = tid >> 5, lane = tid & 31;
    int row0 = blockIdx.x * TM;
    unsigned mb0 = (unsigned)__cvta_generic_to_shared(&mbar[0]);
    unsigned mb1 = (unsigned)__cvta_generic_to_shared(&mbar[1]);
    unsigned smb = (unsigned)__cvta_generic_to_shared(sm);
    if (tid < 64) { csum[tid] = 0.f; csq[tid] = 0.f; }
    if (tid == 0) { mbar_init(mb0, 1); mbar_init(mb1, 1); }
    {   // coalesced preload of neighbor indices
        size_t base = (size_t)row0 * 27;
        size_t lim = (size_t)n * 27;
        for (int i = tid; i < TM * 27; i += NTHR) {
            size_t pos = base + i;
            idxs[i] = (pos < lim) ? __ldg(&nbr[pos]) : 0;
        }
    }
    __syncthreads();
    int ph0 = 0, ph1 = 0;
    conv_stage(smb, 0, 0, AF, idxs, packc, mb0, tid);
    float acc[8][4] = {};
    for (int k = 0; k < 27; ++k) {
        if (k + 1 < 27)
            conv_stage(smb, (k + 1) & 1, k + 1, AF, idxs, packc,
                       (k & 1) ? mb0 : mb1, tid);
        if (k & 1) { mbar_wait(mb1, ph1); ph1 ^= 1; }
        else       { mbar_wait(mb0, ph0); ph0 ^= 1; }
        mma_compute_h(sm + (k & 1) * CBUF, acc, wid, lane);
        __syncthreads();
    }
    epilogue_stats(acc, Co, statsg, csum, csq, row0, n, wid, lane, tid);
}

// per-scale (gridDim.y=3): P = exp((relu(bn(P)) - mean[cl]) @ W_w); den += P
__global__ __launch_bounds__(NTHR)
void k_mma_submean_exp(float* __restrict__ bufs, const float* __restrict__ statsb,
                       const float* __restrict__ glw, const float* __restrict__ blw,
                       const unsigned* __restrict__ pack, const float* __restrict__ mean,
                       const float* __restrict__ cnt,
                       const int* __restrict__ cl0, const int* __restrict__ cl1,
                       const int* __restrict__ cl2, float* __restrict__ den, int n) {
    extern __shared__ unsigned buf[];
    __shared__ float coef[128];
    __shared__ int   cls[TM];
    __shared__ float cinv[TM];
    int s = blockIdx.y;
    const int* cl = (s == 0) ? cl0 : ((s == 1) ? cl1 : cl2);
    int soff = c_soff[s];
    float* P = bufs + (size_t)s * ROWSZ;
    int tid = threadIdx.x, wid = tid >> 5, lane = tid & 31;
    int row0 = blockIdx.x * TM;
    load_coef(coef, statsb + s * 128, glw + s * 64, blw + s * 64, n, tid);
    if (tid < 128) {
        int r = row0 + tid;
        int c = (r < n) ? cl[r] : 0;
        cls[tid] = c;
        cinv[tid] = 1.f / fmaxf(cnt[soff + c], 1.f);
    }
    stage_Bc(buf + COFF_B, pack + (size_t)(3 + s) * 2304, tid);
    cp_commit();
    __syncthreads();
#pragma unroll
    for (int i = 0; i < 8; ++i) {
        int idx = tid + i * NTHR;
        int r = idx >> 4, c4 = idx & 15;
        int grow = row0 + r;
        float4 vv = make_float4(0.f, 0.f, 0.f, 0.f);
        if (grow < n) {
            vv = *(const float4*)(P + (size_t)grow * 64 + c4 * 4);
            float4 ms = *(const float4*)(mean + (size_t)(soff + cls[r]) * 64 + c4 * 4);
            float ci = cinv[r];
            int ch = c4 * 4;
            vv.x = fmaxf(vv.x * coef[ch + 0] + coef[64 + ch + 0], 0.f) - ms.x * ci;
            vv.y = fmaxf(vv.y * coef[ch + 1] + coef[64 + ch + 1], 0.f) - ms.y * ci;
            vv.z = fmaxf(vv.z * coef[ch + 2] + coef[64 + ch + 2], 0.f) - ms.z * ci;
            vv.w = fmaxf(vv.w * coef[ch + 3] + coef[64 + ch + 3], 0.f) - ms.w * ci;
        }
        a_storeh(buf, r, c4, vv);
    }
    cp_wait<0>();
    __syncthreads();
    float acc[8][4] = {};
    mma_compute_h(buf, acc, wid, lane);
    int g = lane >> 2, c = lane & 3;
    int lr0 = wid * 16 + g, lr1 = lr0 + 8;
    int r0 = row0 + lr0, r1 = row0 + lr1;
    float* d0 = den + (size_t)(soff + cls[lr0]) * 64;
    float* d1 = den + (size_t)(soff + cls[lr1]) * 64;
#pragma unroll
    for (int nt = 0; nt < 8; ++nt) {
        int ch = nt * 8 + 2 * c;
        if (r0 < n) {
            float e0 = __expf(acc[nt][0]), e1 = __expf(acc[nt][1]);
            *(float2*)(P + (size_t)r0 * 64 + ch) = make_float2(e0, e1);
            red_add_v2(d0 + ch, e0, e1);
        }
        if (r1 < n) {
            float e2 = __expf(acc[nt][2]), e3 = __expf(acc[nt][3]);
            *(float2*)(P + (size_t)r1 * 64 + ch) = make_float2(e2, e3);
            red_add_v2(d1 + ch, e2, e3);
        }
    }
}

// fuse GEMM: Co = relu(bn(Q))@Wf[0:64] + mix@Wf[64:128] + stats
__global__ __launch_bounds__(NTHR)
void k_mma_gemm2(const float* __restrict__ Q, const float* __restrict__ stats,
                 const float* __restrict__ gg, const float* __restrict__ bb,
                 const unsigned* __restrict__ tiles, const float* __restrict__ segS,
                 const int* __restrict__ cl0, const int* __restrict__ cl1,
                 const int* __restrict__ cl2, const float* __restrict__ adp,
                 float* __restrict__ Co, float* __restrict__ statsg, int n) {
    extern __shared__ unsigned buf[];
    __shared__ float csum[64], csq[64];
    __shared__ float coef[128];
    __shared__ int   cls[3][TM];
    __shared__ float sad[3][TM];
    int tid = threadIdx.x, wid = tid >> 5, lane = tid & 31;
    int row0 = blockIdx.x * TM;
    if (tid < 64) { csum[tid] = 0.f; csq[tid] = 0.f; }
    load_coef(coef, stats, gg, bb, n, tid);
    if (tid < 128) {
        int r = row0 + tid;
        bool v = r < n;
        cls[0][tid] = v ? cl0[r] : 0;
        cls[1][tid] = v ? cl1[r] : 0;
        cls[2][tid] = v ? cl2[r] : 0;
        sad[0][tid] = v ? adp[(size_t)r * 3 + 0] : 0.f;
        sad[1][tid] = v ? adp[(size_t)r * 3 + 1] : 0.f;
        sad[2][tid] = v ? adp[(size_t)r * 3 + 2] : 0.f;
    }
    __syncthreads();
    float acc[8][4] = {};
#pragma unroll
    for (int p = 0; p < 2; ++p) {
        stage_Bc(buf + COFF_B, tiles + (size_t)p * 2304, tid);
        cp_commit();
#pragma unroll
        for (int i = 0; i < 8; ++i) {
            int idx = tid + i * NTHR;
            int r = idx >> 4, c4 = idx & 15;
            int grow = row0 + r;
            float4 vv = make_float4(0.f, 0.f, 0.f, 0.f);
            if (grow < n) {
                if (p == 0) {
                    vv = *(const float4*)(Q + (size_t)grow * 64 + c4 * 4);
                    int ch = c4 * 4;
                    vv.x = fmaxf(vv.x * coef[ch + 0] + coef[64 + ch + 0], 0.f);
                    vv.y = fmaxf(vv.y * coef[ch + 1] + coef[64 + ch + 1], 0.f);
                    vv.z = fmaxf(vv.z * coef[ch + 2] + coef[64 + ch + 2], 0.f);
                    vv.w = fmaxf(vv.w * coef[ch + 3] + coef[64 + ch + 3], 0.f);
                } else {
                    float w0 = sad[0][r], w1 = sad[1][r], w2 = sad[2][r];
                    float4 a = *(const float4*)(segS + (size_t)(0 + cls[0][r]) * 64 + c4 * 4);
                    float4 bv = *(const float4*)(segS + (size_t)(4096 + cls[1][r]) * 64 + c4 * 4);
                    float4 cc = *(const float4*)(segS + (size_t)(36864 + cls[2][r]) * 64 + c4 * 4);
                    vv.x = w0 * a.x + w1 * bv.x + w2 * cc.x;
                    vv.y = w0 * a.y + w1 * bv.y + w2 * cc.y;
                    vv.z = w0 * a.z + w1 * bv.z + w2 * cc.z;
                    vv.w = w0 * a.w + w1 * bv.w + w2 * cc.w;
                }
            }
            a_storeh(buf, r, c4, vv);
        }
        cp_wait<0>();
        __syncthreads();
        mma_compute_h(buf, acc, wid, lane);
        __syncthreads();
    }
    epilogue_stats(acc, Co, statsg, csum, csq, row0, n, wid, lane, tid);
}

// ---------------- small / elementwise kernels ----------------
// per-scale (gridDim.y=3): mean-arena += relu(bn(P)), cnt++
__global__ void k_segsum3(const float* __restrict__ bufs, const float* __restrict__ statsb,
                          const float* __restrict__ glw, const float* __restrict__ blw,
                          const int* __restrict__ cl0, const int* __restrict__ cl1,
                          const int* __restrict__ cl2, float* __restrict__ mean,
                          float* __restrict__ cnt, int n) {
    __shared__ float sc[128];
    int s = blockIdx.y;
    load_coef(sc, statsb + s * 128, glw + s * 64, blw + s * 64, n, threadIdx.x);
    __syncthreads();
    int row = blockIdx.x * blockDim.x + threadIdx.x;
    if (row >= n) return;
    const int* cl = (s == 0) ? cl0 : ((s == 1) ? cl1 : cl2);
    int c = c_soff[s] + cl[row];
    const float* p = bufs + (size_t)s * ROWSZ + (size_t)row * 64;
    float* sg = mean + (size_t)c * 64;
#pragma unroll
    for (int c4 = 0; c4 < 16; ++c4) {
        float4 x = *(const float4*)(p + c4 * 4);
        x.x = fmaxf(x.x * sc[c4 * 4 + 0] + sc[64 + c4 * 4 + 0], 0.f);
        x.y = fmaxf(x.y * sc[c4 * 4 + 1] + sc[64 + c4 * 4 + 1], 0.f);
        x.z = fmaxf(x.z * sc[c4 * 4 + 2] + sc[64 + c4 * 4 + 2], 0.f);
        x.w = fmaxf(x.w * sc[c4 * 4 + 3] + sc[64 + c4 * 4 + 3], 0.f);
        red_add_v4(sg + c4 * 4, x);
    }
    atomicAdd(&cnt[c], 1.f);
}

// per-scale (gridDim.y=3): segS += relu(bn(Q)) * expP / (den[cl]+1e-6)
__global__ void k_pw3(const float* __restrict__ bufs, const float* __restrict__ statsb,
                      const float* __restrict__ gproj, const float* __restrict__ bproj,
                      const float* __restrict__ den,
                      const int* __restrict__ cl0, const int* __restrict__ cl1,
                      const int* __restrict__ cl2, float* __restrict__ segS, int n) {
    __shared__ float sc[128];
    int s = blockIdx.y;
    load_coef(sc, statsb + (3 + s) * 128, gproj + s * 64, bproj + s * 64, n, threadIdx.x);
    __syncthreads();
    int row = blockIdx.x * blockDim.x + threadIdx.x;
    if (row >= n) return;
    const int* cl = (s == 0) ? cl0 : ((s == 1) ? cl1 : cl2);
    int c = c_soff[s] + cl[row];
    const float* q = bufs + (size_t)(3 + s) * ROWSZ + (size_t)row * 64;
    const float* p = bufs + (size_t)s * ROWSZ + (size_t)row * 64;
    const float* d = den + (size_t)c * 64;
    float* sg = segS + (size_t)c * 64;
#pragma unroll
    for (int c4 = 0; c4 < 16; ++c4) {
        float4 qv = *(const float4*)(q + c4 * 4);
        float4 pv = *(const float4*)(p + c4 * 4);
        float4 dv = *(const float4*)(d + c4 * 4);
        float4 o;
        o.x = fmaxf(qv.x * sc[c4 * 4 + 0] + sc[64 + c4 * 4 + 0], 0.f) * pv.x / (dv.x + 1e-6f);
        o.y = fmaxf(qv.y * sc[c4 * 4 + 1] + sc[64 + c4 * 4 + 1], 0.f) * pv.y / (dv.y + 1e-6f);
        o.z = fmaxf(qv.z * sc[c4 * 4 + 2] + sc[64 + c4 * 4 + 2], 0.f) * pv.z / (dv.z + 1e-6f);
        o.w = fmaxf(qv.w * sc[c4 * 4 + 3] + sc[64 + c4 * 4 + 3], 0.f) * pv.w / (dv.w + 1e-6f);
        red_add_v4(sg + c4 * 4, o);
    }
}

// out = relu(bn(H) + F)
__global__ void k_final(const float* __restrict__ H, const float* __restrict__ stats,
                        const float* __restrict__ g, const float* __restrict__ b,
                        const float* __restrict__ F, float* __restrict__ out,
                        int n, int total4) {
    __shared__ float sc[128];
    load_coef(sc, stats, g, b, n, threadIdx.x);
    __syncthreads();
    int i = blockIdx.x * 256 + threadIdx.x;
    if (i >= total4) return;
    int ch = (i & 15) * 4;
    float4 x = ((const float4*)H)[i];
    float4 r = ((const float4*)F)[i];
    x.x = fmaxf(x.x * sc[ch + 0] + sc[64 + ch + 0] + r.x, 0.f);
    x.y = fmaxf(x.y * sc[ch + 1] + sc[64 + ch + 1] + r.y, 0.f);
    x.z = fmaxf(x.z * sc[ch + 2] + sc[64 + ch + 2] + r.z, 0.f);
    x.w = fmaxf(x.w * sc[ch + 3] + sc[64 + ch + 3] + r.w, 0.f);
    ((float4*)out)[i] = x;
}

// ---------------------------------------------------------------------------
extern "C" void kernel_launch(void* const* d_in, const int* in_sizes, int n_in,
                              void* d_out, int out_size) {
    const float* feat   = (const float*)d_in[0];
    const int*   cl0    = (const int*)d_in[1];
    const int*   cl1    = (const int*)d_in[2];
    const int*   cl2    = (const int*)d_in[3];
    const int*   nbr    = (const int*)d_in[4];
    const float* W_lw   = (const float*)d_in[5];
    const float* g_lw   = (const float*)d_in[6];
    const float* b_lw   = (const float*)d_in[7];
    const float* W_w    = (const float*)d_in[8];
    const float* W_proj = (const float*)d_in[9];
    const float* g_proj = (const float*)d_in[10];
    const float* b_proj = (const float*)d_in[11];
    const float* W_adp  = (const float*)d_in[12];
    const float* W_fuse = (const float*)d_in[13];
    const float* g_fuse = (const float*)d_in[14];
    const float* b_fuse = (const float*)d_in[15];
    const float* W_c1   = (const float*)d_in[16];
    const float* g_c1   = (const float*)d_in[17];
    const float* b_c1   = (const float*)d_in[18];
    const float* W_c2   = (const float*)d_in[19];
    const float* g_c2   = (const float*)d_in[20];
    const float* b_c2   = (const float*)d_in[21];
    float* out = (float*)d_out;
    int n = in_sizes[1];

    float *pBufs, *pF, *pMean, *pDen, *pSegS, *pCnt, *pStats, *pAdp;
    unsigned *pPack, *pPackC, *pFph;
    cudaGetSymbolAddress((void**)&pBufs, g_bufs);
    cudaGetSymbolAddress((void**)&pF, g_bufF);
    cudaGetSymbolAddress((void**)&pFph, g_fph);
    cudaGetSymbolAddress((void**)&pMean, g_segMean);
    cudaGetSymbolAddress((void**)&pDen, g_segDen);
    cudaGetSymbolAddress((void**)&pSegS, g_segS);
    cudaGetSymbolAddress((void**)&pCnt, g_cnt);
    cudaGetSymbolAddress((void**)&pStats, g_statsA);
    cudaGetSymbolAddress((void**)&pAdp, g_adpv);
    cudaGetSymbolAddress((void**)&pPack, g_wpack);
    cudaGetSymbolAddress((void**)&pPackC, g_wpackc);

    const int GB = (n + TM - 1) / TM;
    const int EB = (n + 255) / 256;
    const int total4 = n * 16;
    const int SB = (total4 + 255) / 256;
    const int SM_1  = CBUF * 4;                     // 27648B (fp16 A + B)
    const int SM_CV = (2 * CBUF + TM * 27) * 4;     // 69120B

    cudaFuncSetAttribute(k_mma_gemm7, cudaFuncAttributeMaxDynamicSharedMemorySize, SM_1);
    cudaFuncSetAttribute(k_mma_submean_exp, cudaFuncAttributeMaxDynamicSharedMemorySize, SM_1);
    cudaFuncSetAttribute(k_mma_gemm2, cudaFuncAttributeMaxDynamicSharedMemorySize, SM_1);
    cudaFuncSetAttribute(k_mma_convh, cudaFuncAttributeMaxDynamicSharedMemorySize, SM_CV);

    const uint4* AF = (const uint4*)pFph;
    float* Qb3 = pBufs + 6 * ROWSZ;

    k_prepack<<<12, 256>>>(W_lw, W_w, W_proj, W_fuse, pPack);
    k_prepackc<<<54, 256>>>(W_c1, W_c2, pPackC);

    // 7 feat-GEMMs (feat converted in staging) + fused adp
    cudaMemsetAsync(pStats, 0, 7 * 128 * sizeof(float));
    k_mma_gemm7<<<GB, NTHR, SM_1>>>(feat, W_adp, pPack, pBufs, pAdp, pStats, n);

    // cluster attention, all 3 scales batched
    cudaMemsetAsync(pMean, 0, (size_t)SEGTOT * 64 * sizeof(float));
    cudaMemsetAsync(pCnt, 0, (size_t)SEGTOT * sizeof(float));
    k_segsum3<<<dim3(EB, 3), 256>>>(pBufs, pStats, g_lw, b_lw, cl0, cl1, cl2,
                                    pMean, pCnt, n);
    cudaMemsetAsync(pDen, 0, (size_t)SEGTOT * 64 * sizeof(float));
    k_mma_submean_exp<<<dim3(GB, 3), NTHR, SM_1>>>(pBufs, pStats, g_lw, b_lw, pPack,
                                                   pMean, pCnt, cl0, cl1, cl2, pDen, n);
    cudaMemsetAsync(pSegS, 0, (size_t)SEGTOT * 64 * sizeof(float));
    k_pw3<<<dim3(EB, 3), 256>>>(pBufs, pStats, g_proj, b_proj, pDen,
                                cl0, cl1, cl2, pSegS, n);

    // fused = relu(bn([relu(bn(Q3)), mix] @ W_fuse)) + feat
    cudaMemsetAsync(pStats + 7 * 128, 0, 128 * sizeof(float));
    k_mma_gemm2<<<GB, NTHR, SM_1>>>(Qb3, pStats + 6 * 128, g_proj + 192, b_proj + 192,
                                    pPack + (size_t)10 * 2304, pSegS,
                                    cl0, cl1, cl2, pAdp, pF, pStats + 7 * 128, n);
    k_bnrelu_add_split<<<SB, 256>>>(pF, pStats + 7 * 128, g_fuse, b_fuse, feat,
                                    pFph, n, total4);
    // conv1 -> split ; conv2 -> final
    cudaMemsetAsync(pStats + 8 * 128, 0, 128 * sizeof(float));
    k_mma_convh<<<GB, NTHR, SM_CV>>>(AF, nbr, pPackC, pBufs, pStats + 8 * 128, n);
    k_bnrelu_split<<<SB, 256>>>(pBufs, pStats + 8 * 128, g_c1, b_c1, pFph, n, total4);
    cudaMemsetAsync(pStats + 9 * 128, 0, 128 * sizeof(float));
    k_mma_convh<<<GB, NTHR, SM_CV>>>(AF, nbr, pPackC + (size_t)27 * 2304,
                                     pBufs + ROWSZ, pStats + 9 * 128, n);
    k_final<<<SB, 256>>>(pBufs + ROWSZ, pStats + 9 * 128, g_c2, b_c2, pF, out, n, total4);
}

// round 13
// speedup vs baseline: 2.2697x; 1.0551x over previous
#include <cuda_runtime.h>
#include <cuda_bf16.h>
#include <cuda_fp16.h>

// ---------------------------------------------------------------------------
// OACNNs block, round 13.
//  - ALL N x 64 intermediates (gemm7 outputs, expP, gemm2 raw out, conv
//    outputs) now stored fp16 -> ~1.3GB less DRAM traffic.
//  - fp32 kept for: residual F, BN stats, segment arenas, final output.
//  - matmul/conv/scatter structure unchanged from round 12 (2648us, 4.18e-4).
// ---------------------------------------------------------------------------

#define NPTS_MAX 500000
#define SEGTOT   167936     // 4096 + 32768 + 131072
#define TM   128
#define NTHR 256
#define AS   36             // uints per smem row (144B stride, LDSM conflict-free)
#define CBUF   6912        // uints per fp16 buffer (A 4608 + B 2304)
#define COFF_B 4608
#define ROWH   ((size_t)NPTS_MAX * 32)   // uints per fp16 N x 64 buffer
#define CONV_TX 25600u     // 128 rows * 128B + 9216B B tile

// scratch (device globals: allocation-free rule)
__device__ unsigned       g_bufsH[7 * ROWH];     // fp16 P0,P1,P2,Q0,Q1,Q2,Q3 (+reuse)
__device__ float          g_bufF[(size_t)NPTS_MAX * 64];
__device__ unsigned       g_fph[NPTS_MAX * 32];  // fp16 plane of conv input
__device__ float          g_segMean[SEGTOT * 64];
__device__ float          g_segDen [SEGTOT * 64];
__device__ float          g_segS   [SEGTOT * 64];
__device__ float          g_cnt    [SEGTOT];
__device__ float          g_adpv[NPTS_MAX * 3];
__device__ float          g_statsA[10 * 128];    // 0-6 gemm7, 7 fuse, 8 c1, 9 c2
__device__ unsigned       g_wpack[12 * 2304];    // fp16 tiles (lw,w,proj,fuse)
__device__ unsigned       g_wpackc[54 * 2304];   // fp16 conv tiles

__device__ __constant__ int c_soff[3] = {0, 4096, 36864};

// ---------------- helpers ----------------
__device__ __forceinline__ void red_add_v4(float* addr, float4 v) {
    asm volatile("red.global.add.v4.f32 [%0], {%1,%2,%3,%4};"
                 :: "l"(addr), "f"(v.x), "f"(v.y), "f"(v.z), "f"(v.w)
                 : "memory");
}
__device__ __forceinline__ void red_add_v2(float* addr, float x, float y) {
    asm volatile("red.global.add.v2.f32 [%0], {%1,%2};"
                 :: "l"(addr), "f"(x), "f"(y) : "memory");
}
__device__ __forceinline__ void cp16(unsigned* dst, const void* src, bool v) {
    unsigned d = (unsigned)__cvta_generic_to_shared(dst);
    int sz = v ? 16 : 0;
    asm volatile("cp.async.cg.shared.global [%0], [%1], 16, %2;"
                 :: "r"(d), "l"(src), "r"(sz) : "memory");
}
__device__ __forceinline__ void cp_commit() {
    asm volatile("cp.async.commit_group;" ::: "memory");
}
template <int N> __device__ __forceinline__ void cp_wait() {
    asm volatile("cp.async.wait_group %0;" :: "n"(N) : "memory");
}
__device__ __forceinline__ void cpbulk(unsigned dst, const void* src,
                                       unsigned bytes, unsigned mba) {
    asm volatile(
        "cp.async.bulk.shared::cluster.global.mbarrier::complete_tx::bytes "
        "[%0], [%1], %2, [%3];"
        :: "r"(dst), "l"(src), "r"(bytes), "r"(mba) : "memory");
}
__device__ __forceinline__ void mbar_init(unsigned mba, unsigned cnt) {
    asm volatile("mbarrier.init.shared.b64 [%0], %1;" :: "r"(mba), "r"(cnt) : "memory");
}
__device__ __forceinline__ void mbar_expect(unsigned mba, unsigned bytes) {
    asm volatile("mbarrier.arrive.expect_tx.shared.b64 _, [%0], %1;"
                 :: "r"(mba), "r"(bytes) : "memory");
}
__device__ __forceinline__ void mbar_wait(unsigned mba, int phase) {
    asm volatile(
        "{\n\t"
        ".reg .pred P;\n\t"
        "LAB_%=:\n\t"
        "mbarrier.try_wait.parity.acquire.cta.shared::cta.b64 P, [%0], %1;\n\t"
        "@!P bra LAB_%=;\n\t"
        "}"
        :: "r"(mba), "r"(phase) : "memory");
}

__device__ __forceinline__ unsigned packh2(float x, float y) {
    __half2 h; h.x = __float2half(x); h.y = __float2half(y);
    return *reinterpret_cast<unsigned*>(&h);
}
// load 4 halves (2 uints, 8B-aligned) -> float4
__device__ __forceinline__ float4 ldh4(const unsigned* p) {
    uint2 u = *reinterpret_cast<const uint2*>(p);
    __half2 h0 = *reinterpret_cast<__half2*>(&u.x);
    __half2 h1 = *reinterpret_cast<__half2*>(&u.y);
    float2 f0 = __half22float2(h0), f1 = __half22float2(h1);
    return make_float4(f0.x, f0.y, f1.x, f1.y);
}

__device__ __forceinline__ void mma16816h(float* d, unsigned a0, unsigned a1,
                                          unsigned a2, unsigned a3,
                                          unsigned b0, unsigned b1) {
    asm volatile(
        "mma.sync.aligned.m16n8k16.row.col.f32.f16.f16.f32 "
        "{%0,%1,%2,%3}, {%4,%5,%6,%7}, {%8,%9}, {%0,%1,%2,%3};"
        : "+f"(d[0]), "+f"(d[1]), "+f"(d[2]), "+f"(d[3])
        : "r"(a0), "r"(a1), "r"(a2), "r"(a3), "r"(b0), "r"(b1));
}
__device__ __forceinline__ void ldsm4(unsigned& r0, unsigned& r1, unsigned& r2,
                                      unsigned& r3, const unsigned* p) {
    unsigned a = (unsigned)__cvta_generic_to_shared(p);
    asm volatile("ldmatrix.sync.aligned.m8n8.x4.shared.b16 {%0,%1,%2,%3}, [%4];"
                 : "=r"(r0), "=r"(r1), "=r"(r2), "=r"(r3) : "r"(a));
}

// fp16 A store: one plane, uint2 per float4
__device__ __forceinline__ void a_storeh(unsigned* buf, int r, int c4, float4 v) {
    *reinterpret_cast<uint2*>(buf + r * AS + c4 * 2) =
        make_uint2(packh2(v.x, v.y), packh2(v.z, v.w));
}

// fp16 B tile staging (2304 uints = 9216B)
__device__ __forceinline__ void stage_Bc(unsigned* Bdst, const unsigned* tile, int tid) {
    const uint4* s = reinterpret_cast<const uint4*>(tile);
    for (int i = tid; i < 576; i += NTHR) cp16(Bdst + i * 4, s + i, true);
}

// 128x64x64 fp16 single-plane mma sweep
__device__ __forceinline__ void mma_compute_h(const unsigned* buf, float acc[8][4],
                                              int wid, int lane) {
    const unsigned* Ap = buf;
    const unsigned* Bp = buf + COFF_B;
    const unsigned* aph = Ap + (wid * 16 + (lane & 15)) * AS + (lane >> 4) * 4;
    int brow = lane & 7;
    int koff = ((lane >> 3) & 1) * 4;
    int ntoff = ((lane >> 4) & 1) * 8 * AS;
#pragma unroll
    for (int kk = 0; kk < 4; ++kk) {
        int ko = kk * 8;
        unsigned a0, a1, a2, a3;
        ldsm4(a0, a1, a2, a3, aph + ko);
#pragma unroll
        for (int np = 0; np < 4; ++np) {
            unsigned b0, b1, b2, b3;
            ldsm4(b0, b1, b2, b3, Bp + (np * 16 + brow) * AS + ntoff + ko + koff);
            mma16816h(acc[2 * np], a0, a1, a2, a3, b0, b1);
            mma16816h(acc[2 * np + 1], a0, a1, a2, a3, b2, b3);
        }
    }
}

// fp16 store + shuffle-reduced fp32 stats; rows >= n masked out of stats
__device__ __forceinline__ void epilogue_stats_h(float acc[8][4], unsigned* __restrict__ Co,
                                                 float* __restrict__ statsg,
                                                 float* csum, float* csq,
                                                 int row0, int n, int wid, int lane, int tid) {
    int g = lane >> 2, c = lane & 3;
    int r0 = row0 + wid * 16 + g, r1 = r0 + 8;
    bool v0 = r0 < n, v1 = r1 < n;
#pragma unroll
    for (int nt = 0; nt < 8; ++nt) {
        int ch = nt * 8 + 2 * c;
        float a0 = v0 ? acc[nt][0] : 0.f;
        float a1 = v0 ? acc[nt][1] : 0.f;
        float a2 = v1 ? acc[nt][2] : 0.f;
        float a3 = v1 ? acc[nt][3] : 0.f;
        if (v0) Co[(size_t)r0 * 32 + (ch >> 1)] = packh2(a0, a1);
        if (v1) Co[(size_t)r1 * 32 + (ch >> 1)] = packh2(a2, a3);
        float s0 = a0 + a2;
        float s1 = a1 + a3;
        float q0 = a0 * a0 + a2 * a2;
        float q1 = a1 * a1 + a3 * a3;
#pragma unroll
        for (int d = 4; d < 32; d <<= 1) {
            s0 += __shfl_xor_sync(0xffffffffu, s0, d);
            s1 += __shfl_xor_sync(0xffffffffu, s1, d);
            q0 += __shfl_xor_sync(0xffffffffu, q0, d);
            q1 += __shfl_xor_sync(0xffffffffu, q1, d);
        }
        if (lane < 4) {
            atomicAdd(&csum[ch], s0);
            atomicAdd(&csum[ch + 1], s1);
            atomicAdd(&csq[ch], q0);
            atomicAdd(&csq[ch + 1], q1);
        }
    }
    __syncthreads();
    if (tid < 64)       atomicAdd(&statsg[tid], csum[tid]);
    else if (tid < 128) atomicAdd(&statsg[tid], csq[tid - 64]);
}

__device__ __forceinline__ void load_coef(float* sc, const float* __restrict__ stats,
                                          const float* __restrict__ g,
                                          const float* __restrict__ b, int n, int tid) {
    if (tid < 64) {
        float inv_n = 1.f / (float)n;
        float mean = stats[tid] * inv_n;
        float var = stats[64 + tid] * inv_n - mean * mean;
        float a = g[tid] * rsqrtf(var + 1e-3f);
        sc[tid] = a;
        sc[64 + tid] = b[tid] - mean * a;
    }
}

// ---------------- prepack (all fp16 n-major tiles) ----------------
__global__ void k_prepack(const float* __restrict__ Wlw, const float* __restrict__ Ww,
                          const float* __restrict__ Wproj, const float* __restrict__ Wfuse,
                          unsigned* __restrict__ pack) {
    int t = blockIdx.x;     // 0..11
    const float* src;
    if (t < 3)       src = Wlw  + t * 4096;
    else if (t < 6)  src = Ww   + (t - 3) * 4096;
    else if (t < 10) src = Wproj+ (t - 6) * 4096;
    else             src = Wfuse+ (t - 10) * 4096;
    unsigned* ph = pack + (size_t)t * 2304;
    for (int idx = threadIdx.x; idx < 2048; idx += 256) {
        int cout = idx & 63, p = idx >> 6;
        ph[cout * AS + p] = packh2(src[2 * p * 64 + cout], src[(2 * p + 1) * 64 + cout]);
    }
}
__global__ void k_prepackc(const float* __restrict__ Wc1, const float* __restrict__ Wc2,
                           unsigned* __restrict__ packc) {
    int t = blockIdx.x;     // 0..53
    const float* src = (t < 27) ? Wc1 + t * 4096 : Wc2 + (t - 27) * 4096;
    unsigned* ph = packc + (size_t)t * 2304;
    for (int idx = threadIdx.x; idx < 2048; idx += 256) {
        int cout = idx & 63, p = idx >> 6;
        ph[cout * AS + p] = packh2(src[2 * p * 64 + cout], src[(2 * p + 1) * 64 + cout]);
    }
}

// F = relu(bn(rawF_h)) + feat; emit F fp32 and fp16 plane of F
__global__ void k_bnrelu_add_split(const unsigned* __restrict__ RawH,
                                   float* __restrict__ F, const float* __restrict__ stats,
                                   const float* __restrict__ g, const float* __restrict__ b,
                                   const float* __restrict__ feat,
                                   unsigned* __restrict__ Hp, int n, int total4) {
    __shared__ float sc[128];
    load_coef(sc, stats, g, b, n, threadIdx.x);
    __syncthreads();
    int i = blockIdx.x * 256 + threadIdx.x;
    if (i >= total4) return;
    int ch = (i & 15) * 4;
    float4 x = ldh4(RawH + (size_t)i * 2);
    float4 r = ((const float4*)feat)[i];
    x.x = fmaxf(x.x * sc[ch + 0] + sc[64 + ch + 0], 0.f) + r.x;
    x.y = fmaxf(x.y * sc[ch + 1] + sc[64 + ch + 1], 0.f) + r.y;
    x.z = fmaxf(x.z * sc[ch + 2] + sc[64 + ch + 2], 0.f) + r.z;
    x.w = fmaxf(x.w * sc[ch + 3] + sc[64 + ch + 3], 0.f) + r.w;
    ((float4*)F)[i] = x;
    ((uint2*)Hp)[i] = make_uint2(packh2(x.x, x.y), packh2(x.z, x.w));
}

// fp16 plane = relu(bn(P_h))
__global__ void k_bnrelu_split(const unsigned* __restrict__ Ph, const float* __restrict__ stats,
                               const float* __restrict__ g, const float* __restrict__ b,
                               unsigned* __restrict__ Hp, int n, int total4) {
    __shared__ float sc[128];
    load_coef(sc, stats, g, b, n, threadIdx.x);
    __syncthreads();
    int i = blockIdx.x * 256 + threadIdx.x;
    if (i >= total4) return;
    int ch = (i & 15) * 4;
    float4 x = ldh4(Ph + (size_t)i * 2);
    x.x = fmaxf(x.x * sc[ch + 0] + sc[64 + ch + 0], 0.f);
    x.y = fmaxf(x.y * sc[ch + 1] + sc[64 + ch + 1], 0.f);
    x.z = fmaxf(x.z * sc[ch + 2] + sc[64 + ch + 2], 0.f);
    x.w = fmaxf(x.w * sc[ch + 3] + sc[64 + ch + 3], 0.f);
    ((uint2*)Hp)[i] = make_uint2(packh2(x.x, x.y), packh2(x.z, x.w));
}

// ---------------- tensor-core kernels ----------------
// 7 GEMMs sharing A=feat (fp16-converted in staging) + fused adp softmax.
__global__ __launch_bounds__(NTHR, 4)
void k_mma_gemm7(const float* __restrict__ feat, const float* __restrict__ Wa,
                 const unsigned* __restrict__ pack, unsigned* __restrict__ bufs,
                 float* __restrict__ adp, float* __restrict__ statsg, int n) {
    extern __shared__ unsigned sm[];     // A:[0,4608) B:[4608,6912)
    __shared__ float csum[64], csq[64];
    __shared__ float wa[192];
    const int tidx[7] = {0, 1, 2, 6, 7, 8, 9};
    int tid = threadIdx.x, wid = tid >> 5, lane = tid & 31;
    int row0 = blockIdx.x * TM;
    if (tid < 192) wa[tid] = Wa[tid];
    stage_Bc(sm + COFF_B, pack + (size_t)tidx[0] * 2304, tid);
    cp_commit();
    __syncthreads();     // wa visible
#pragma unroll
    for (int i = 0; i < 8; ++i) {   // convert feat -> fp16 plane, fused adp
        int idx = tid + i * NTHR;
        int r = idx >> 4, c4 = idx & 15;
        int grow = row0 + r;
        float4 v = make_float4(0.f, 0.f, 0.f, 0.f);
        if (grow < n) v = *(const float4*)(feat + (size_t)grow * 64 + c4 * 4);
        a_storeh(sm, r, c4, v);
        int ch = c4 * 4;
        float s0 = v.x * wa[ch * 3 + 0] + v.y * wa[ch * 3 + 3] +
                   v.z * wa[ch * 3 + 6] + v.w * wa[ch * 3 + 9];
        float s1 = v.x * wa[ch * 3 + 1] + v.y * wa[ch * 3 + 4] +
                   v.z * wa[ch * 3 + 7] + v.w * wa[ch * 3 + 10];
        float s2 = v.x * wa[ch * 3 + 2] + v.y * wa[ch * 3 + 5] +
                   v.z * wa[ch * 3 + 8] + v.w * wa[ch * 3 + 11];
#pragma unroll
        for (int d = 1; d < 16; d <<= 1) {
            s0 += __shfl_xor_sync(0xffffffffu, s0, d);
            s1 += __shfl_xor_sync(0xffffffffu, s1, d);
            s2 += __shfl_xor_sync(0xffffffffu, s2, d);
        }
        if ((lane & 15) == 0 && grow < n) {
            float m = fmaxf(s0, fmaxf(s1, s2));
            float e0 = __expf(s0 - m), e1 = __expf(s1 - m), e2 = __expf(s2 - m);
            float inv = 1.f / (e0 + e1 + e2);
            adp[(size_t)grow * 3 + 0] = e0 * inv;
            adp[(size_t)grow * 3 + 1] = e1 * inv;
            adp[(size_t)grow * 3 + 2] = e2 * inv;
        }
    }
    cp_wait<0>();
    __syncthreads();
    for (int t = 0; t < 7; ++t) {
        if (tid < 64) { csum[tid] = 0.f; csq[tid] = 0.f; }
        __syncthreads();
        float acc[8][4] = {};
        mma_compute_h(sm, acc, wid, lane);
        epilogue_stats_h(acc, bufs + (size_t)t * ROWH, statsg + t * 128,
                         csum, csq, row0, n, wid, lane, tid);
        if (t + 1 < 7) {    // all B reads done (epilogue's internal sync)
            stage_Bc(sm + COFF_B, pack + (size_t)tidx[t + 1] * 2304, tid);
            cp_commit();
            cp_wait<0>();
        }
    }
}

// stage one conv tap via cp.async.bulk into buffer `buf` tracked by mbar `mba`
__device__ __forceinline__ void conv_stage(unsigned smb, int buf, int k,
                                           const uint4* __restrict__ AF,
                                           const int* __restrict__ idxs,
                                           const unsigned* __restrict__ packc,
                                           unsigned mba, int tid) {
    unsigned bbase = smb + (unsigned)buf * (CBUF * 4);
    if (tid < 128) {
        const void* src = AF + (size_t)idxs[tid * 27 + k] * 8;
        cpbulk(bbase + tid * (AS * 4), src, 128, mba);
    } else if (tid == 128) {
        mbar_expect(mba, CONV_TX);
        cpbulk(bbase + COFF_B * 4, packc + (size_t)k * 2304, 9216, mba);
    }
}

// gather conv (fp16), bulk-copy double-buffer pipeline; fp16 out + stats
__global__ __launch_bounds__(NTHR)
void k_mma_convh(const uint4* __restrict__ AF, const int* __restrict__ nbr,
                 const unsigned* __restrict__ packc,
                 unsigned* __restrict__ Co, float* __restrict__ statsg, int n) {
    extern __shared__ unsigned sm[];          // 2 x CBUF + idx cache
    int* idxs = (int*)(sm + 2 * CBUF);        // [TM*27]
    __shared__ float csum[64], csq[64];
    __shared__ unsigned long long mbar[2];
    int tid = threadIdx.x, wid = tid >> 5, lane = tid & 31;
    int row0 = blockIdx.x * TM;
    unsigned mb0 = (unsigned)__cvta_generic_to_shared(&mbar[0]);
    unsigned mb1 = (unsigned)__cvta_generic_to_shared(&mbar[1]);
    unsigned smb = (unsigned)__cvta_generic_to_shared(sm);
    if (tid < 64) { csum[tid] = 0.f; csq[tid] = 0.f; }
    if (tid == 0) { mbar_init(mb0, 1); mbar_init(mb1, 1); }
    {   // coalesced preload of neighbor indices
        size_t base = (size_t)row0 * 27;
        size_t lim = (size_t)n * 27;
        for (int i = tid; i < TM * 27; i += NTHR) {
            size_t pos = base + i;
            idxs[i] = (pos < lim) ? __ldg(&nbr[pos]) : 0;
        }
    }
    __syncthreads();
    int ph0 = 0, ph1 = 0;
    conv_stage(smb, 0, 0, AF, idxs, packc, mb0, tid);
    float acc[8][4] = {};
    for (int k = 0; k < 27; ++k) {
        if (k + 1 < 27)
            conv_stage(smb, (k + 1) & 1, k + 1, AF, idxs, packc,
                       (k & 1) ? mb0 : mb1, tid);
        if (k & 1) { mbar_wait(mb1, ph1); ph1 ^= 1; }
        else       { mbar_wait(mb0, ph0); ph0 ^= 1; }
        mma_compute_h(sm + (k & 1) * CBUF, acc, wid, lane);
        __syncthreads();
    }
    epilogue_stats_h(acc, Co, statsg, csum, csq, row0, n, wid, lane, tid);
}

// per-scale (gridDim.y=3): P = exp((relu(bn(P)) - mean[cl]) @ W_w); den += P
// P is fp16 in/out (in-place).
__global__ __launch_bounds__(NTHR)
void k_mma_submean_exp(unsigned* __restrict__ bufs, const float* __restrict__ statsb,
                       const float* __restrict__ glw, const float* __restrict__ blw,
                       const unsigned* __restrict__ pack, const float* __restrict__ mean,
                       const float* __restrict__ cnt,
                       const int* __restrict__ cl0, const int* __restrict__ cl1,
                       const int* __restrict__ cl2, float* __restrict__ den, int n) {
    extern __shared__ unsigned buf[];
    __shared__ float coef[128];
    __shared__ int   cls[TM];
    __shared__ float cinv[TM];
    int s = blockIdx.y;
    const int* cl = (s == 0) ? cl0 : ((s == 1) ? cl1 : cl2);
    int soff = c_soff[s];
    unsigned* P = bufs + (size_t)s * ROWH;
    int tid = threadIdx.x, wid = tid >> 5, lane = tid & 31;
    int row0 = blockIdx.x * TM;
    load_coef(coef, statsb + s * 128, glw + s * 64, blw + s * 64, n, tid);
    if (tid < 128) {
        int r = row0 + tid;
        int c = (r < n) ? cl[r] : 0;
        cls[tid] = c;
        cinv[tid] = 1.f / fmaxf(cnt[soff + c], 1.f);
    }
    stage_Bc(buf + COFF_B, pack + (size_t)(3 + s) * 2304, tid);
    cp_commit();
    __syncthreads();
#pragma unroll
    for (int i = 0; i < 8; ++i) {
        int idx = tid + i * NTHR;
        int r = idx >> 4, c4 = idx & 15;
        int grow = row0 + r;
        float4 vv = make_float4(0.f, 0.f, 0.f, 0.f);
        if (grow < n) {
            vv = ldh4(P + (size_t)grow * 32 + c4 * 2);
            float4 ms = *(const float4*)(mean + (size_t)(soff + cls[r]) * 64 + c4 * 4);
            float ci = cinv[r];
            int ch = c4 * 4;
            vv.x = fmaxf(vv.x * coef[ch + 0] + coef[64 + ch + 0], 0.f) - ms.x * ci;
            vv.y = fmaxf(vv.y * coef[ch + 1] + coef[64 + ch + 1], 0.f) - ms.y * ci;
            vv.z = fmaxf(vv.z * coef[ch + 2] + coef[64 + ch + 2], 0.f) - ms.z * ci;
            vv.w = fmaxf(vv.w * coef[ch + 3] + coef[64 + ch + 3], 0.f) - ms.w * ci;
        }
        a_storeh(buf, r, c4, vv);
    }
    cp_wait<0>();
    __syncthreads();
    float acc[8][4] = {};
    mma_compute_h(buf, acc, wid, lane);
    int g = lane >> 2, c = lane & 3;
    int lr0 = wid * 16 + g, lr1 = lr0 + 8;
    int r0 = row0 + lr0, r1 = row0 + lr1;
    float* d0 = den + (size_t)(soff + cls[lr0]) * 64;
    float* d1 = den + (size_t)(soff + cls[lr1]) * 64;
#pragma unroll
    for (int nt = 0; nt < 8; ++nt) {
        int ch = nt * 8 + 2 * c;
        if (r0 < n) {
            float e0 = __expf(acc[nt][0]), e1 = __expf(acc[nt][1]);
            P[(size_t)r0 * 32 + (ch >> 1)] = packh2(e0, e1);
            red_add_v2(d0 + ch, e0, e1);
        }
        if (r1 < n) {
            float e2 = __expf(acc[nt][2]), e3 = __expf(acc[nt][3]);
            P[(size_t)r1 * 32 + (ch >> 1)] = packh2(e2, e3);
            red_add_v2(d1 + ch, e2, e3);
        }
    }
}

// fuse GEMM: rawF_h = relu(bn(Q3))@Wf[0:64] + mix@Wf[64:128]; fp16 out + stats
__global__ __launch_bounds__(NTHR)
void k_mma_gemm2(const unsigned* __restrict__ Qh, const float* __restrict__ stats,
                 const float* __restrict__ gg, const float* __restrict__ bb,
                 const unsigned* __restrict__ tiles, const float* __restrict__ segS,
                 const int* __restrict__ cl0, const int* __restrict__ cl1,
                 const int* __restrict__ cl2, const float* __restrict__ adp,
                 unsigned* __restrict__ Co, float* __restrict__ statsg, int n) {
    extern __shared__ unsigned buf[];
    __shared__ float csum[64], csq[64];
    __shared__ float coef[128];
    __shared__ int   cls[3][TM];
    __shared__ float sad[3][TM];
    int tid = threadIdx.x, wid = tid >> 5, lane = tid & 31;
    int row0 = blockIdx.x * TM;
    if (tid < 64) { csum[tid] = 0.f; csq[tid] = 0.f; }
    load_coef(coef, stats, gg, bb, n, tid);
    if (tid < 128) {
        int r = row0 + tid;
        bool v = r < n;
        cls[0][tid] = v ? cl0[r] : 0;
        cls[1][tid] = v ? cl1[r] : 0;
        cls[2][tid] = v ? cl2[r] : 0;
        sad[0][tid] = v ? adp[(size_t)r * 3 + 0] : 0.f;
        sad[1][tid] = v ? adp[(size_t)r * 3 + 1] : 0.f;
        sad[2][tid] = v ? adp[(size_t)r * 3 + 2] : 0.f;
    }
    __syncthreads();
    float acc[8][4] = {};
#pragma unroll
    for (int p = 0; p < 2; ++p) {
        stage_Bc(buf + COFF_B, tiles + (size_t)p * 2304, tid);
        cp_commit();
#pragma unroll
        for (int i = 0; i < 8; ++i) {
            int idx = tid + i * NTHR;
            int r = idx >> 4, c4 = idx & 15;
            int grow = row0 + r;
            float4 vv = make_float4(0.f, 0.f, 0.f, 0.f);
            if (grow < n) {
                if (p == 0) {
                    vv = ldh4(Qh + (size_t)grow * 32 + c4 * 2);
                    int ch = c4 * 4;
                    vv.x = fmaxf(vv.x * coef[ch + 0] + coef[64 + ch + 0], 0.f);
                    vv.y = fmaxf(vv.y * coef[ch + 1] + coef[64 + ch + 1], 0.f);
                    vv.z = fmaxf(vv.z * coef[ch + 2] + coef[64 + ch + 2], 0.f);
                    vv.w = fmaxf(vv.w * coef[ch + 3] + coef[64 + ch + 3], 0.f);
                } else {
                    float w0 = sad[0][r], w1 = sad[1][r], w2 = sad[2][r];
                    float4 a = *(const float4*)(segS + (size_t)(0 + cls[0][r]) * 64 + c4 * 4);
                    float4 bv = *(const float4*)(segS + (size_t)(4096 + cls[1][r]) * 64 + c4 * 4);
                    float4 cc = *(const float4*)(segS + (size_t)(36864 + cls[2][r]) * 64 + c4 * 4);
                    vv.x = w0 * a.x + w1 * bv.x + w2 * cc.x;
                    vv.y = w0 * a.y + w1 * bv.y + w2 * cc.y;
                    vv.z = w0 * a.z + w1 * bv.z + w2 * cc.z;
                    vv.w = w0 * a.w + w1 * bv.w + w2 * cc.w;
                }
            }
            a_storeh(buf, r, c4, vv);
        }
        cp_wait<0>();
        __syncthreads();
        mma_compute_h(buf, acc, wid, lane);
        __syncthreads();
    }
    epilogue_stats_h(acc, Co, statsg, csum, csq, row0, n, wid, lane, tid);
}

// ---------------- small / elementwise kernels ----------------
// per-scale (gridDim.y=3): mean-arena += relu(bn(P_h)), cnt++
__global__ void k_segsum3(const unsigned* __restrict__ bufs, const float* __restrict__ statsb,
                          const float* __restrict__ glw, const float* __restrict__ blw,
                          const int* __restrict__ cl0, const int* __restrict__ cl1,
                          const int* __restrict__ cl2, float* __restrict__ mean,
                          float* __restrict__ cnt, int n) {
    __shared__ float sc[128];
    int s = blockIdx.y;
    load_coef(sc, statsb + s * 128, glw + s * 64, blw + s * 64, n, threadIdx.x);
    __syncthreads();
    int row = blockIdx.x * blockDim.x + threadIdx.x;
    if (row >= n) return;
    const int* cl = (s == 0) ? cl0 : ((s == 1) ? cl1 : cl2);
    int c = c_soff[s] + cl[row];
    const unsigned* p = bufs + (size_t)s * ROWH + (size_t)row * 32;
    float* sg = mean + (size_t)c * 64;
#pragma unroll
    for (int c4 = 0; c4 < 16; ++c4) {
        float4 x = ldh4(p + c4 * 2);
        x.x = fmaxf(x.x * sc[c4 * 4 + 0] + sc[64 + c4 * 4 + 0], 0.f);
        x.y = fmaxf(x.y * sc[c4 * 4 + 1] + sc[64 + c4 * 4 + 1], 0.f);
        x.z = fmaxf(x.z * sc[c4 * 4 + 2] + sc[64 + c4 * 4 + 2], 0.f);
        x.w = fmaxf(x.w * sc[c4 * 4 + 3] + sc[64 + c4 * 4 + 3], 0.f);
        red_add_v4(sg + c4 * 4, x);
    }
    atomicAdd(&cnt[c], 1.f);
}

// per-scale (gridDim.y=3): segS += relu(bn(Q_h)) * expP_h / (den[cl]+1e-6)
__global__ void k_pw3(const unsigned* __restrict__ bufs, const float* __restrict__ statsb,
                      const float* __restrict__ gproj, const float* __restrict__ bproj,
                      const float* __restrict__ den,
                      const int* __restrict__ cl0, const int* __restrict__ cl1,
                      const int* __restrict__ cl2, float* __restrict__ segS, int n) {
    __shared__ float sc[128];
    int s = blockIdx.y;
    load_coef(sc, statsb + (3 + s) * 128, gproj + s * 64, bproj + s * 64, n, threadIdx.x);
    __syncthreads();
    int row = blockIdx.x * blockDim.x + threadIdx.x;
    if (row >= n) return;
    const int* cl = (s == 0) ? cl0 : ((s == 1) ? cl1 : cl2);
    int c = c_soff[s] + cl[row];
    const unsigned* q = bufs + (size_t)(3 + s) * ROWH + (size_t)row * 32;
    const unsigned* p = bufs + (size_t)s * ROWH + (size_t)row * 32;
    const float* d = den + (size_t)c * 64;
    float* sg = segS + (size_t)c * 64;
#pragma unroll
    for (int c4 = 0; c4 < 16; ++c4) {
        float4 qv = ldh4(q + c4 * 2);
        float4 pv = ldh4(p + c4 * 2);
        float4 dv = *(const float4*)(d + c4 * 4);
        float4 o;
        o.x = fmaxf(qv.x * sc[c4 * 4 + 0] + sc[64 + c4 * 4 + 0], 0.f) * pv.x / (dv.x + 1e-6f);
        o.y = fmaxf(qv.y * sc[c4 * 4 + 1] + sc[64 + c4 * 4 + 1], 0.f) * pv.y / (dv.y + 1e-6f);
        o.z = fmaxf(qv.z * sc[c4 * 4 + 2] + sc[64 + c4 * 4 + 2], 0.f) * pv.z / (dv.z + 1e-6f);
        o.w = fmaxf(qv.w * sc[c4 * 4 + 3] + sc[64 + c4 * 4 + 3], 0.f) * pv.w / (dv.w + 1e-6f);
        red_add_v4(sg + c4 * 4, o);
    }
}

// out = relu(bn(H_h) + F)
__global__ void k_final(const unsigned* __restrict__ Hh, const float* __restrict__ stats,
                        const float* __restrict__ g, const float* __restrict__ b,
                        const float* __restrict__ F, float* __restrict__ out,
                        int n, int total4) {
    __shared__ float sc[128];
    load_coef(sc, stats, g, b, n, threadIdx.x);
    __syncthreads();
    int i = blockIdx.x * 256 + threadIdx.x;
    if (i >= total4) return;
    int ch = (i & 15) * 4;
    float4 x = ldh4(Hh + (size_t)i * 2);
    float4 r = ((const float4*)F)[i];
    x.x = fmaxf(x.x * sc[ch + 0] + sc[64 + ch + 0] + r.x, 0.f);
    x.y = fmaxf(x.y * sc[ch + 1] + sc[64 + ch + 1] + r.y, 0.f);
    x.z = fmaxf(x.z * sc[ch + 2] + sc[64 + ch + 2] + r.z, 0.f);
    x.w = fmaxf(x.w * sc[ch + 3] + sc[64 + ch + 3] + r.w, 0.f);
    ((float4*)out)[i] = x;
}

// ---------------------------------------------------------------------------
extern "C" void kernel_launch(void* const* d_in, const int* in_sizes, int n_in,
                              void* d_out, int out_size) {
    const float* feat   = (const float*)d_in[0];
    const int*   cl0    = (const int*)d_in[1];
    const int*   cl1    = (const int*)d_in[2];
    const int*   cl2    = (const int*)d_in[3];
    const int*   nbr    = (const int*)d_in[4];
    const float* W_lw   = (const float*)d_in[5];
    const float* g_lw   = (const float*)d_in[6];
    const float* b_lw   = (const float*)d_in[7];
    const float* W_w    = (const float*)d_in[8];
    const float* W_proj = (const float*)d_in[9];
    const float* g_proj = (const float*)d_in[10];
    const float* b_proj = (const float*)d_in[11];
    const float* W_adp  = (const float*)d_in[12];
    const float* W_fuse = (const float*)d_in[13];
    const float* g_fuse = (const float*)d_in[14];
    const float* b_fuse = (const float*)d_in[15];
    const float* W_c1   = (const float*)d_in[16];
    const float* g_c1   = (const float*)d_in[17];
    const float* b_c1   = (const float*)d_in[18];
    const float* W_c2   = (const float*)d_in[19];
    const float* g_c2   = (const float*)d_in[20];
    const float* b_c2   = (const float*)d_in[21];
    float* out = (float*)d_out;
    int n = in_sizes[1];

    float *pF, *pMean, *pDen, *pSegS, *pCnt, *pStats, *pAdp;
    unsigned *pBufH, *pPack, *pPackC, *pFph;
    cudaGetSymbolAddress((void**)&pBufH, g_bufsH);
    cudaGetSymbolAddress((void**)&pF, g_bufF);
    cudaGetSymbolAddress((void**)&pFph, g_fph);
    cudaGetSymbolAddress((void**)&pMean, g_segMean);
    cudaGetSymbolAddress((void**)&pDen, g_segDen);
    cudaGetSymbolAddress((void**)&pSegS, g_segS);
    cudaGetSymbolAddress((void**)&pCnt, g_cnt);
    cudaGetSymbolAddress((void**)&pStats, g_statsA);
    cudaGetSymbolAddress((void**)&pAdp, g_adpv);
    cudaGetSymbolAddress((void**)&pPack, g_wpack);
    cudaGetSymbolAddress((void**)&pPackC, g_wpackc);

    const int GB = (n + TM - 1) / TM;
    const int EB = (n + 255) / 256;
    const int total4 = n * 16;
    const int SB = (total4 + 255) / 256;
    const int SM_1  = CBUF * 4;                     // 27648B (fp16 A + B)
    const int SM_CV = (2 * CBUF + TM * 27) * 4;     // 69120B

    cudaFuncSetAttribute(k_mma_gemm7, cudaFuncAttributeMaxDynamicSharedMemorySize, SM_1);
    cudaFuncSetAttribute(k_mma_submean_exp, cudaFuncAttributeMaxDynamicSharedMemorySize, SM_1);
    cudaFuncSetAttribute(k_mma_gemm2, cudaFuncAttributeMaxDynamicSharedMemorySize, SM_1);
    cudaFuncSetAttribute(k_mma_convh, cudaFuncAttributeMaxDynamicSharedMemorySize, SM_CV);

    const uint4* AF = (const uint4*)pFph;
    unsigned* Qh3 = pBufH + 6 * ROWH;
    unsigned* RawFH = pBufH;                // slot 0 (P0, free after pw3)
    unsigned* C1H  = pBufH + 1 * ROWH;      // slot 1
    unsigned* C2H  = pBufH + 2 * ROWH;      // slot 2

    k_prepack<<<12, 256>>>(W_lw, W_w, W_proj, W_fuse, pPack);
    k_prepackc<<<54, 256>>>(W_c1, W_c2, pPackC);

    // 7 feat-GEMMs (feat converted in staging) + fused adp
    cudaMemsetAsync(pStats, 0, 7 * 128 * sizeof(float));
    k_mma_gemm7<<<GB, NTHR, SM_1>>>(feat, W_adp, pPack, pBufH, pAdp, pStats, n);

    // cluster attention, all 3 scales batched
    cudaMemsetAsync(pMean, 0, (size_t)SEGTOT * 64 * sizeof(float));
    cudaMemsetAsync(pCnt, 0, (size_t)SEGTOT * sizeof(float));
    k_segsum3<<<dim3(EB, 3), 256>>>(pBufH, pStats, g_lw, b_lw, cl0, cl1, cl2,
                                    pMean, pCnt, n);
    cudaMemsetAsync(pDen, 0, (size_t)SEGTOT * 64 * sizeof(float));
    k_mma_submean_exp<<<dim3(GB, 3), NTHR, SM_1>>>(pBufH, pStats, g_lw, b_lw, pPack,
                                                   pMean, pCnt, cl0, cl1, cl2, pDen, n);
    cudaMemsetAsync(pSegS, 0, (size_t)SEGTOT * 64 * sizeof(float));
    k_pw3<<<dim3(EB, 3), 256>>>(pBufH, pStats, g_proj, b_proj, pDen,
                                cl0, cl1, cl2, pSegS, n);

    // fused = relu(bn([relu(bn(Q3)), mix] @ W_fuse)) + feat
    cudaMemsetAsync(pStats + 7 * 128, 0, 128 * sizeof(float));
    k_mma_gemm2<<<GB, NTHR, SM_1>>>(Qh3, pStats + 6 * 128, g_proj + 192, b_proj + 192,
                                    pPack + (size_t)10 * 2304, pSegS,
                                    cl0, cl1, cl2, pAdp, RawFH, pStats + 7 * 128, n);
    k_bnrelu_add_split<<<SB, 256>>>(RawFH, pF, pStats + 7 * 128, g_fuse, b_fuse, feat,
                                    pFph, n, total4);
    // conv1 -> split ; conv2 -> final
    cudaMemsetAsync(pStats + 8 * 128, 0, 128 * sizeof(float));
    k_mma_convh<<<GB, NTHR, SM_CV>>>(AF, nbr, pPackC, C1H, pStats + 8 * 128, n);
    k_bnrelu_split<<<SB, 256>>>(C1H, pStats + 8 * 128, g_c1, b_c1, pFph, n, total4);
    cudaMemsetAsync(pStats + 9 * 128, 0, 128 * sizeof(float));
    k_mma_convh<<<GB, NTHR, SM_CV>>>(AF, nbr, pPackC + (size_t)27 * 2304,
                                     C2H, pStats + 9 * 128, n);
    k_final<<<SB, 256>>>(C2H, pStats + 9 * 128, g_c2, b_c2, pF, out, n, total4);
}

// round 14
// speedup vs baseline: 2.2949x; 1.0111x over previous
#include <cuda_runtime.h>
#include <cuda_bf16.h>
#include <cuda_fp16.h>

// ---------------------------------------------------------------------------
// OACNNs block, round 14.
//  - fp32 F buffer eliminated: k_final recomputes the fused residual in
//    registers from fp16 RawFH + fp32 feat (bit-identical, -64MB traffic).
//  - single prepack kernel; single stats memset (5 launches merged).
//  - all else identical to round 13 (2510us, rel_err 5.23e-4).
// ---------------------------------------------------------------------------

#define NPTS_MAX 500000
#define SEGTOT   167936     // 4096 + 32768 + 131072
#define TM   128
#define NTHR 256
#define AS   36             // uints per smem row (144B stride, LDSM conflict-free)
#define CBUF   6912        // uints per fp16 buffer (A 4608 + B 2304)
#define COFF_B 4608
#define ROWH   ((size_t)NPTS_MAX * 32)   // uints per fp16 N x 64 buffer
#define CONV_TX 25600u     // 128 rows * 128B + 9216B B tile

// scratch (device globals: allocation-free rule)
__device__ unsigned       g_bufsH[7 * ROWH];     // fp16 P0,P1,P2,Q0,Q1,Q2,Q3 (+reuse)
__device__ unsigned       g_fph[NPTS_MAX * 32];  // fp16 plane of conv input
__device__ float          g_segMean[SEGTOT * 64];
__device__ float          g_segDen [SEGTOT * 64];
__device__ float          g_segS   [SEGTOT * 64];
__device__ float          g_cnt    [SEGTOT];
__device__ float          g_adpv[NPTS_MAX * 3];
__device__ float          g_statsA[10 * 128];    // 0-6 gemm7, 7 fuse, 8 c1, 9 c2
__device__ unsigned       g_wpack[12 * 2304];    // fp16 tiles (lw,w,proj,fuse)
__device__ unsigned       g_wpackc[54 * 2304];   // fp16 conv tiles

__device__ __constant__ int c_soff[3] = {0, 4096, 36864};

// ---------------- helpers ----------------
__device__ __forceinline__ void red_add_v4(float* addr, float4 v) {
    asm volatile("red.global.add.v4.f32 [%0], {%1,%2,%3,%4};"
                 :: "l"(addr), "f"(v.x), "f"(v.y), "f"(v.z), "f"(v.w)
                 : "memory");
}
__device__ __forceinline__ void red_add_v2(float* addr, float x, float y) {
    asm volatile("red.global.add.v2.f32 [%0], {%1,%2};"
                 :: "l"(addr), "f"(x), "f"(y) : "memory");
}
__device__ __forceinline__ void cp16(unsigned* dst, const void* src, bool v) {
    unsigned d = (unsigned)__cvta_generic_to_shared(dst);
    int sz = v ? 16 : 0;
    asm volatile("cp.async.cg.shared.global [%0], [%1], 16, %2;"
                 :: "r"(d), "l"(src), "r"(sz) : "memory");
}
__device__ __forceinline__ void cp_commit() {
    asm volatile("cp.async.commit_group;" ::: "memory");
}
template <int N> __device__ __forceinline__ void cp_wait() {
    asm volatile("cp.async.wait_group %0;" :: "n"(N) : "memory");
}
__device__ __forceinline__ void cpbulk(unsigned dst, const void* src,
                                       unsigned bytes, unsigned mba) {
    asm volatile(
        "cp.async.bulk.shared::cluster.global.mbarrier::complete_tx::bytes "
        "[%0], [%1], %2, [%3];"
        :: "r"(dst), "l"(src), "r"(bytes), "r"(mba) : "memory");
}
__device__ __forceinline__ void mbar_init(unsigned mba, unsigned cnt) {
    asm volatile("mbarrier.init.shared.b64 [%0], %1;" :: "r"(mba), "r"(cnt) : "memory");
}
__device__ __forceinline__ void mbar_expect(unsigned mba, unsigned bytes) {
    asm volatile("mbarrier.arrive.expect_tx.shared.b64 _, [%0], %1;"
                 :: "r"(mba), "r"(bytes) : "memory");
}
__device__ __forceinline__ void mbar_wait(unsigned mba, int phase) {
    asm volatile(
        "{\n\t"
        ".reg .pred P;\n\t"
        "LAB_%=:\n\t"
        "mbarrier.try_wait.parity.acquire.cta.shared::cta.b64 P, [%0], %1;\n\t"
        "@!P bra LAB_%=;\n\t"
        "}"
        :: "r"(mba), "r"(phase) : "memory");
}

__device__ __forceinline__ unsigned packh2(float x, float y) {
    __half2 h; h.x = __float2half(x); h.y = __float2half(y);
    return *reinterpret_cast<unsigned*>(&h);
}
__device__ __forceinline__ float4 ldh4(const unsigned* p) {
    uint2 u = *reinterpret_cast<const uint2*>(p);
    __half2 h0 = *reinterpret_cast<__half2*>(&u.x);
    __half2 h1 = *reinterpret_cast<__half2*>(&u.y);
    float2 f0 = __half22float2(h0), f1 = __half22float2(h1);
    return make_float4(f0.x, f0.y, f1.x, f1.y);
}

__device__ __forceinline__ void mma16816h(float* d, unsigned a0, unsigned a1,
                                          unsigned a2, unsigned a3,
                                          unsigned b0, unsigned b1) {
    asm volatile(
        "mma.sync.aligned.m16n8k16.row.col.f32.f16.f16.f32 "
        "{%0,%1,%2,%3}, {%4,%5,%6,%7}, {%8,%9}, {%0,%1,%2,%3};"
        : "+f"(d[0]), "+f"(d[1]), "+f"(d[2]), "+f"(d[3])
        : "r"(a0), "r"(a1), "r"(a2), "r"(a3), "r"(b0), "r"(b1));
}
__device__ __forceinline__ void ldsm4(unsigned& r0, unsigned& r1, unsigned& r2,
                                      unsigned& r3, const unsigned* p) {
    unsigned a = (unsigned)__cvta_generic_to_shared(p);
    asm volatile("ldmatrix.sync.aligned.m8n8.x4.shared.b16 {%0,%1,%2,%3}, [%4];"
                 : "=r"(r0), "=r"(r1), "=r"(r2), "=r"(r3) : "r"(a));
}

__device__ __forceinline__ void a_storeh(unsigned* buf, int r, int c4, float4 v) {
    *reinterpret_cast<uint2*>(buf + r * AS + c4 * 2) =
        make_uint2(packh2(v.x, v.y), packh2(v.z, v.w));
}

__device__ __forceinline__ void stage_Bc(unsigned* Bdst, const unsigned* tile, int tid) {
    const uint4* s = reinterpret_cast<const uint4*>(tile);
    for (int i = tid; i < 576; i += NTHR) cp16(Bdst + i * 4, s + i, true);
}

// 128x64x64 fp16 single-plane mma sweep
__device__ __forceinline__ void mma_compute_h(const unsigned* buf, float acc[8][4],
                                              int wid, int lane) {
    const unsigned* Ap = buf;
    const unsigned* Bp = buf + COFF_B;
    const unsigned* aph = Ap + (wid * 16 + (lane & 15)) * AS + (lane >> 4) * 4;
    int brow = lane & 7;
    int koff = ((lane >> 3) & 1) * 4;
    int ntoff = ((lane >> 4) & 1) * 8 * AS;
#pragma unroll
    for (int kk = 0; kk < 4; ++kk) {
        int ko = kk * 8;
        unsigned a0, a1, a2, a3;
        ldsm4(a0, a1, a2, a3, aph + ko);
#pragma unroll
        for (int np = 0; np < 4; ++np) {
            unsigned b0, b1, b2, b3;
            ldsm4(b0, b1, b2, b3, Bp + (np * 16 + brow) * AS + ntoff + ko + koff);
            mma16816h(acc[2 * np], a0, a1, a2, a3, b0, b1);
            mma16816h(acc[2 * np + 1], a0, a1, a2, a3, b2, b3);
        }
    }
}

// fp16 store + shuffle-reduced fp32 stats; rows >= n masked out of stats
__device__ __forceinline__ void epilogue_stats_h(float acc[8][4], unsigned* __restrict__ Co,
                                                 float* __restrict__ statsg,
                                                 float* csum, float* csq,
                                                 int row0, int n, int wid, int lane, int tid) {
    int g = lane >> 2, c = lane & 3;
    int r0 = row0 + wid * 16 + g, r1 = r0 + 8;
    bool v0 = r0 < n, v1 = r1 < n;
#pragma unroll
    for (int nt = 0; nt < 8; ++nt) {
        int ch = nt * 8 + 2 * c;
        float a0 = v0 ? acc[nt][0] : 0.f;
        float a1 = v0 ? acc[nt][1] : 0.f;
        float a2 = v1 ? acc[nt][2] : 0.f;
        float a3 = v1 ? acc[nt][3] : 0.f;
        if (v0) Co[(size_t)r0 * 32 + (ch >> 1)] = packh2(a0, a1);
        if (v1) Co[(size_t)r1 * 32 + (ch >> 1)] = packh2(a2, a3);
        float s0 = a0 + a2;
        float s1 = a1 + a3;
        float q0 = a0 * a0 + a2 * a2;
        float q1 = a1 * a1 + a3 * a3;
#pragma unroll
        for (int d = 4; d < 32; d <<= 1) {
            s0 += __shfl_xor_sync(0xffffffffu, s0, d);
            s1 += __shfl_xor_sync(0xffffffffu, s1, d);
            q0 += __shfl_xor_sync(0xffffffffu, q0, d);
            q1 += __shfl_xor_sync(0xffffffffu, q1, d);
        }
        if (lane < 4) {
            atomicAdd(&csum[ch], s0);
            atomicAdd(&csum[ch + 1], s1);
            atomicAdd(&csq[ch], q0);
            atomicAdd(&csq[ch + 1], q1);
        }
    }
    __syncthreads();
    if (tid < 64)       atomicAdd(&statsg[tid], csum[tid]);
    else if (tid < 128) atomicAdd(&statsg[tid], csq[tid - 64]);
}

__device__ __forceinline__ void load_coef(float* sc, const float* __restrict__ stats,
                                          const float* __restrict__ g,
                                          const float* __restrict__ b, int n, int tid) {
    if (tid < 64) {
        float inv_n = 1.f / (float)n;
        float mean = stats[tid] * inv_n;
        float var = stats[64 + tid] * inv_n - mean * mean;
        float a = g[tid] * rsqrtf(var + 1e-3f);
        sc[tid] = a;
        sc[64 + tid] = b[tid] - mean * a;
    }
}

// ---------------- prepack (all 66 fp16 n-major tiles, one kernel) ----------------
__global__ void k_prepack_all(const float* __restrict__ Wlw, const float* __restrict__ Ww,
                              const float* __restrict__ Wproj, const float* __restrict__ Wfuse,
                              const float* __restrict__ Wc1, const float* __restrict__ Wc2,
                              unsigned* __restrict__ pack, unsigned* __restrict__ packc) {
    int t = blockIdx.x;     // 0..65
    const float* src;
    unsigned* ph;
    if (t < 3)       { src = Wlw  + t * 4096;        ph = pack  + (size_t)t * 2304; }
    else if (t < 6)  { src = Ww   + (t - 3) * 4096;  ph = pack  + (size_t)t * 2304; }
    else if (t < 10) { src = Wproj+ (t - 6) * 4096;  ph = pack  + (size_t)t * 2304; }
    else if (t < 12) { src = Wfuse+ (t - 10) * 4096; ph = pack  + (size_t)t * 2304; }
    else if (t < 39) { src = Wc1  + (t - 12) * 4096; ph = packc + (size_t)(t - 12) * 2304; }
    else             { src = Wc2  + (t - 39) * 4096; ph = packc + (size_t)(t - 12) * 2304; }
    for (int idx = threadIdx.x; idx < 2048; idx += 256) {
        int cout = idx & 63, p = idx >> 6;
        ph[cout * AS + p] = packh2(src[2 * p * 64 + cout], src[(2 * p + 1) * 64 + cout]);
    }
}

// Hp = fp16(relu(bn(rawF_h)) + feat)   (F itself recomputed later in k_final)
__global__ void k_bnrelu_add_split(const unsigned* __restrict__ RawH,
                                   const float* __restrict__ stats,
                                   const float* __restrict__ g, const float* __restrict__ b,
                                   const float* __restrict__ feat,
                                   unsigned* __restrict__ Hp, int n, int total4) {
    __shared__ float sc[128];
    load_coef(sc, stats, g, b, n, threadIdx.x);
    __syncthreads();
    int i = blockIdx.x * 256 + threadIdx.x;
    if (i >= total4) return;
    int ch = (i & 15) * 4;
    float4 x = ldh4(RawH + (size_t)i * 2);
    float4 r = ((const float4*)feat)[i];
    x.x = fmaxf(x.x * sc[ch + 0] + sc[64 + ch + 0], 0.f) + r.x;
    x.y = fmaxf(x.y * sc[ch + 1] + sc[64 + ch + 1], 0.f) + r.y;
    x.z = fmaxf(x.z * sc[ch + 2] + sc[64 + ch + 2], 0.f) + r.z;
    x.w = fmaxf(x.w * sc[ch + 3] + sc[64 + ch + 3], 0.f) + r.w;
    ((uint2*)Hp)[i] = make_uint2(packh2(x.x, x.y), packh2(x.z, x.w));
}

// fp16 plane = relu(bn(P_h))
__global__ void k_bnrelu_split(const unsigned* __restrict__ Ph, const float* __restrict__ stats,
                               const float* __restrict__ g, const float* __restrict__ b,
                               unsigned* __restrict__ Hp, int n, int total4) {
    __shared__ float sc[128];
    load_coef(sc, stats, g, b, n, threadIdx.x);
    __syncthreads();
    int i = blockIdx.x * 256 + threadIdx.x;
    if (i >= total4) return;
    int ch = (i & 15) * 4;
    float4 x = ldh4(Ph + (size_t)i * 2);
    x.x = fmaxf(x.x * sc[ch + 0] + sc[64 + ch + 0], 0.f);
    x.y = fmaxf(x.y * sc[ch + 1] + sc[64 + ch + 1], 0.f);
    x.z = fmaxf(x.z * sc[ch + 2] + sc[64 + ch + 2], 0.f);
    x.w = fmaxf(x.w * sc[ch + 3] + sc[64 + ch + 3], 0.f);
    ((uint2*)Hp)[i] = make_uint2(packh2(x.x, x.y), packh2(x.z, x.w));
}

// ---------------- tensor-core kernels ----------------
// 7 GEMMs sharing A=feat (fp16-converted in staging) + fused adp softmax.
__global__ __launch_bounds__(NTHR, 4)
void k_mma_gemm7(const float* __restrict__ feat, const float* __restrict__ Wa,
                 const unsigned* __restrict__ pack, unsigned* __restrict__ bufs,
                 float* __restrict__ adp, float* __restrict__ statsg, int n) {
    extern __shared__ unsigned sm[];     // A:[0,4608) B:[4608,6912)
    __shared__ float csum[64], csq[64];
    __shared__ float wa[192];
    const int tidx[7] = {0, 1, 2, 6, 7, 8, 9};
    int tid = threadIdx.x, wid = tid >> 5, lane = tid & 31;
    int row0 = blockIdx.x * TM;
    if (tid < 192) wa[tid] = Wa[tid];
    stage_Bc(sm + COFF_B, pack + (size_t)tidx[0] * 2304, tid);
    cp_commit();
    __syncthreads();     // wa visible
#pragma unroll
    for (int i = 0; i < 8; ++i) {   // convert feat -> fp16 plane, fused adp
        int idx = tid + i * NTHR;
        int r = idx >> 4, c4 = idx & 15;
        int grow = row0 + r;
        float4 v = make_float4(0.f, 0.f, 0.f, 0.f);
        if (grow < n) v = *(const float4*)(feat + (size_t)grow * 64 + c4 * 4);
        a_storeh(sm, r, c4, v);
        int ch = c4 * 4;
        float s0 = v.x * wa[ch * 3 + 0] + v.y * wa[ch * 3 + 3] +
                   v.z * wa[ch * 3 + 6] + v.w * wa[ch * 3 + 9];
        float s1 = v.x * wa[ch * 3 + 1] + v.y * wa[ch * 3 + 4] +
                   v.z * wa[ch * 3 + 7] + v.w * wa[ch * 3 + 10];
        float s2 = v.x * wa[ch * 3 + 2] + v.y * wa[ch * 3 + 5] +
                   v.z * wa[ch * 3 + 8] + v.w * wa[ch * 3 + 11];
#pragma unroll
        for (int d = 1; d < 16; d <<= 1) {
            s0 += __shfl_xor_sync(0xffffffffu, s0, d);
            s1 += __shfl_xor_sync(0xffffffffu, s1, d);
            s2 += __shfl_xor_sync(0xffffffffu, s2, d);
        }
        if ((lane & 15) == 0 && grow < n) {
            float m = fmaxf(s0, fmaxf(s1, s2));
            float e0 = __expf(s0 - m), e1 = __expf(s1 - m), e2 = __expf(s2 - m);
            float inv = 1.f / (e0 + e1 + e2);
            adp[(size_t)grow * 3 + 0] = e0 * inv;
            adp[(size_t)grow * 3 + 1] = e1 * inv;
            adp[(size_t)grow * 3 + 2] = e2 * inv;
        }
    }
    cp_wait<0>();
    __syncthreads();
    for (int t = 0; t < 7; ++t) {
        if (tid < 64) { csum[tid] = 0.f; csq[tid] = 0.f; }
        __syncthreads();
        float acc[8][4] = {};
        mma_compute_h(sm, acc, wid, lane);
        epilogue_stats_h(acc, bufs + (size_t)t * ROWH, statsg + t * 128,
                         csum, csq, row0, n, wid, lane, tid);
        if (t + 1 < 7) {    // all B reads done (epilogue's internal sync)
            stage_Bc(sm + COFF_B, pack + (size_t)tidx[t + 1] * 2304, tid);
            cp_commit();
            cp_wait<0>();
        }
    }
}

// stage one conv tap via cp.async.bulk into buffer `buf` tracked by mbar `mba`
__device__ __forceinline__ void conv_stage(unsigned smb, int buf, int k,
                                           const uint4* __restrict__ AF,
                                           const int* __restrict__ idxs,
                                           const unsigned* __restrict__ packc,
                                           unsigned mba, int tid) {
    unsigned bbase = smb + (unsigned)buf * (CBUF * 4);
    if (tid < 128) {
        const void* src = AF + (size_t)idxs[tid * 27 + k] * 8;
        cpbulk(bbase + tid * (AS * 4), src, 128, mba);
    } else if (tid == 128) {
        mbar_expect(mba, CONV_TX);
        cpbulk(bbase + COFF_B * 4, packc + (size_t)k * 2304, 9216, mba);
    }
}

// gather conv (fp16), bulk-copy double-buffer pipeline; fp16 out + stats
__global__ __launch_bounds__(NTHR)
void k_mma_convh(const uint4* __restrict__ AF, const int* __restrict__ nbr,
                 const unsigned* __restrict__ packc,
                 unsigned* __restrict__ Co, float* __restrict__ statsg, int n) {
    extern __shared__ unsigned sm[];          // 2 x CBUF + idx cache
    int* idxs = (int*)(sm + 2 * CBUF);        // [TM*27]
    __shared__ float csum[64], csq[64];
    __shared__ unsigned long long mbar[2];
    int tid = threadIdx.x, wid = tid >> 5, lane = tid & 31;
    int row0 = blockIdx.x * TM;
    unsigned mb0 = (unsigned)__cvta_generic_to_shared(&mbar[0]);
    unsigned mb1 = (unsigned)__cvta_generic_to_shared(&mbar[1]);
    unsigned smb = (unsigned)__cvta_generic_to_shared(sm);
    if (tid < 64) { csum[tid] = 0.f; csq[tid] = 0.f; }
    if (tid == 0) { mbar_init(mb0, 1); mbar_init(mb1, 1); }
    {   // coalesced preload of neighbor indices
        size_t base = (size_t)row0 * 27;
        size_t lim = (size_t)n * 27;
        for (int i = tid; i < TM * 27; i += NTHR) {
            size_t pos = base + i;
            idxs[i] = (pos < lim) ? __ldg(&nbr[pos]) : 0;
        }
    }
    __syncthreads();
    int ph0 = 0, ph1 = 0;
    conv_stage(smb, 0, 0, AF, idxs, packc, mb0, tid);
    float acc[8][4] = {};
    for (int k = 0; k < 27; ++k) {
        if (k + 1 < 27)
            conv_stage(smb, (k + 1) & 1, k + 1, AF, idxs, packc,
                       (k & 1) ? mb0 : mb1, tid);
        if (k & 1) { mbar_wait(mb1, ph1); ph1 ^= 1; }
        else       { mbar_wait(mb0, ph0); ph0 ^= 1; }
        mma_compute_h(sm + (k & 1) * CBUF, acc, wid, lane);
        __syncthreads();
    }
    epilogue_stats_h(acc, Co, statsg, csum, csq, row0, n, wid, lane, tid);
}

// per-scale (gridDim.y=3): P = exp((relu(bn(P)) - mean[cl]) @ W_w); den += P
__global__ __launch_bounds__(NTHR)
void k_mma_submean_exp(unsigned* __restrict__ bufs, const float* __restrict__ statsb,
                       const float* __restrict__ glw, const float* __restrict__ blw,
                       const unsigned* __restrict__ pack, const float* __restrict__ mean,
                       const float* __restrict__ cnt,
                       const int* __restrict__ cl0, const int* __restrict__ cl1,
                       const int* __restrict__ cl2, float* __restrict__ den, int n) {
    extern __shared__ unsigned buf[];
    __shared__ float coef[128];
    __shared__ int   cls[TM];
    __shared__ float cinv[TM];
    int s = blockIdx.y;
    const int* cl = (s == 0) ? cl0 : ((s == 1) ? cl1 : cl2);
    int soff = c_soff[s];
    unsigned* P = bufs + (size_t)s * ROWH;
    int tid = threadIdx.x, wid = tid >> 5, lane = tid & 31;
    int row0 = blockIdx.x * TM;
    load_coef(coef, statsb + s * 128, glw + s * 64, blw + s * 64, n, tid);
    if (tid < 128) {
        int r = row0 + tid;
        int c = (r < n) ? cl[r] : 0;
        cls[tid] = c;
        cinv[tid] = 1.f / fmaxf(cnt[soff + c], 1.f);
    }
    stage_Bc(buf + COFF_B, pack + (size_t)(3 + s) * 2304, tid);
    cp_commit();
    __syncthreads();
#pragma unroll
    for (int i = 0; i < 8; ++i) {
        int idx = tid + i * NTHR;
        int r = idx >> 4, c4 = idx & 15;
        int grow = row0 + r;
        float4 vv = make_float4(0.f, 0.f, 0.f, 0.f);
        if (grow < n) {
            vv = ldh4(P + (size_t)grow * 32 + c4 * 2);
            float4 ms = *(const float4*)(mean + (size_t)(soff + cls[r]) * 64 + c4 * 4);
            float ci = cinv[r];
            int ch = c4 * 4;
            vv.x = fmaxf(vv.x * coef[ch + 0] + coef[64 + ch + 0], 0.f) - ms.x * ci;
            vv.y = fmaxf(vv.y * coef[ch + 1] + coef[64 + ch + 1], 0.f) - ms.y * ci;
            vv.z = fmaxf(vv.z * coef[ch + 2] + coef[64 + ch + 2], 0.f) - ms.z * ci;
            vv.w = fmaxf(vv.w * coef[ch + 3] + coef[64 + ch + 3], 0.f) - ms.w * ci;
        }
        a_storeh(buf, r, c4, vv);
    }
    cp_wait<0>();
    __syncthreads();
    float acc[8][4] = {};
    mma_compute_h(buf, acc, wid, lane);
    int g = lane >> 2, c = lane & 3;
    int lr0 = wid * 16 + g, lr1 = lr0 + 8;
    int r0 = row0 + lr0, r1 = row0 + lr1;
    float* d0 = den + (size_t)(soff + cls[lr0]) * 64;
    float* d1 = den + (size_t)(soff + cls[lr1]) * 64;
#pragma unroll
    for (int nt = 0; nt < 8; ++nt) {
        int ch = nt * 8 + 2 * c;
        if (r0 < n) {
            float e0 = __expf(acc[nt][0]), e1 = __expf(acc[nt][1]);
            P[(size_t)r0 * 32 + (ch >> 1)] = packh2(e0, e1);
            red_add_v2(d0 + ch, e0, e1);
        }
        if (r1 < n) {
            float e2 = __expf(acc[nt][2]), e3 = __expf(acc[nt][3]);
            P[(size_t)r1 * 32 + (ch >> 1)] = packh2(e2, e3);
            red_add_v2(d1 + ch, e2, e3);
        }
    }
}

// fuse GEMM: rawF_h = relu(bn(Q3))@Wf[0:64] + mix@Wf[64:128]; fp16 out + stats
__global__ __launch_bounds__(NTHR)
void k_mma_gemm2(const unsigned* __restrict__ Qh, const float* __restrict__ stats,
                 const float* __restrict__ gg, const float* __restrict__ bb,
                 const unsigned* __restrict__ tiles, const float* __restrict__ segS,
                 const int* __restrict__ cl0, const int* __restrict__ cl1,
                 const int* __restrict__ cl2, const float* __restrict__ adp,
                 unsigned* __restrict__ Co, float* __restrict__ statsg, int n) {
    extern __shared__ unsigned buf[];
    __shared__ float csum[64], csq[64];
    __shared__ float coef[128];
    __shared__ int   cls[3][TM];
    __shared__ float sad[3][TM];
    int tid = threadIdx.x, wid = tid >> 5, lane = tid & 31;
    int row0 = blockIdx.x * TM;
    if (tid < 64) { csum[tid] = 0.f; csq[tid] = 0.f; }
    load_coef(coef, stats, gg, bb, n, tid);
    if (tid < 128) {
        int r = row0 + tid;
        bool v = r < n;
        cls[0][tid] = v ? cl0[r] : 0;
        cls[1][tid] = v ? cl1[r] : 0;
        cls[2][tid] = v ? cl2[r] : 0;
        sad[0][tid] = v ? adp[(size_t)r * 3 + 0] : 0.f;
        sad[1][tid] = v ? adp[(size_t)r * 3 + 1] : 0.f;
        sad[2][tid] = v ? adp[(size_t)r * 3 + 2] : 0.f;
    }
    __syncthreads();
    float acc[8][4] = {};
#pragma unroll
    for (int p = 0; p < 2; ++p) {
        stage_Bc(buf + COFF_B, tiles + (size_t)p * 2304, tid);
        cp_commit();
#pragma unroll
        for (int i = 0; i < 8; ++i) {
            int idx = tid + i * NTHR;
            int r = idx >> 4, c4 = idx & 15;
            int grow = row0 + r;
            float4 vv = make_float4(0.f, 0.f, 0.f, 0.f);
            if (grow < n) {
                if (p == 0) {
                    vv = ldh4(Qh + (size_t)grow * 32 + c4 * 2);
                    int ch = c4 * 4;
                    vv.x = fmaxf(vv.x * coef[ch + 0] + coef[64 + ch + 0], 0.f);
                    vv.y = fmaxf(vv.y * coef[ch + 1] + coef[64 + ch + 1], 0.f);
                    vv.z = fmaxf(vv.z * coef[ch + 2] + coef[64 + ch + 2], 0.f);
                    vv.w = fmaxf(vv.w * coef[ch + 3] + coef[64 + ch + 3], 0.f);
                } else {
                    float w0 = sad[0][r], w1 = sad[1][r], w2 = sad[2][r];
                    float4 a = *(const float4*)(segS + (size_t)(0 + cls[0][r]) * 64 + c4 * 4);
                    float4 bv = *(const float4*)(segS + (size_t)(4096 + cls[1][r]) * 64 + c4 * 4);
                    float4 cc = *(const float4*)(segS + (size_t)(36864 + cls[2][r]) * 64 + c4 * 4);
                    vv.x = w0 * a.x + w1 * bv.x + w2 * cc.x;
                    vv.y = w0 * a.y + w1 * bv.y + w2 * cc.y;
                    vv.z = w0 * a.z + w1 * bv.z + w2 * cc.z;
                    vv.w = w0 * a.w + w1 * bv.w + w2 * cc.w;
                }
            }
            a_storeh(buf, r, c4, vv);
        }
        cp_wait<0>();
        __syncthreads();
        mma_compute_h(buf, acc, wid, lane);
        __syncthreads();
    }
    epilogue_stats_h(acc, Co, statsg, csum, csq, row0, n, wid, lane, tid);
}

// ---------------- small / elementwise kernels ----------------
// per-scale (gridDim.y=3): mean-arena += relu(bn(P_h)), cnt++
__global__ void k_segsum3(const unsigned* __restrict__ bufs, const float* __restrict__ statsb,
                          const float* __restrict__ glw, const float* __restrict__ blw,
                          const int* __restrict__ cl0, const int* __restrict__ cl1,
                          const int* __restrict__ cl2, float* __restrict__ mean,
                          float* __restrict__ cnt, int n) {
    __shared__ float sc[128];
    int s = blockIdx.y;
    load_coef(sc, statsb + s * 128, glw + s * 64, blw + s * 64, n, threadIdx.x);
    __syncthreads();
    int row = blockIdx.x * blockDim.x + threadIdx.x;
    if (row >= n) return;
    const int* cl = (s == 0) ? cl0 : ((s == 1) ? cl1 : cl2);
    int c = c_soff[s] + cl[row];
    const unsigned* p = bufs + (size_t)s * ROWH + (size_t)row * 32;
    float* sg = mean + (size_t)c * 64;
#pragma unroll
    for (int c4 = 0; c4 < 16; ++c4) {
        float4 x = ldh4(p + c4 * 2);
        x.x = fmaxf(x.x * sc[c4 * 4 + 0] + sc[64 + c4 * 4 + 0], 0.f);
        x.y = fmaxf(x.y * sc[c4 * 4 + 1] + sc[64 + c4 * 4 + 1], 0.f);
        x.z = fmaxf(x.z * sc[c4 * 4 + 2] + sc[64 + c4 * 4 + 2], 0.f);
        x.w = fmaxf(x.w * sc[c4 * 4 + 3] + sc[64 + c4 * 4 + 3], 0.f);
        red_add_v4(sg + c4 * 4, x);
    }
    atomicAdd(&cnt[c], 1.f);
}

// per-scale (gridDim.y=3): segS += relu(bn(Q_h)) * expP_h / (den[cl]+1e-6)
__global__ void k_pw3(const unsigned* __restrict__ bufs, const float* __restrict__ statsb,
                      const float* __restrict__ gproj, const float* __restrict__ bproj,
                      const float* __restrict__ den,
                      const int* __restrict__ cl0, const int* __restrict__ cl1,
                      const int* __restrict__ cl2, float* __restrict__ segS, int n) {
    __shared__ float sc[128];
    int s = blockIdx.y;
    load_coef(sc, statsb + (3 + s) * 128, gproj + s * 64, bproj + s * 64, n, threadIdx.x);
    __syncthreads();
    int row = blockIdx.x * blockDim.x + threadIdx.x;
    if (row >= n) return;
    const int* cl = (s == 0) ? cl0 : ((s == 1) ? cl1 : cl2);
    int c = c_soff[s] + cl[row];
    const unsigned* q = bufs + (size_t)(3 + s) * ROWH + (size_t)row * 32;
    const unsigned* p = bufs + (size_t)s * ROWH + (size_t)row * 32;
    const float* d = den + (size_t)c * 64;
    float* sg = segS + (size_t)c * 64;
#pragma unroll
    for (int c4 = 0; c4 < 16; ++c4) {
        float4 qv = ldh4(q + c4 * 2);
        float4 pv = ldh4(p + c4 * 2);
        float4 dv = *(const float4*)(d + c4 * 4);
        float4 o;
        o.x = fmaxf(qv.x * sc[c4 * 4 + 0] + sc[64 + c4 * 4 + 0], 0.f) * pv.x / (dv.x + 1e-6f);
        o.y = fmaxf(qv.y * sc[c4 * 4 + 1] + sc[64 + c4 * 4 + 1], 0.f) * pv.y / (dv.y + 1e-6f);
        o.z = fmaxf(qv.z * sc[c4 * 4 + 2] + sc[64 + c4 * 4 + 2], 0.f) * pv.z / (dv.z + 1e-6f);
        o.w = fmaxf(qv.w * sc[c4 * 4 + 3] + sc[64 + c4 * 4 + 3], 0.f) * pv.w / (dv.w + 1e-6f);
        red_add_v4(sg + c4 * 4, o);
    }
}

// out = relu(bn_c2(H_h) + F), F = relu(bn_fuse(rawF_h)) + feat (recomputed)
__global__ void k_final(const unsigned* __restrict__ Hh, const float* __restrict__ statsC,
                        const float* __restrict__ gC, const float* __restrict__ bC,
                        const unsigned* __restrict__ RawH, const float* __restrict__ statsF,
                        const float* __restrict__ gF, const float* __restrict__ bF,
                        const float* __restrict__ feat, float* __restrict__ out,
                        int n, int total4) {
    __shared__ float sc[128];   // conv2 coef
    __shared__ float sf[128];   // fuse coef
    load_coef(sc, statsC, gC, bC, n, threadIdx.x);
    load_coef(sf, statsF, gF, bF, n, threadIdx.x >= 128 ? threadIdx.x - 128 : 128);
    if (threadIdx.x >= 128) load_coef(sf, statsF, gF, bF, n, threadIdx.x - 128);
    __syncthreads();
    int i = blockIdx.x * 256 + threadIdx.x;
    if (i >= total4) return;
    int ch = (i & 15) * 4;
    float4 h = ldh4(Hh + (size_t)i * 2);
    float4 w = ldh4(RawH + (size_t)i * 2);
    float4 r = ((const float4*)feat)[i];
    float f0 = fmaxf(w.x * sf[ch + 0] + sf[64 + ch + 0], 0.f) + r.x;
    float f1 = fmaxf(w.y * sf[ch + 1] + sf[64 + ch + 1], 0.f) + r.y;
    float f2 = fmaxf(w.z * sf[ch + 2] + sf[64 + ch + 2], 0.f) + r.z;
    float f3 = fmaxf(w.w * sf[ch + 3] + sf[64 + ch + 3], 0.f) + r.w;
    float4 x;
    x.x = fmaxf(h.x * sc[ch + 0] + sc[64 + ch + 0] + f0, 0.f);
    x.y = fmaxf(h.y * sc[ch + 1] + sc[64 + ch + 1] + f1, 0.f);
    x.z = fmaxf(h.z * sc[ch + 2] + sc[64 + ch + 2] + f2, 0.f);
    x.w = fmaxf(h.w * sc[ch + 3] + sc[64 + ch + 3] + f3, 0.f);
    ((float4*)out)[i] = x;
}

// ---------------------------------------------------------------------------
extern "C" void kernel_launch(void* const* d_in, const int* in_sizes, int n_in,
                              void* d_out, int out_size) {
    const float* feat   = (const float*)d_in[0];
    const int*   cl0    = (const int*)d_in[1];
    const int*   cl1    = (const int*)d_in[2];
    const int*   cl2    = (const int*)d_in[3];
    const int*   nbr    = (const int*)d_in[4];
    const float* W_lw   = (const float*)d_in[5];
    const float* g_lw   = (const float*)d_in[6];
    const float* b_lw   = (const float*)d_in[7];
    const float* W_w    = (const float*)d_in[8];
    const float* W_proj = (const float*)d_in[9];
    const float* g_proj = (const float*)d_in[10];
    const float* b_proj = (const float*)d_in[11];
    const float* W_adp  = (const float*)d_in[12];
    const float* W_fuse = (const float*)d_in[13];
    const float* g_fuse = (const float*)d_in[14];
    const float* b_fuse = (const float*)d_in[15];
    const float* W_c1   = (const float*)d_in[16];
    const float* g_c1   = (const float*)d_in[17];
    const float* b_c1   = (const float*)d_in[18];
    const float* W_c2   = (const float*)d_in[19];
    const float* g_c2   = (const float*)d_in[20];
    const float* b_c2   = (const float*)d_in[21];
    float* out = (float*)d_out;
    int n = in_sizes[1];

    float *pMean, *pDen, *pSegS, *pCnt, *pStats, *pAdp;
    unsigned *pBufH, *pPack, *pPackC, *pFph;
    cudaGetSymbolAddress((void**)&pBufH, g_bufsH);
    cudaGetSymbolAddress((void**)&pFph, g_fph);
    cudaGetSymbolAddress((void**)&pMean, g_segMean);
    cudaGetSymbolAddress((void**)&pDen, g_segDen);
    cudaGetSymbolAddress((void**)&pSegS, g_segS);
    cudaGetSymbolAddress((void**)&pCnt, g_cnt);
    cudaGetSymbolAddress((void**)&pStats, g_statsA);
    cudaGetSymbolAddress((void**)&pAdp, g_adpv);
    cudaGetSymbolAddress((void**)&pPack, g_wpack);
    cudaGetSymbolAddress((void**)&pPackC, g_wpackc);

    const int GB = (n + TM - 1) / TM;
    const int EB = (n + 255) / 256;
    const int total4 = n * 16;
    const int SB = (total4 + 255) / 256;
    const int SM_1  = CBUF * 4;                     // 27648B (fp16 A + B)
    const int SM_CV = (2 * CBUF + TM * 27) * 4;     // 69120B

    cudaFuncSetAttribute(k_mma_gemm7, cudaFuncAttributeMaxDynamicSharedMemorySize, SM_1);
    cudaFuncSetAttribute(k_mma_submean_exp, cudaFuncAttributeMaxDynamicSharedMemorySize, SM_1);
    cudaFuncSetAttribute(k_mma_gemm2, cudaFuncAttributeMaxDynamicSharedMemorySize, SM_1);
    cudaFuncSetAttribute(k_mma_convh, cudaFuncAttributeMaxDynamicSharedMemorySize, SM_CV);

    const uint4* AF = (const uint4*)pFph;
    unsigned* Qh3 = pBufH + 6 * ROWH;
    unsigned* RawFH = pBufH;                // slot 0 (P0, free after pw3)
    unsigned* C1H  = pBufH + 1 * ROWH;      // slot 1
    unsigned* C2H  = pBufH + 2 * ROWH;      // slot 2

    k_prepack_all<<<66, 256>>>(W_lw, W_w, W_proj, W_fuse, W_c1, W_c2, pPack, pPackC);
    cudaMemsetAsync(pStats, 0, 10 * 128 * sizeof(float));   // all stat slots at once

    // 7 feat-GEMMs (feat converted in staging) + fused adp
    k_mma_gemm7<<<GB, NTHR, SM_1>>>(feat, W_adp, pPack, pBufH, pAdp, pStats, n);

    // cluster attention, all 3 scales batched
    cudaMemsetAsync(pMean, 0, (size_t)SEGTOT * 64 * sizeof(float));
    cudaMemsetAsync(pCnt, 0, (size_t)SEGTOT * sizeof(float));
    k_segsum3<<<dim3(EB, 3), 256>>>(pBufH, pStats, g_lw, b_lw, cl0, cl1, cl2,
                                    pMean, pCnt, n);
    cudaMemsetAsync(pDen, 0, (size_t)SEGTOT * 64 * sizeof(float));
    k_mma_submean_exp<<<dim3(GB, 3), NTHR, SM_1>>>(pBufH, pStats, g_lw, b_lw, pPack,
                                                   pMean, pCnt, cl0, cl1, cl2, pDen, n);
    cudaMemsetAsync(pSegS, 0, (size_t)SEGTOT * 64 * sizeof(float));
    k_pw3<<<dim3(EB, 3), 256>>>(pBufH, pStats, g_proj, b_proj, pDen,
                                cl0, cl1, cl2, pSegS, n);

    // fused: rawF_h = [relu(bn(Q3)), mix] @ W_fuse  (F recomputed in k_final)
    k_mma_gemm2<<<GB, NTHR, SM_1>>>(Qh3, pStats + 6 * 128, g_proj + 192, b_proj + 192,
                                    pPack + (size_t)10 * 2304, pSegS,
                                    cl0, cl1, cl2, pAdp, RawFH, pStats + 7 * 128, n);
    k_bnrelu_add_split<<<SB, 256>>>(RawFH, pStats + 7 * 128, g_fuse, b_fuse, feat,
                                    pFph, n, total4);
    // conv1 -> split ; conv2 -> final (recomputes F)
    k_mma_convh<<<GB, NTHR, SM_CV>>>(AF, nbr, pPackC, C1H, pStats + 8 * 128, n);
    k_bnrelu_split<<<SB, 256>>>(C1H, pStats + 8 * 128, g_c1, b_c1, pFph, n, total4);
    k_mma_convh<<<GB, NTHR, SM_CV>>>(AF, nbr, pPackC + (size_t)27 * 2304,
                                     C2H, pStats + 9 * 128, n);
    k_final<<<SB, 256>>>(C2H, pStats + 9 * 128, g_c2, b_c2,
                         RawFH, pStats + 7 * 128, g_fuse, b_fuse,
                         feat, out, n, total4);
}